// round 1
// baseline (speedup 1.0000x reference)
#include <cuda_runtime.h>
#include <cuda_bf16.h>
#include <math.h>

// ---------------------------------------------------------------------------
// MTCNN P-Net forward, fp32 direct conv baseline.
// x[16,3,720,720] -> conv1(3x3,3->10)+PReLU -> maxpool2 -> conv2(3x3,10->16)+PReLU
// -> conv3(3x3,16->32)+PReLU -> {conv42(1x1,32->4)=reg, softmax(conv41(1x1,32->2))=prob}
// out = [reg (16*4*355*355) | prob (16*2*355*355)]
// ---------------------------------------------------------------------------

#define B       16
#define H0      720
#define H1      718   // conv1 out
#define HP      359   // pooled
#define H2      357   // conv2 out
#define H3      355   // conv3 out
#define P3      (H3*H3)   // 126025

// scratch (device globals; no allocations allowed)
__device__ float g_p1[B*10*HP*HP];   // pooled conv1 output
__device__ float g_c2[B*16*H2*H2];   // conv2 output
__device__ float g_c3[B*32*H3*H3];   // conv3 output

// ---------------------------------------------------------------------------
// Kernel 1: normalize + conv1(3x3, 3->10) + PReLU + maxpool(2,2)  fused
// block (32,4): each thread = 1 pooled output pixel (computes the 2x2 conv quad)
// ---------------------------------------------------------------------------
__global__ void k_conv1_pool(const float* __restrict__ x,
                             const float* __restrict__ w1,
                             const float* __restrict__ b1,
                             const float* __restrict__ a1)
{
    __shared__ float sIn[3][10][66];   // input tile (normalized)
    __shared__ float sW[10][3][9];
    __shared__ float sB[10], sA[10];

    const int b   = blockIdx.z;
    const int px0 = blockIdx.x * 32;
    const int py0 = blockIdx.y * 4;
    const int tid = threadIdx.y * 32 + threadIdx.x;

    for (int i = tid; i < 270; i += 128) sW[i/27][(i%27)/9][i%9] = w1[i];
    if (tid < 10) { sB[tid] = b1[tid]; sA[tid] = a1[tid]; }

    const int row0 = 2*py0, col0 = 2*px0;
    for (int i = tid; i < 3*10*66; i += 128) {
        int ci = i/660, r = (i%660)/66, c = i%66;
        int gr = row0 + r, gc = col0 + c;
        float v = 0.f;
        if (gr < H0 && gc < H0)
            v = (x[((b*3+ci)*H0 + gr)*H0 + gc] - 127.5f) * 0.0078125f;
        sIn[ci][r][c] = v;
    }
    __syncthreads();

    const int px = px0 + threadIdx.x;
    const int py = py0 + threadIdx.y;
    if (px >= HP || py >= HP) return;

    float acc[10][4];
    #pragma unroll
    for (int co = 0; co < 10; co++) {
        float bb = sB[co];
        acc[co][0]=bb; acc[co][1]=bb; acc[co][2]=bb; acc[co][3]=bb;
    }

    const int lr = 2*threadIdx.y, lc = 2*threadIdx.x;
    #pragma unroll
    for (int ci = 0; ci < 3; ci++) {
        float p[4][4];
        #pragma unroll
        for (int i = 0; i < 4; i++)
            #pragma unroll
            for (int j = 0; j < 4; j++) p[i][j] = sIn[ci][lr+i][lc+j];
        #pragma unroll
        for (int co = 0; co < 10; co++) {
            #pragma unroll
            for (int ky = 0; ky < 3; ky++)
                #pragma unroll
                for (int kx = 0; kx < 3; kx++) {
                    float w = sW[co][ci][ky*3+kx];
                    acc[co][0] = fmaf(p[ky  ][kx  ], w, acc[co][0]);
                    acc[co][1] = fmaf(p[ky  ][kx+1], w, acc[co][1]);
                    acc[co][2] = fmaf(p[ky+1][kx  ], w, acc[co][2]);
                    acc[co][3] = fmaf(p[ky+1][kx+1], w, acc[co][3]);
                }
        }
    }
    #pragma unroll
    for (int co = 0; co < 10; co++) {
        float a = sA[co];
        float m = -INFINITY;
        #pragma unroll
        for (int k = 0; k < 4; k++) {
            float v = acc[co][k];
            v = (v >= 0.f) ? v : a*v;
            m = fmaxf(m, v);
        }
        g_p1[((b*10+co)*HP + py)*HP + px] = m;
    }
}

// ---------------------------------------------------------------------------
// Kernel 2: conv2(3x3, 10->16) + PReLU.  in [B,10,359,359] -> out [B,16,357,357]
// block (32,8), output tile 64x8, 2 pixels/thread (x and x+32)
// ---------------------------------------------------------------------------
__global__ void k_conv2(const float* __restrict__ w,
                        const float* __restrict__ bias,
                        const float* __restrict__ alpha)
{
    __shared__ float sIn[10][10][66];     // 6600 floats
    __shared__ float sW[16][10][9];       // 1440
    __shared__ float sB[16], sA[16];

    const int b   = blockIdx.z;
    const int ox0 = blockIdx.x * 64;
    const int oy0 = blockIdx.y * 8;
    const int tid = threadIdx.y * 32 + threadIdx.x;

    for (int i = tid; i < 1440; i += 256) sW[i/90][(i%90)/9][i%9] = w[i];
    if (tid < 16) { sB[tid] = bias[tid]; sA[tid] = alpha[tid]; }

    for (int i = tid; i < 10*10*66; i += 256) {
        int ci = i/660, r = (i%660)/66, c = i%66;
        int gr = oy0 + r, gc = ox0 + c;
        sIn[ci][r][c] = (gr < HP && gc < HP)
                      ? g_p1[((b*10+ci)*HP + gr)*HP + gc] : 0.f;
    }
    __syncthreads();

    const int ty = threadIdx.y, tx = threadIdx.x;
    const int oy = oy0 + ty;
    const int ox = ox0 + tx;

    float acc[16][2];
    #pragma unroll
    for (int co = 0; co < 16; co++) { float bb = sB[co]; acc[co][0]=bb; acc[co][1]=bb; }

    #pragma unroll
    for (int ci = 0; ci < 10; ci++) {
        float pA[3][3], pB[3][3];
        #pragma unroll
        for (int ky = 0; ky < 3; ky++)
            #pragma unroll
            for (int kx = 0; kx < 3; kx++) {
                pA[ky][kx] = sIn[ci][ty+ky][tx+kx];
                pB[ky][kx] = sIn[ci][ty+ky][tx+32+kx];
            }
        #pragma unroll
        for (int co = 0; co < 16; co++)
            #pragma unroll
            for (int ky = 0; ky < 3; ky++)
                #pragma unroll
                for (int kx = 0; kx < 3; kx++) {
                    float wv = sW[co][ci][ky*3+kx];
                    acc[co][0] = fmaf(pA[ky][kx], wv, acc[co][0]);
                    acc[co][1] = fmaf(pB[ky][kx], wv, acc[co][1]);
                }
    }

    if (oy < H2) {
        #pragma unroll
        for (int co = 0; co < 16; co++) {
            float a = sA[co];
            if (ox < H2) {
                float v = acc[co][0]; v = (v >= 0.f) ? v : a*v;
                g_c2[((b*16+co)*H2 + oy)*H2 + ox] = v;
            }
            if (ox + 32 < H2) {
                float v = acc[co][1]; v = (v >= 0.f) ? v : a*v;
                g_c2[((b*16+co)*H2 + oy)*H2 + ox + 32] = v;
            }
        }
    }
}

// ---------------------------------------------------------------------------
// Kernel 3: conv3(3x3, 16->32) + PReLU.  in [B,16,357,357] -> out [B,32,355,355]
// block (32,8), output tile 64x8, 2 pixels/thread. Dynamic smem (~61KB).
// ---------------------------------------------------------------------------
__global__ void k_conv3(const float* __restrict__ w,
                        const float* __restrict__ bias,
                        const float* __restrict__ alpha)
{
    extern __shared__ float smem[];
    float* sIn = smem;                 // [16][10][66] = 10560
    float* sW  = smem + 10560;         // [32][16*9]   = 4608
    float* sB  = sW + 4608;            // [32]
    float* sA  = sB + 32;              // [32]

    const int b   = blockIdx.z;
    const int ox0 = blockIdx.x * 64;
    const int oy0 = blockIdx.y * 8;
    const int tid = threadIdx.y * 32 + threadIdx.x;

    for (int i = tid; i < 4608; i += 256) sW[i] = w[i];
    if (tid < 32) { sB[tid] = bias[tid]; sA[tid] = alpha[tid]; }

    for (int i = tid; i < 16*10*66; i += 256) {
        int ci = i/660, r = (i%660)/66, c = i%66;
        int gr = oy0 + r, gc = ox0 + c;
        sIn[(ci*10 + r)*66 + c] = (gr < H2 && gc < H2)
                                ? g_c2[((b*16+ci)*H2 + gr)*H2 + gc] : 0.f;
    }
    __syncthreads();

    const int ty = threadIdx.y, tx = threadIdx.x;
    const int oy = oy0 + ty;
    const int ox = ox0 + tx;

    float acc0[32], acc1[32];
    #pragma unroll
    for (int co = 0; co < 32; co++) { float bb = sB[co]; acc0[co]=bb; acc1[co]=bb; }

    #pragma unroll
    for (int ci = 0; ci < 16; ci++) {
        float pA[3][3], pB[3][3];
        #pragma unroll
        for (int ky = 0; ky < 3; ky++)
            #pragma unroll
            for (int kx = 0; kx < 3; kx++) {
                pA[ky][kx] = sIn[(ci*10 + ty+ky)*66 + tx+kx];
                pB[ky][kx] = sIn[(ci*10 + ty+ky)*66 + tx+32+kx];
            }
        #pragma unroll
        for (int co = 0; co < 32; co++) {
            const float* wp = &sW[co*144 + ci*9];
            #pragma unroll
            for (int k = 0; k < 9; k++) {
                float wv = wp[k];
                acc0[co] = fmaf(pA[k/3][k%3], wv, acc0[co]);
                acc1[co] = fmaf(pB[k/3][k%3], wv, acc1[co]);
            }
        }
    }

    if (oy < H3) {
        #pragma unroll
        for (int co = 0; co < 32; co++) {
            float a = sA[co];
            if (ox < H3) {
                float v = acc0[co]; v = (v >= 0.f) ? v : a*v;
                g_c3[((b*32+co)*H3 + oy)*H3 + ox] = v;
            }
            if (ox + 32 < H3) {
                float v = acc1[co]; v = (v >= 0.f) ? v : a*v;
                g_c3[((b*32+co)*H3 + oy)*H3 + ox + 32] = v;
            }
        }
    }
}

// ---------------------------------------------------------------------------
// Kernel 4: 1x1 heads. reg = conv42(h), prob = softmax(conv41(h), ch-axis)
// ---------------------------------------------------------------------------
__global__ void k_heads(const float* __restrict__ w41, const float* __restrict__ b41,
                        const float* __restrict__ w42, const float* __restrict__ b42,
                        float* __restrict__ out)
{
    __shared__ float sw1[2][32], sw2[4][32], sb1[2], sb2[4];
    const int tid = threadIdx.x;
    if (tid < 64)  sw1[tid/32][tid%32] = w41[tid];
    if (tid < 128) sw2[tid/32][tid%32] = w42[tid];
    if (tid < 2) sb1[tid] = b41[tid];
    if (tid < 4) sb2[tid] = b42[tid];
    __syncthreads();

    int idx = blockIdx.x * blockDim.x + tid;
    if (idx >= B * P3) return;
    int b = idx / P3, p = idx % P3;

    const float* hp = g_c3 + (size_t)(b*32) * P3 + p;
    float l0 = sb1[0], l1 = sb1[1];
    float r0 = sb2[0], r1 = sb2[1], r2 = sb2[2], r3 = sb2[3];
    #pragma unroll
    for (int c = 0; c < 32; c++) {
        float v = hp[(size_t)c * P3];
        l0 = fmaf(v, sw1[0][c], l0); l1 = fmaf(v, sw1[1][c], l1);
        r0 = fmaf(v, sw2[0][c], r0); r1 = fmaf(v, sw2[1][c], r1);
        r2 = fmaf(v, sw2[2][c], r2); r3 = fmaf(v, sw2[3][c], r3);
    }
    float m  = fmaxf(l0, l1);
    float e0 = expf(l0 - m), e1 = expf(l1 - m);
    float inv = 1.f / (e0 + e1);

    float* regp  = out;                         // [B,4,355,355]
    float* probp = out + (size_t)B * 4 * P3;    // [B,2,355,355]
    regp[(size_t)(b*4+0)*P3 + p] = r0;
    regp[(size_t)(b*4+1)*P3 + p] = r1;
    regp[(size_t)(b*4+2)*P3 + p] = r2;
    regp[(size_t)(b*4+3)*P3 + p] = r3;
    probp[(size_t)(b*2+0)*P3 + p] = e0 * inv;
    probp[(size_t)(b*2+1)*P3 + p] = e1 * inv;
}

// ---------------------------------------------------------------------------
extern "C" void kernel_launch(void* const* d_in, const int* in_sizes, int n_in,
                              void* d_out, int out_size)
{
    const float* x    = (const float*)d_in[0];
    const float* c1w  = (const float*)d_in[1];
    const float* c1b  = (const float*)d_in[2];
    const float* p1a  = (const float*)d_in[3];
    const float* c2w  = (const float*)d_in[4];
    const float* c2b  = (const float*)d_in[5];
    const float* p2a  = (const float*)d_in[6];
    const float* c3w  = (const float*)d_in[7];
    const float* c3b  = (const float*)d_in[8];
    const float* p3a  = (const float*)d_in[9];
    const float* c41w = (const float*)d_in[10];
    const float* c41b = (const float*)d_in[11];
    const float* c42w = (const float*)d_in[12];
    const float* c42b = (const float*)d_in[13];
    float* out = (float*)d_out;

    // conv3 needs ~61KB dynamic smem
    cudaFuncSetAttribute(k_conv3, cudaFuncAttributeMaxDynamicSharedMemorySize, 62000);

    {
        dim3 blk(32, 4);
        dim3 grd((HP + 31) / 32, (HP + 3) / 4, B);
        k_conv1_pool<<<grd, blk>>>(x, c1w, c1b, p1a);
    }
    {
        dim3 blk(32, 8);
        dim3 grd((H2 + 63) / 64, (H2 + 7) / 8, B);
        k_conv2<<<grd, blk>>>(c2w, c2b, p2a);
    }
    {
        dim3 blk(32, 8);
        dim3 grd((H3 + 63) / 64, (H3 + 7) / 8, B);
        size_t smem = (10560 + 4608 + 64) * sizeof(float);
        k_conv3<<<grd, blk, smem>>>(c3w, c3b, p3a);
    }
    {
        int total = B * P3;
        int threads = 256;
        int blocks = (total + threads - 1) / threads;
        k_heads<<<blocks, threads>>>(c41w, c41b, c42w, c42b, out);
    }
}

// round 2
// speedup vs baseline: 1.9478x; 1.9478x over previous
#include <cuda_runtime.h>
#include <cuda_bf16.h>
#include <math.h>

// ---------------------------------------------------------------------------
// MTCNN P-Net forward. fp32 with packed f32x2 FFMA2 (2 FMAs/instr on sm_103a).
// Output-channel PAIRS packed in 64-bit accumulators; weight pairs pre-packed
// in smem (one uniform LDS.64 feeds 2 FMAs); pixel broadcast packed once per
// k-step and reused across all channel pairs.
// ---------------------------------------------------------------------------

#define B       16
#define H0      720
#define HP      359   // pooled
#define H2      357   // conv2 out
#define H3      355   // conv3 out
#define P3      (H3*H3)

typedef unsigned long long ull;

__device__ __forceinline__ ull pack2(float a, float b) {
    ull r;
    asm("mov.b64 %0, {%1,%2};" : "=l"(r)
        : "r"(__float_as_uint(a)), "r"(__float_as_uint(b)));
    return r;
}
__device__ __forceinline__ void unpack2(ull v, float& a, float& b) {
    unsigned lo, hi;
    asm("mov.b64 {%0,%1}, %2;" : "=r"(lo), "=r"(hi) : "l"(v));
    a = __uint_as_float(lo); b = __uint_as_float(hi);
}
// d = a*b + d  (packed 2xfp32)
__device__ __forceinline__ void fma2(ull& d, ull a, ull b) {
    asm("fma.rn.f32x2 %0, %1, %2, %3;" : "=l"(d) : "l"(a), "l"(b), "l"(d));
}

// scratch
__device__ float g_p1[B*10*HP*HP];
__device__ float g_c2[B*16*H2*H2];
__device__ float g_c3[B*32*H3*H3];

// ---------------------------------------------------------------------------
// Kernel 1: normalize + conv1(3x3,3->10) + PReLU + maxpool2  (5 co-pairs)
// block (32,4) = 1 pooled pixel/thread (2x2 conv quad)
// ---------------------------------------------------------------------------
__global__ __launch_bounds__(128) void k_conv1_pool(
    const float* __restrict__ x, const float* __restrict__ w1,
    const float* __restrict__ b1, const float* __restrict__ a1)
{
    __shared__ ull   sWp[5][3][9];     // (w[2cp],w[2cp+1])
    __shared__ float sIn[3][10][66];
    __shared__ float sB[10], sA[10];

    const int b   = blockIdx.z;
    const int px0 = blockIdx.x * 32;
    const int py0 = blockIdx.y * 4;
    const int tid = threadIdx.y * 32 + threadIdx.x;

    for (int i = tid; i < 135; i += 128) {
        int cp = i / 27, ci = (i % 27) / 9, k = i % 9;
        sWp[cp][ci][k] = pack2(w1[(2*cp)*27 + ci*9 + k], w1[(2*cp+1)*27 + ci*9 + k]);
    }
    if (tid < 10) { sB[tid] = b1[tid]; sA[tid] = a1[tid]; }

    const int row0 = 2*py0, col0 = 2*px0;
    for (int i = tid; i < 3*10*66; i += 128) {
        int ci = i/660, r = (i%660)/66, c = i%66;
        int gr = row0 + r, gc = col0 + c;
        float v = 0.f;
        if (gr < H0 && gc < H0)
            v = (x[((b*3+ci)*H0 + gr)*H0 + gc] - 127.5f) * 0.0078125f;
        sIn[ci][r][c] = v;
    }
    __syncthreads();

    const int px = px0 + threadIdx.x;
    const int py = py0 + threadIdx.y;
    if (px >= HP || py >= HP) return;

    ull acc[5][4];
    #pragma unroll
    for (int cp = 0; cp < 5; cp++) {
        ull bb = pack2(sB[2*cp], sB[2*cp+1]);
        acc[cp][0]=bb; acc[cp][1]=bb; acc[cp][2]=bb; acc[cp][3]=bb;
    }

    const int lr = 2*threadIdx.y, lc = 2*threadIdx.x;
    #pragma unroll
    for (int ci = 0; ci < 3; ci++) {
        ull q[4][4];
        #pragma unroll
        for (int i = 0; i < 4; i++)
            #pragma unroll
            for (int j = 0; j < 4; j++) {
                float v = sIn[ci][lr+i][lc+j];
                q[i][j] = pack2(v, v);
            }
        #pragma unroll
        for (int ky = 0; ky < 3; ky++)
            #pragma unroll
            for (int kx = 0; kx < 3; kx++) {
                #pragma unroll
                for (int cp = 0; cp < 5; cp++) {
                    ull wp = sWp[cp][ci][ky*3+kx];
                    fma2(acc[cp][0], wp, q[ky  ][kx  ]);
                    fma2(acc[cp][1], wp, q[ky  ][kx+1]);
                    fma2(acc[cp][2], wp, q[ky+1][kx  ]);
                    fma2(acc[cp][3], wp, q[ky+1][kx+1]);
                }
            }
    }

    #pragma unroll
    for (int cp = 0; cp < 5; cp++) {
        float a0 = sA[2*cp], a1v = sA[2*cp+1];
        float m0 = -INFINITY, m1 = -INFINITY;
        #pragma unroll
        for (int k = 0; k < 4; k++) {
            float v0, v1; unpack2(acc[cp][k], v0, v1);
            v0 = (v0 >= 0.f) ? v0 : a0*v0;
            v1 = (v1 >= 0.f) ? v1 : a1v*v1;
            m0 = fmaxf(m0, v0); m1 = fmaxf(m1, v1);
        }
        g_p1[((b*10 + 2*cp  )*HP + py)*HP + px] = m0;
        g_p1[((b*10 + 2*cp+1)*HP + py)*HP + px] = m1;
    }
}

// ---------------------------------------------------------------------------
// Kernel 2: conv2(3x3,10->16)+PReLU. 8 co-pairs x 2 pixels. block (32,8)
// ---------------------------------------------------------------------------
__global__ __launch_bounds__(256) void k_conv2(
    const float* __restrict__ w, const float* __restrict__ bias,
    const float* __restrict__ alpha)
{
    __shared__ ull   sWp[8][10][9];    // 5760B
    __shared__ float sIn[10][10][66];  // 26400B
    __shared__ float sB[16], sA[16];

    const int b   = blockIdx.z;
    const int ox0 = blockIdx.x * 64;
    const int oy0 = blockIdx.y * 8;
    const int tid = threadIdx.y * 32 + threadIdx.x;

    for (int i = tid; i < 720; i += 256) {
        int cp = i / 90, ci = (i % 90) / 9, k = i % 9;
        sWp[cp][ci][k] = pack2(w[(2*cp)*90 + ci*9 + k], w[(2*cp+1)*90 + ci*9 + k]);
    }
    if (tid < 16) { sB[tid] = bias[tid]; sA[tid] = alpha[tid]; }

    for (int i = tid; i < 10*10*66; i += 256) {
        int ci = i/660, r = (i%660)/66, c = i%66;
        int gr = oy0 + r, gc = ox0 + c;
        sIn[ci][r][c] = (gr < HP && gc < HP)
                      ? g_p1[((b*10+ci)*HP + gr)*HP + gc] : 0.f;
    }
    __syncthreads();

    const int ty = threadIdx.y, tx = threadIdx.x;
    const int oy = oy0 + ty, ox = ox0 + tx;

    ull acc0[8], acc1[8];
    #pragma unroll
    for (int cp = 0; cp < 8; cp++) {
        ull bb = pack2(sB[2*cp], sB[2*cp+1]);
        acc0[cp] = bb; acc1[cp] = bb;
    }

    #pragma unroll
    for (int ci = 0; ci < 10; ci++) {
        ull qA[9], qB[9];
        #pragma unroll
        for (int ky = 0; ky < 3; ky++)
            #pragma unroll
            for (int kx = 0; kx < 3; kx++) {
                float vA = sIn[ci][ty+ky][tx+kx];
                float vB = sIn[ci][ty+ky][tx+32+kx];
                qA[ky*3+kx] = pack2(vA, vA);
                qB[ky*3+kx] = pack2(vB, vB);
            }
        #pragma unroll
        for (int k = 0; k < 9; k++) {
            #pragma unroll
            for (int cp = 0; cp < 8; cp++) {
                ull wp = sWp[cp][ci][k];
                fma2(acc0[cp], wp, qA[k]);
                fma2(acc1[cp], wp, qB[k]);
            }
        }
    }

    if (oy < H2) {
        #pragma unroll
        for (int cp = 0; cp < 8; cp++) {
            float a0 = sA[2*cp], a1v = sA[2*cp+1];
            float v0, v1;
            if (ox < H2) {
                unpack2(acc0[cp], v0, v1);
                v0 = (v0 >= 0.f) ? v0 : a0*v0;
                v1 = (v1 >= 0.f) ? v1 : a1v*v1;
                g_c2[((b*16 + 2*cp  )*H2 + oy)*H2 + ox] = v0;
                g_c2[((b*16 + 2*cp+1)*H2 + oy)*H2 + ox] = v1;
            }
            if (ox + 32 < H2) {
                unpack2(acc1[cp], v0, v1);
                v0 = (v0 >= 0.f) ? v0 : a0*v0;
                v1 = (v1 >= 0.f) ? v1 : a1v*v1;
                g_c2[((b*16 + 2*cp  )*H2 + oy)*H2 + ox + 32] = v0;
                g_c2[((b*16 + 2*cp+1)*H2 + oy)*H2 + ox + 32] = v1;
            }
        }
    }
}

// ---------------------------------------------------------------------------
// Kernel 3: conv3(3x3,16->32)+PReLU. 16 co-pairs x 2 pixels. block (32,8)
// dynamic smem ~60KB
// ---------------------------------------------------------------------------
__global__ __launch_bounds__(256, 2) void k_conv3(
    const float* __restrict__ w, const float* __restrict__ bias,
    const float* __restrict__ alpha)
{
    extern __shared__ char smem[];
    ull*   sWp = (ull*)smem;                       // [16][16][9] = 18432B
    float* sIn = (float*)(smem + 18432);           // [16][10][66] = 42240B
    float* sBA = (float*)(smem + 18432 + 42240);   // 64 floats

    const int b   = blockIdx.z;
    const int ox0 = blockIdx.x * 64;
    const int oy0 = blockIdx.y * 8;
    const int tid = threadIdx.y * 32 + threadIdx.x;

    for (int i = tid; i < 2304; i += 256) {
        int cp = i / 144, ci = (i % 144) / 9, k = i % 9;
        sWp[(cp*16 + ci)*9 + k] =
            pack2(w[(2*cp)*144 + ci*9 + k], w[(2*cp+1)*144 + ci*9 + k]);
    }
    if (tid < 32) { sBA[tid] = bias[tid]; sBA[32+tid] = alpha[tid]; }

    for (int i = tid; i < 16*10*66; i += 256) {
        int ci = i/660, r = (i%660)/66, c = i%66;
        int gr = oy0 + r, gc = ox0 + c;
        sIn[(ci*10 + r)*66 + c] = (gr < H2 && gc < H2)
                                ? g_c2[((b*16+ci)*H2 + gr)*H2 + gc] : 0.f;
    }
    __syncthreads();

    const int ty = threadIdx.y, tx = threadIdx.x;
    const int oy = oy0 + ty, ox = ox0 + tx;

    ull acc0[16], acc1[16];
    #pragma unroll
    for (int cp = 0; cp < 16; cp++) {
        ull bb = pack2(sBA[2*cp], sBA[2*cp+1]);
        acc0[cp] = bb; acc1[cp] = bb;
    }

    #pragma unroll 4
    for (int ci = 0; ci < 16; ci++) {
        ull qA[9], qB[9];
        #pragma unroll
        for (int ky = 0; ky < 3; ky++)
            #pragma unroll
            for (int kx = 0; kx < 3; kx++) {
                float vA = sIn[(ci*10 + ty+ky)*66 + tx+kx];
                float vB = sIn[(ci*10 + ty+ky)*66 + tx+32+kx];
                qA[ky*3+kx] = pack2(vA, vA);
                qB[ky*3+kx] = pack2(vB, vB);
            }
        #pragma unroll
        for (int k = 0; k < 9; k++) {
            #pragma unroll
            for (int cp = 0; cp < 16; cp++) {
                ull wp = sWp[(cp*16 + ci)*9 + k];
                fma2(acc0[cp], wp, qA[k]);
                fma2(acc1[cp], wp, qB[k]);
            }
        }
    }

    if (oy < H3) {
        #pragma unroll
        for (int cp = 0; cp < 16; cp++) {
            float a0 = sBA[32+2*cp], a1v = sBA[32+2*cp+1];
            float v0, v1;
            if (ox < H3) {
                unpack2(acc0[cp], v0, v1);
                v0 = (v0 >= 0.f) ? v0 : a0*v0;
                v1 = (v1 >= 0.f) ? v1 : a1v*v1;
                g_c3[((b*32 + 2*cp  )*H3 + oy)*H3 + ox] = v0;
                g_c3[((b*32 + 2*cp+1)*H3 + oy)*H3 + ox] = v1;
            }
            if (ox + 32 < H3) {
                unpack2(acc1[cp], v0, v1);
                v0 = (v0 >= 0.f) ? v0 : a0*v0;
                v1 = (v1 >= 0.f) ? v1 : a1v*v1;
                g_c3[((b*32 + 2*cp  )*H3 + oy)*H3 + ox + 32] = v0;
                g_c3[((b*32 + 2*cp+1)*H3 + oy)*H3 + ox + 32] = v1;
            }
        }
    }
}

// ---------------------------------------------------------------------------
// Kernel 4: 1x1 heads, 4 consecutive pixels per thread
// ---------------------------------------------------------------------------
__global__ __launch_bounds__(256) void k_heads(
    const float* __restrict__ w41, const float* __restrict__ b41,
    const float* __restrict__ w42, const float* __restrict__ b42,
    float* __restrict__ out)
{
    __shared__ float sw1[2][32], sw2[4][32], sb1[2], sb2[4];
    const int tid = threadIdx.x;
    if (tid < 64)  sw1[tid/32][tid%32] = w41[tid];
    if (tid < 128) sw2[tid/32][tid%32] = w42[tid];
    if (tid < 2) sb1[tid] = b41[tid];
    if (tid < 4) sb2[tid] = b42[tid];
    __syncthreads();

    const int b  = blockIdx.y;
    const int p0 = (blockIdx.x * 256 + tid) * 4;
    if (p0 >= P3) return;
    const int nv = min(4, P3 - p0);

    const float* hp = g_c3 + (size_t)(b*32) * P3 + p0;
    float l0[4], l1[4], r0[4], r1[4], r2[4], r3[4];
    #pragma unroll
    for (int j = 0; j < 4; j++) {
        l0[j]=sb1[0]; l1[j]=sb1[1];
        r0[j]=sb2[0]; r1[j]=sb2[1]; r2[j]=sb2[2]; r3[j]=sb2[3];
    }
    for (int c = 0; c < 32; c++) {
        float u1_0 = sw1[0][c], u1_1 = sw1[1][c];
        float u2_0 = sw2[0][c], u2_1 = sw2[1][c], u2_2 = sw2[2][c], u2_3 = sw2[3][c];
        const float* pc = hp + (size_t)c * P3;
        #pragma unroll
        for (int j = 0; j < 4; j++) {
            float v = (j < nv) ? __ldg(pc + j) : 0.f;
            l0[j] = fmaf(v, u1_0, l0[j]); l1[j] = fmaf(v, u1_1, l1[j]);
            r0[j] = fmaf(v, u2_0, r0[j]); r1[j] = fmaf(v, u2_1, r1[j]);
            r2[j] = fmaf(v, u2_2, r2[j]); r3[j] = fmaf(v, u2_3, r3[j]);
        }
    }

    float* regp  = out;                      // [B,4,355,355]
    float* probp = out + (size_t)B * 4 * P3; // [B,2,355,355]
    #pragma unroll
    for (int j = 0; j < 4; j++) {
        if (j >= nv) break;
        float m  = fmaxf(l0[j], l1[j]);
        float e0 = expf(l0[j] - m), e1 = expf(l1[j] - m);
        float inv = 1.f / (e0 + e1);
        int p = p0 + j;
        regp[(size_t)(b*4+0)*P3 + p] = r0[j];
        regp[(size_t)(b*4+1)*P3 + p] = r1[j];
        regp[(size_t)(b*4+2)*P3 + p] = r2[j];
        regp[(size_t)(b*4+3)*P3 + p] = r3[j];
        probp[(size_t)(b*2+0)*P3 + p] = e0 * inv;
        probp[(size_t)(b*2+1)*P3 + p] = e1 * inv;
    }
}

// ---------------------------------------------------------------------------
extern "C" void kernel_launch(void* const* d_in, const int* in_sizes, int n_in,
                              void* d_out, int out_size)
{
    const float* x    = (const float*)d_in[0];
    const float* c1w  = (const float*)d_in[1];
    const float* c1b  = (const float*)d_in[2];
    const float* p1a  = (const float*)d_in[3];
    const float* c2w  = (const float*)d_in[4];
    const float* c2b  = (const float*)d_in[5];
    const float* p2a  = (const float*)d_in[6];
    const float* c3w  = (const float*)d_in[7];
    const float* c3b  = (const float*)d_in[8];
    const float* p3a  = (const float*)d_in[9];
    const float* c41w = (const float*)d_in[10];
    const float* c41b = (const float*)d_in[11];
    const float* c42w = (const float*)d_in[12];
    const float* c42b = (const float*)d_in[13];
    float* out = (float*)d_out;

    cudaFuncSetAttribute(k_conv3, cudaFuncAttributeMaxDynamicSharedMemorySize, 61000);

    {
        dim3 blk(32, 4);
        dim3 grd((HP + 31) / 32, (HP + 3) / 4, B);
        k_conv1_pool<<<grd, blk>>>(x, c1w, c1b, p1a);
    }
    {
        dim3 blk(32, 8);
        dim3 grd((H2 + 63) / 64, (H2 + 7) / 8, B);
        k_conv2<<<grd, blk>>>(c2w, c2b, p2a);
    }
    {
        dim3 blk(32, 8);
        dim3 grd((H3 + 63) / 64, (H3 + 7) / 8, B);
        size_t smem = 18432 + 42240 + 64 * sizeof(float);
        k_conv3<<<grd, blk, smem>>>(c3w, c3b, p3a);
    }
    {
        int pix_blocks = (P3 + 256*4 - 1) / (256*4);
        dim3 grd(pix_blocks, B);
        k_heads<<<grd, 256>>>(c41w, c41b, c42w, c42b, out);
    }
}

// round 4
// speedup vs baseline: 2.5297x; 1.2987x over previous
#include <cuda_runtime.h>
#include <cuda_bf16.h>
#include <math.h>
#include <stdint.h>

// ---------------------------------------------------------------------------
// MTCNN P-Net forward.
// conv1: scalar FFMA2 (fused norm+conv+prelu+pool)
// conv2: scalar FFMA2, output channel-last [b][y][x][16]
// conv3: warp-level mma.sync m16n8k16 bf16 hi/lo implicit GEMM (base-target safe)
// heads: 1x1 convs + softmax, coalesced channel-last reads
// ---------------------------------------------------------------------------

#define B       16
#define H0      720
#define HP      359
#define H2      357
#define H3      355
#define P3      (H3*H3)

typedef unsigned long long ull;

__device__ __forceinline__ ull pack2(float a, float b) {
    ull r;
    asm("mov.b64 %0, {%1,%2};" : "=l"(r)
        : "r"(__float_as_uint(a)), "r"(__float_as_uint(b)));
    return r;
}
__device__ __forceinline__ void unpack2(ull v, float& a, float& b) {
    unsigned lo, hi;
    asm("mov.b64 {%0,%1}, %2;" : "=r"(lo), "=r"(hi) : "l"(v));
    a = __uint_as_float(lo); b = __uint_as_float(hi);
}
__device__ __forceinline__ void fma2(ull& d, ull a, ull b) {
    asm("fma.rn.f32x2 %0, %1, %2, %3;" : "=l"(d) : "l"(a), "l"(b), "l"(d));
}

// scratch
__device__ float g_p1[B*10*HP*HP];            // conv1+pool out [b][10][y][x]
__device__ float g_c2cl[(size_t)B*H2*H2*16];  // conv2 out channel-last
__device__ float g_c3cl[(size_t)B*P3*32];     // conv3 out channel-last

// ---------------------------------------------------------------------------
// Kernel 1: normalize + conv1(3x3,3->10) + PReLU + maxpool2
// ---------------------------------------------------------------------------
__global__ __launch_bounds__(128) void k_conv1_pool(
    const float* __restrict__ x, const float* __restrict__ w1,
    const float* __restrict__ b1, const float* __restrict__ a1)
{
    __shared__ ull   sWp[5][3][9];
    __shared__ float sIn[3][10][66];
    __shared__ float sB[10], sA[10];

    const int b   = blockIdx.z;
    const int px0 = blockIdx.x * 32;
    const int py0 = blockIdx.y * 4;
    const int tid = threadIdx.y * 32 + threadIdx.x;

    for (int i = tid; i < 135; i += 128) {
        int cp = i / 27, ci = (i % 27) / 9, k = i % 9;
        sWp[cp][ci][k] = pack2(w1[(2*cp)*27 + ci*9 + k], w1[(2*cp+1)*27 + ci*9 + k]);
    }
    if (tid < 10) { sB[tid] = b1[tid]; sA[tid] = a1[tid]; }

    const int row0 = 2*py0, col0 = 2*px0;
    for (int i = tid; i < 3*10*66; i += 128) {
        int ci = i/660, r = (i%660)/66, c = i%66;
        int gr = row0 + r, gc = col0 + c;
        float v = 0.f;
        if (gr < H0 && gc < H0)
            v = (x[((b*3+ci)*H0 + gr)*H0 + gc] - 127.5f) * 0.0078125f;
        sIn[ci][r][c] = v;
    }
    __syncthreads();

    const int px = px0 + threadIdx.x;
    const int py = py0 + threadIdx.y;
    if (px >= HP || py >= HP) return;

    ull acc[5][4];
    #pragma unroll
    for (int cp = 0; cp < 5; cp++) {
        ull bb = pack2(sB[2*cp], sB[2*cp+1]);
        acc[cp][0]=bb; acc[cp][1]=bb; acc[cp][2]=bb; acc[cp][3]=bb;
    }

    const int lr = 2*threadIdx.y, lc = 2*threadIdx.x;
    #pragma unroll
    for (int ci = 0; ci < 3; ci++) {
        ull q[4][4];
        #pragma unroll
        for (int i = 0; i < 4; i++)
            #pragma unroll
            for (int j = 0; j < 4; j++) {
                float v = sIn[ci][lr+i][lc+j];
                q[i][j] = pack2(v, v);
            }
        #pragma unroll
        for (int ky = 0; ky < 3; ky++)
            #pragma unroll
            for (int kx = 0; kx < 3; kx++) {
                #pragma unroll
                for (int cp = 0; cp < 5; cp++) {
                    ull wp = sWp[cp][ci][ky*3+kx];
                    fma2(acc[cp][0], wp, q[ky  ][kx  ]);
                    fma2(acc[cp][1], wp, q[ky  ][kx+1]);
                    fma2(acc[cp][2], wp, q[ky+1][kx  ]);
                    fma2(acc[cp][3], wp, q[ky+1][kx+1]);
                }
            }
    }

    #pragma unroll
    for (int cp = 0; cp < 5; cp++) {
        float a0 = sA[2*cp], a1v = sA[2*cp+1];
        float m0 = -INFINITY, m1 = -INFINITY;
        #pragma unroll
        for (int k = 0; k < 4; k++) {
            float v0, v1; unpack2(acc[cp][k], v0, v1);
            v0 = (v0 >= 0.f) ? v0 : a0*v0;
            v1 = (v1 >= 0.f) ? v1 : a1v*v1;
            m0 = fmaxf(m0, v0); m1 = fmaxf(m1, v1);
        }
        g_p1[((b*10 + 2*cp  )*HP + py)*HP + px] = m0;
        g_p1[((b*10 + 2*cp+1)*HP + py)*HP + px] = m1;
    }
}

// ---------------------------------------------------------------------------
// Kernel 2: conv2(3x3,10->16)+PReLU -> channel-last
// ---------------------------------------------------------------------------
__global__ __launch_bounds__(256) void k_conv2(
    const float* __restrict__ w, const float* __restrict__ bias,
    const float* __restrict__ alpha)
{
    __shared__ ull   sWp[8][10][9];
    __shared__ float sIn[10][10][66];
    __shared__ float sB[16], sA[16];

    const int b   = blockIdx.z;
    const int ox0 = blockIdx.x * 64;
    const int oy0 = blockIdx.y * 8;
    const int tid = threadIdx.y * 32 + threadIdx.x;

    for (int i = tid; i < 720; i += 256) {
        int cp = i / 90, ci = (i % 90) / 9, k = i % 9;
        sWp[cp][ci][k] = pack2(w[(2*cp)*90 + ci*9 + k], w[(2*cp+1)*90 + ci*9 + k]);
    }
    if (tid < 16) { sB[tid] = bias[tid]; sA[tid] = alpha[tid]; }

    for (int i = tid; i < 10*10*66; i += 256) {
        int ci = i/660, r = (i%660)/66, c = i%66;
        int gr = oy0 + r, gc = ox0 + c;
        sIn[ci][r][c] = (gr < HP && gc < HP)
                      ? g_p1[((b*10+ci)*HP + gr)*HP + gc] : 0.f;
    }
    __syncthreads();

    const int ty = threadIdx.y, tx = threadIdx.x;
    const int oy = oy0 + ty, ox = ox0 + tx;

    ull acc0[8], acc1[8];
    #pragma unroll
    for (int cp = 0; cp < 8; cp++) {
        ull bb = pack2(sB[2*cp], sB[2*cp+1]);
        acc0[cp] = bb; acc1[cp] = bb;
    }

    #pragma unroll
    for (int ci = 0; ci < 10; ci++) {
        ull qA[9], qB[9];
        #pragma unroll
        for (int ky = 0; ky < 3; ky++)
            #pragma unroll
            for (int kx = 0; kx < 3; kx++) {
                float vA = sIn[ci][ty+ky][tx+kx];
                float vB = sIn[ci][ty+ky][tx+32+kx];
                qA[ky*3+kx] = pack2(vA, vA);
                qB[ky*3+kx] = pack2(vB, vB);
            }
        #pragma unroll
        for (int k = 0; k < 9; k++) {
            #pragma unroll
            for (int cp = 0; cp < 8; cp++) {
                ull wp = sWp[cp][ci][k];
                fma2(acc0[cp], wp, qA[k]);
                fma2(acc1[cp], wp, qB[k]);
            }
        }
    }

    if (oy < H2) {
        float v[16];
        if (ox < H2) {
            #pragma unroll
            for (int cp = 0; cp < 8; cp++) {
                float v0, v1; unpack2(acc0[cp], v0, v1);
                float a0 = sA[2*cp], a1v = sA[2*cp+1];
                v[2*cp]   = (v0 >= 0.f) ? v0 : a0*v0;
                v[2*cp+1] = (v1 >= 0.f) ? v1 : a1v*v1;
            }
            float* dst = &g_c2cl[((size_t)(b*H2+oy)*H2 + ox)*16];
            #pragma unroll
            for (int q = 0; q < 4; q++)
                *(float4*)(dst + q*4) = make_float4(v[q*4],v[q*4+1],v[q*4+2],v[q*4+3]);
        }
        if (ox + 32 < H2) {
            #pragma unroll
            for (int cp = 0; cp < 8; cp++) {
                float v0, v1; unpack2(acc1[cp], v0, v1);
                float a0 = sA[2*cp], a1v = sA[2*cp+1];
                v[2*cp]   = (v0 >= 0.f) ? v0 : a0*v0;
                v[2*cp+1] = (v1 >= 0.f) ? v1 : a1v*v1;
            }
            float* dst = &g_c2cl[((size_t)(b*H2+oy)*H2 + ox + 32)*16];
            #pragma unroll
            for (int q = 0; q < 4; q++)
                *(float4*)(dst + q*4) = make_float4(v[q*4],v[q*4+1],v[q*4+2],v[q*4+3]);
        }
    }
}

// ---------------------------------------------------------------------------
// Kernel 3: conv3 via mma.sync m16n8k16 bf16, hi/lo 3-term.
// Each warp: 16 px x 32 co; block 256thr = 128 px row; 4 rows per block.
// A fragments loaded straight from channel-last conv2 output (k-chunk = one
// 3x3 tap x 16 ci; fragment k-pairs are consecutive ci -> float2 loads).
// ---------------------------------------------------------------------------
__device__ __forceinline__ void hilo2(float2 v, uint32_t& hi, uint32_t& lo) {
    __nv_bfloat162 h = __floats2bfloat162_rn(v.x, v.y);
    float rx = v.x - __bfloat162float(h.x);
    float ry = v.y - __bfloat162float(h.y);
    __nv_bfloat162 l = __floats2bfloat162_rn(rx, ry);
    hi = *(uint32_t*)&h; lo = *(uint32_t*)&l;
}
__device__ __forceinline__ void mma16816(float* d, const uint32_t* a,
                                         uint32_t b0, uint32_t b1) {
    asm volatile(
        "mma.sync.aligned.m16n8k16.row.col.f32.bf16.bf16.f32 "
        "{%0,%1,%2,%3}, {%4,%5,%6,%7}, {%8,%9}, {%0,%1,%2,%3};"
        : "+f"(d[0]), "+f"(d[1]), "+f"(d[2]), "+f"(d[3])
        : "r"(a[0]), "r"(a[1]), "r"(a[2]), "r"(a[3]), "r"(b0), "r"(b1));
}

__global__ __launch_bounds__(256) void k_conv3_mma(
    const float* __restrict__ w, const float* __restrict__ bias,
    const float* __restrict__ alpha)
{
    __shared__ __nv_bfloat16 sWh[9*32*16];   // [kc][co][ci]
    __shared__ __nv_bfloat16 sWl[9*32*16];
    __shared__ float sBA[64];

    const int b    = blockIdx.z;
    const int ox0  = blockIdx.x * 128;
    const int oy0  = blockIdx.y * 4;
    const int tid  = threadIdx.x;
    const int wid  = tid >> 5;
    const int lane = tid & 31;

    for (int i = tid; i < 4608; i += 256) {
        int kc = i >> 9, co = (i >> 4) & 31, ci = i & 15;
        int ky = kc / 3, kx = kc % 3;
        float wv = w[((co*16 + ci)*3 + ky)*3 + kx];
        __nv_bfloat16 h = __float2bfloat16(wv);
        sWh[i] = h;
        sWl[i] = __float2bfloat16(wv - __bfloat162float(h));
    }
    if (tid < 32) { sBA[tid] = bias[tid]; sBA[32+tid] = alpha[tid]; }
    __syncthreads();

    const int g   = lane >> 2;      // groupID (pixel row / B col)
    const int ci0 = (lane & 3) * 2; // fragment k-pair base / D col base

    const int pxb = ox0 + wid * 16;
    const int p0  = pxb + g;
    const int p1  = p0 + 8;
    const int p0c = min(p0, H3 - 1);
    const int p1c = min(p1, H3 - 1);

    for (int r = 0; r < 4; r++) {
        const int oy = oy0 + r;
        if (oy >= H3) break;

        float acc[4][4];
        #pragma unroll
        for (int cg = 0; cg < 4; cg++)
            #pragma unroll
            for (int j = 0; j < 4; j++) acc[cg][j] = 0.f;

        #pragma unroll
        for (int kc = 0; kc < 9; kc++) {
            const int ky = kc / 3, kx = kc % 3;
            const float* rowp = &g_c2cl[(size_t)(b*H2 + oy + ky) * H2 * 16];
            float2 L00 = *(const float2*)&rowp[(p0c + kx)*16 + ci0];
            float2 L10 = *(const float2*)&rowp[(p1c + kx)*16 + ci0];
            float2 L01 = *(const float2*)&rowp[(p0c + kx)*16 + ci0 + 8];
            float2 L11 = *(const float2*)&rowp[(p1c + kx)*16 + ci0 + 8];
            uint32_t ah[4], al[4];
            hilo2(L00, ah[0], al[0]);
            hilo2(L10, ah[1], al[1]);
            hilo2(L01, ah[2], al[2]);
            hilo2(L11, ah[3], al[3]);

            #pragma unroll
            for (int cg = 0; cg < 4; cg++) {
                const int co = cg*8 + g;
                const int base = (kc*32 + co)*16;
                uint32_t bh0 = *(const uint32_t*)&sWh[base + ci0];
                uint32_t bh1 = *(const uint32_t*)&sWh[base + ci0 + 8];
                uint32_t bl0 = *(const uint32_t*)&sWl[base + ci0];
                uint32_t bl1 = *(const uint32_t*)&sWl[base + ci0 + 8];
                mma16816(acc[cg], ah, bh0, bh1);
                mma16816(acc[cg], ah, bl0, bl1);
                mma16816(acc[cg], al, bh0, bh1);
            }
        }

        // epilogue: bias + prelu, store channel-last
        const size_t rowbase = (size_t)b * P3 + (size_t)oy * H3;
        #pragma unroll
        for (int cg = 0; cg < 4; cg++) {
            const int co = cg*8 + ci0;   // D col = (lane%4)*2
            const float b0 = sBA[co], b1 = sBA[co+1];
            const float a0 = sBA[32+co], a1 = sBA[32+co+1];
            float t0 = acc[cg][0] + b0, t1 = acc[cg][1] + b1;
            float t2 = acc[cg][2] + b0, t3 = acc[cg][3] + b1;
            float2 o01, o23;
            o01.x = (t0 >= 0.f) ? t0 : a0*t0;
            o01.y = (t1 >= 0.f) ? t1 : a1*t1;
            o23.x = (t2 >= 0.f) ? t2 : a0*t2;
            o23.y = (t3 >= 0.f) ? t3 : a1*t3;
            if (p0 < H3) *(float2*)&g_c3cl[(rowbase + p0)*32 + co] = o01;
            if (p1 < H3) *(float2*)&g_c3cl[(rowbase + p1)*32 + co] = o23;
        }
    }
}

// ---------------------------------------------------------------------------
// Kernel 4: 1x1 heads from channel-last conv3 output
// ---------------------------------------------------------------------------
__global__ __launch_bounds__(256) void k_heads(
    const float* __restrict__ w41, const float* __restrict__ b41,
    const float* __restrict__ w42, const float* __restrict__ b42,
    float* __restrict__ out)
{
    __shared__ float sw1[2][32], sw2[4][32], sb1[2], sb2[4];
    const int tid = threadIdx.x;
    if (tid < 64)  sw1[tid/32][tid%32] = w41[tid];
    if (tid < 128) sw2[tid/32][tid%32] = w42[tid];
    if (tid < 2) sb1[tid] = b41[tid];
    if (tid < 4) sb2[tid] = b42[tid];
    __syncthreads();

    int i = blockIdx.x * 256 + tid;
    if (i >= B * P3) return;
    int b = i / P3, p = i % P3;

    const float4* hp = (const float4*)(g_c3cl + (size_t)i * 32);
    float l0 = sb1[0], l1 = sb1[1];
    float r0 = sb2[0], r1 = sb2[1], r2 = sb2[2], r3 = sb2[3];
    #pragma unroll
    for (int q = 0; q < 8; q++) {
        float4 v = hp[q];
        int c = q * 4;
        l0 = fmaf(v.x, sw1[0][c  ], l0); l1 = fmaf(v.x, sw1[1][c  ], l1);
        r0 = fmaf(v.x, sw2[0][c  ], r0); r1 = fmaf(v.x, sw2[1][c  ], r1);
        r2 = fmaf(v.x, sw2[2][c  ], r2); r3 = fmaf(v.x, sw2[3][c  ], r3);
        l0 = fmaf(v.y, sw1[0][c+1], l0); l1 = fmaf(v.y, sw1[1][c+1], l1);
        r0 = fmaf(v.y, sw2[0][c+1], r0); r1 = fmaf(v.y, sw2[1][c+1], r1);
        r2 = fmaf(v.y, sw2[2][c+1], r2); r3 = fmaf(v.y, sw2[3][c+1], r3);
        l0 = fmaf(v.z, sw1[0][c+2], l0); l1 = fmaf(v.z, sw1[1][c+2], l1);
        r0 = fmaf(v.z, sw2[0][c+2], r0); r1 = fmaf(v.z, sw2[1][c+2], r1);
        r2 = fmaf(v.z, sw2[2][c+2], r2); r3 = fmaf(v.z, sw2[3][c+2], r3);
        l0 = fmaf(v.w, sw1[0][c+3], l0); l1 = fmaf(v.w, sw1[1][c+3], l1);
        r0 = fmaf(v.w, sw2[0][c+3], r0); r1 = fmaf(v.w, sw2[1][c+3], r1);
        r2 = fmaf(v.w, sw2[2][c+3], r2); r3 = fmaf(v.w, sw2[3][c+3], r3);
    }
    float m  = fmaxf(l0, l1);
    float e0 = expf(l0 - m), e1 = expf(l1 - m);
    float inv = 1.f / (e0 + e1);

    float* regp  = out;
    float* probp = out + (size_t)B * 4 * P3;
    regp[(size_t)(b*4+0)*P3 + p] = r0;
    regp[(size_t)(b*4+1)*P3 + p] = r1;
    regp[(size_t)(b*4+2)*P3 + p] = r2;
    regp[(size_t)(b*4+3)*P3 + p] = r3;
    probp[(size_t)(b*2+0)*P3 + p] = e0 * inv;
    probp[(size_t)(b*2+1)*P3 + p] = e1 * inv;
}

// ---------------------------------------------------------------------------
extern "C" void kernel_launch(void* const* d_in, const int* in_sizes, int n_in,
                              void* d_out, int out_size)
{
    const float* x    = (const float*)d_in[0];
    const float* c1w  = (const float*)d_in[1];
    const float* c1b  = (const float*)d_in[2];
    const float* p1a  = (const float*)d_in[3];
    const float* c2w  = (const float*)d_in[4];
    const float* c2b  = (const float*)d_in[5];
    const float* p2a  = (const float*)d_in[6];
    const float* c3w  = (const float*)d_in[7];
    const float* c3b  = (const float*)d_in[8];
    const float* p3a  = (const float*)d_in[9];
    const float* c41w = (const float*)d_in[10];
    const float* c41b = (const float*)d_in[11];
    const float* c42w = (const float*)d_in[12];
    const float* c42b = (const float*)d_in[13];
    float* out = (float*)d_out;

    {
        dim3 blk(32, 4);
        dim3 grd((HP + 31) / 32, (HP + 3) / 4, B);
        k_conv1_pool<<<grd, blk>>>(x, c1w, c1b, p1a);
    }
    {
        dim3 blk(32, 8);
        dim3 grd((H2 + 63) / 64, (H2 + 7) / 8, B);
        k_conv2<<<grd, blk>>>(c2w, c2b, p2a);
    }
    {
        dim3 grd((H3 + 127) / 128, (H3 + 3) / 4, B);
        k_conv3_mma<<<grd, 256>>>(c3w, c3b, p3a);
    }
    {
        int blocks = (B * P3 + 255) / 256;
        k_heads<<<blocks, 256>>>(c41w, c41b, c42w, c42b, out);
    }
}

// round 5
// speedup vs baseline: 2.7541x; 1.0887x over previous
#include <cuda_runtime.h>
#include <cuda_bf16.h>
#include <math.h>
#include <stdint.h>

// ---------------------------------------------------------------------------
// MTCNN P-Net forward.
// conv1: scalar FFMA2 (norm+conv+prelu+pool), out channel-last padded [b][y][x][16]
// conv2: mma.sync bf16 hi/lo implicit GEMM (K=144, N=16), out channel-last [16]
// conv3: mma.sync bf16 hi/lo implicit GEMM (K=144, N=32) + FUSED 1x1 heads +
//        softmax (quad shuffle reduction) -> writes final output directly
// ---------------------------------------------------------------------------

#define B       16
#define H0      720
#define HP      359
#define H2      357
#define H3      355
#define P3      (H3*H3)

typedef unsigned long long ull;

__device__ __forceinline__ ull pack2(float a, float b) {
    ull r;
    asm("mov.b64 %0, {%1,%2};" : "=l"(r)
        : "r"(__float_as_uint(a)), "r"(__float_as_uint(b)));
    return r;
}
__device__ __forceinline__ void unpack2(ull v, float& a, float& b) {
    unsigned lo, hi;
    asm("mov.b64 {%0,%1}, %2;" : "=r"(lo), "=r"(hi) : "l"(v));
    a = __uint_as_float(lo); b = __uint_as_float(hi);
}
__device__ __forceinline__ void fma2(ull& d, ull a, ull b) {
    asm("fma.rn.f32x2 %0, %1, %2, %3;" : "=l"(d) : "l"(a), "l"(b), "l"(d));
}

// scratch (channel-last, 16-ch padded)
__device__ float g_p1cl[(size_t)B*HP*HP*16];  // conv1+pool out
__device__ float g_c2cl[(size_t)B*H2*H2*16];  // conv2 out

// ======================= mma.sync helpers ==================================
__device__ __forceinline__ void hilo2(float2 v, uint32_t& hi, uint32_t& lo) {
    __nv_bfloat162 h = __floats2bfloat162_rn(v.x, v.y);
    float rx = v.x - __bfloat162float(h.x);
    float ry = v.y - __bfloat162float(h.y);
    __nv_bfloat162 l = __floats2bfloat162_rn(rx, ry);
    hi = *(uint32_t*)&h; lo = *(uint32_t*)&l;
}
__device__ __forceinline__ void mma16816(float* d, const uint32_t* a,
                                         uint32_t b0, uint32_t b1) {
    asm volatile(
        "mma.sync.aligned.m16n8k16.row.col.f32.bf16.bf16.f32 "
        "{%0,%1,%2,%3}, {%4,%5,%6,%7}, {%8,%9}, {%0,%1,%2,%3};"
        : "+f"(d[0]), "+f"(d[1]), "+f"(d[2]), "+f"(d[3])
        : "r"(a[0]), "r"(a[1]), "r"(a[2]), "r"(a[3]), "r"(b0), "r"(b1));
}

// ---------------------------------------------------------------------------
// Kernel 1: normalize + conv1(3x3,3->10) + PReLU + maxpool2 -> ch-last pad16
// ---------------------------------------------------------------------------
__global__ __launch_bounds__(128) void k_conv1_pool(
    const float* __restrict__ x, const float* __restrict__ w1,
    const float* __restrict__ b1, const float* __restrict__ a1)
{
    __shared__ ull   sWp[5][3][9];
    __shared__ float sIn[3][10][66];
    __shared__ float sB[10], sA[10];

    const int b   = blockIdx.z;
    const int px0 = blockIdx.x * 32;
    const int py0 = blockIdx.y * 4;
    const int tid = threadIdx.y * 32 + threadIdx.x;

    for (int i = tid; i < 135; i += 128) {
        int cp = i / 27, ci = (i % 27) / 9, k = i % 9;
        sWp[cp][ci][k] = pack2(w1[(2*cp)*27 + ci*9 + k], w1[(2*cp+1)*27 + ci*9 + k]);
    }
    if (tid < 10) { sB[tid] = b1[tid]; sA[tid] = a1[tid]; }

    const int row0 = 2*py0, col0 = 2*px0;
    for (int i = tid; i < 3*10*66; i += 128) {
        int ci = i/660, r = (i%660)/66, c = i%66;
        int gr = row0 + r, gc = col0 + c;
        float v = 0.f;
        if (gr < H0 && gc < H0)
            v = (x[((b*3+ci)*H0 + gr)*H0 + gc] - 127.5f) * 0.0078125f;
        sIn[ci][r][c] = v;
    }
    __syncthreads();

    const int px = px0 + threadIdx.x;
    const int py = py0 + threadIdx.y;
    if (px >= HP || py >= HP) return;

    ull acc[5][4];
    #pragma unroll
    for (int cp = 0; cp < 5; cp++) {
        ull bb = pack2(sB[2*cp], sB[2*cp+1]);
        acc[cp][0]=bb; acc[cp][1]=bb; acc[cp][2]=bb; acc[cp][3]=bb;
    }

    const int lr = 2*threadIdx.y, lc = 2*threadIdx.x;
    #pragma unroll
    for (int ci = 0; ci < 3; ci++) {
        ull q[4][4];
        #pragma unroll
        for (int i = 0; i < 4; i++)
            #pragma unroll
            for (int j = 0; j < 4; j++) {
                float v = sIn[ci][lr+i][lc+j];
                q[i][j] = pack2(v, v);
            }
        #pragma unroll
        for (int ky = 0; ky < 3; ky++)
            #pragma unroll
            for (int kx = 0; kx < 3; kx++) {
                #pragma unroll
                for (int cp = 0; cp < 5; cp++) {
                    ull wp = sWp[cp][ci][ky*3+kx];
                    fma2(acc[cp][0], wp, q[ky  ][kx  ]);
                    fma2(acc[cp][1], wp, q[ky  ][kx+1]);
                    fma2(acc[cp][2], wp, q[ky+1][kx  ]);
                    fma2(acc[cp][3], wp, q[ky+1][kx+1]);
                }
            }
    }

    float v[16];
    #pragma unroll
    for (int cp = 0; cp < 5; cp++) {
        float a0 = sA[2*cp], a1v = sA[2*cp+1];
        float m0 = -INFINITY, m1 = -INFINITY;
        #pragma unroll
        for (int k = 0; k < 4; k++) {
            float v0, v1; unpack2(acc[cp][k], v0, v1);
            v0 = (v0 >= 0.f) ? v0 : a0*v0;
            v1 = (v1 >= 0.f) ? v1 : a1v*v1;
            m0 = fmaxf(m0, v0); m1 = fmaxf(m1, v1);
        }
        v[2*cp] = m0; v[2*cp+1] = m1;
    }
    #pragma unroll
    for (int c = 10; c < 16; c++) v[c] = 0.f;

    float* dst = &g_p1cl[((size_t)(b*HP + py)*HP + px)*16];
    #pragma unroll
    for (int q = 0; q < 4; q++)
        *(float4*)(dst + q*4) = make_float4(v[q*4],v[q*4+1],v[q*4+2],v[q*4+3]);
}

// ---------------------------------------------------------------------------
// Kernel 2: conv2 via mma.sync. Warp: 16px x 16co, K=144 (9 taps x 16ci pad).
// Block 256 = 128px row; 4 rows per block. Out channel-last [b][y][x][16].
// ---------------------------------------------------------------------------
__global__ __launch_bounds__(256) void k_conv2_mma(
    const float* __restrict__ w, const float* __restrict__ bias,
    const float* __restrict__ alpha)
{
    __shared__ __nv_bfloat16 sWh[9*16*16];   // [kc][co][ci]
    __shared__ __nv_bfloat16 sWl[9*16*16];
    __shared__ float sBA[32];

    const int b    = blockIdx.z;
    const int ox0  = blockIdx.x * 128;
    const int oy0  = blockIdx.y * 4;
    const int tid  = threadIdx.x;
    const int wid  = tid >> 5;
    const int lane = tid & 31;

    for (int i = tid; i < 2304; i += 256) {
        int kc = i >> 8, co = (i >> 4) & 15, ci = i & 15;
        int ky = kc / 3, kx = kc % 3;
        float wv = (ci < 10) ? w[((co*10 + ci)*3 + ky)*3 + kx] : 0.f;
        __nv_bfloat16 h = __float2bfloat16(wv);
        sWh[i] = h;
        sWl[i] = __float2bfloat16(wv - __bfloat162float(h));
    }
    if (tid < 16) { sBA[tid] = bias[tid]; sBA[16+tid] = alpha[tid]; }
    __syncthreads();

    const int g   = lane >> 2;
    const int ci0 = (lane & 3) * 2;

    const int p0  = ox0 + wid * 16 + g;
    const int p1  = p0 + 8;
    const int p0c = min(p0, H2 - 1);
    const int p1c = min(p1, H2 - 1);

    for (int r = 0; r < 4; r++) {
        const int oy = oy0 + r;
        if (oy >= H2) break;

        float acc[2][4];
        #pragma unroll
        for (int cg = 0; cg < 2; cg++)
            #pragma unroll
            for (int j = 0; j < 4; j++) acc[cg][j] = 0.f;

        #pragma unroll
        for (int kc = 0; kc < 9; kc++) {
            const int ky = kc / 3, kx = kc % 3;
            const float* rowp = &g_p1cl[(size_t)(b*HP + oy + ky) * HP * 16];
            float2 L00 = *(const float2*)&rowp[(p0c + kx)*16 + ci0];
            float2 L10 = *(const float2*)&rowp[(p1c + kx)*16 + ci0];
            float2 L01 = *(const float2*)&rowp[(p0c + kx)*16 + ci0 + 8];
            float2 L11 = *(const float2*)&rowp[(p1c + kx)*16 + ci0 + 8];
            uint32_t ah[4], al[4];
            hilo2(L00, ah[0], al[0]);
            hilo2(L10, ah[1], al[1]);
            hilo2(L01, ah[2], al[2]);
            hilo2(L11, ah[3], al[3]);

            #pragma unroll
            for (int cg = 0; cg < 2; cg++) {
                const int co = cg*8 + g;
                const int base = (kc*16 + co)*16;
                uint32_t bh0 = *(const uint32_t*)&sWh[base + ci0];
                uint32_t bh1 = *(const uint32_t*)&sWh[base + ci0 + 8];
                uint32_t bl0 = *(const uint32_t*)&sWl[base + ci0];
                uint32_t bl1 = *(const uint32_t*)&sWl[base + ci0 + 8];
                mma16816(acc[cg], ah, bh0, bh1);
                mma16816(acc[cg], ah, bl0, bl1);
                mma16816(acc[cg], al, bh0, bh1);
            }
        }

        const size_t rowbase = (size_t)(b*H2 + oy) * H2;
        #pragma unroll
        for (int cg = 0; cg < 2; cg++) {
            const int co = cg*8 + ci0;
            const float b0 = sBA[co], b1 = sBA[co+1];
            const float a0 = sBA[16+co], a1 = sBA[16+co+1];
            float t0 = acc[cg][0] + b0, t1 = acc[cg][1] + b1;
            float t2 = acc[cg][2] + b0, t3 = acc[cg][3] + b1;
            float2 o01, o23;
            o01.x = (t0 >= 0.f) ? t0 : a0*t0;
            o01.y = (t1 >= 0.f) ? t1 : a1*t1;
            o23.x = (t2 >= 0.f) ? t2 : a0*t2;
            o23.y = (t3 >= 0.f) ? t3 : a1*t3;
            if (p0 < H2) *(float2*)&g_c2cl[(rowbase + p0)*16 + co] = o01;
            if (p1 < H2) *(float2*)&g_c2cl[(rowbase + p1)*16 + co] = o23;
        }
    }
}

// ---------------------------------------------------------------------------
// Kernel 3: conv3 (mma.sync, 16px x 32co per warp) + fused 1x1 heads + softmax.
// Lane-quad (ci0 in {0,2,4,6}) holds all 32 channels of a pixel -> partial
// head dot products + shfl.bfly quad reduction -> write reg/prob directly.
// ---------------------------------------------------------------------------
__global__ __launch_bounds__(256) void k_conv3_heads(
    const float* __restrict__ w, const float* __restrict__ bias,
    const float* __restrict__ alpha,
    const float* __restrict__ w41, const float* __restrict__ b41,
    const float* __restrict__ w42, const float* __restrict__ b42,
    float* __restrict__ out)
{
    __shared__ __nv_bfloat16 sWh[9*32*16];   // [kc][co][ci]
    __shared__ __nv_bfloat16 sWl[9*32*16];
    __shared__ float sBA[64];
    __shared__ float sHW[6][32];             // rows 0-1: w41, 2-5: w42
    __shared__ float sHB[6];

    const int b    = blockIdx.z;
    const int ox0  = blockIdx.x * 128;
    const int oy0  = blockIdx.y * 4;
    const int tid  = threadIdx.x;
    const int wid  = tid >> 5;
    const int lane = tid & 31;

    for (int i = tid; i < 4608; i += 256) {
        int kc = i >> 9, co = (i >> 4) & 31, ci = i & 15;
        int ky = kc / 3, kx = kc % 3;
        float wv = w[((co*16 + ci)*3 + ky)*3 + kx];
        __nv_bfloat16 h = __float2bfloat16(wv);
        sWh[i] = h;
        sWl[i] = __float2bfloat16(wv - __bfloat162float(h));
    }
    if (tid < 32) { sBA[tid] = bias[tid]; sBA[32+tid] = alpha[tid]; }
    if (tid < 64)  sHW[tid/32][tid%32] = w41[tid];
    if (tid >= 64 && tid < 192) sHW[2 + (tid-64)/32][(tid-64)%32] = w42[tid-64];
    if (tid < 2) sHB[tid] = b41[tid];
    if (tid >= 2 && tid < 6) sHB[tid] = b42[tid-2];
    __syncthreads();

    const int g   = lane >> 2;
    const int ci0 = (lane & 3) * 2;
    const int q   = lane & 3;

    const int p0  = ox0 + wid * 16 + g;
    const int p1  = p0 + 8;
    const int p0c = min(p0, H3 - 1);
    const int p1c = min(p1, H3 - 1);

    float* regp  = out;                      // [B,4,355,355]
    float* probp = out + (size_t)B * 4 * P3; // [B,2,355,355]

    for (int r = 0; r < 4; r++) {
        const int oy = oy0 + r;
        if (oy >= H3) break;

        float acc[4][4];
        #pragma unroll
        for (int cg = 0; cg < 4; cg++)
            #pragma unroll
            for (int j = 0; j < 4; j++) acc[cg][j] = 0.f;

        #pragma unroll
        for (int kc = 0; kc < 9; kc++) {
            const int ky = kc / 3, kx = kc % 3;
            const float* rowp = &g_c2cl[(size_t)(b*H2 + oy + ky) * H2 * 16];
            float2 L00 = *(const float2*)&rowp[(p0c + kx)*16 + ci0];
            float2 L10 = *(const float2*)&rowp[(p1c + kx)*16 + ci0];
            float2 L01 = *(const float2*)&rowp[(p0c + kx)*16 + ci0 + 8];
            float2 L11 = *(const float2*)&rowp[(p1c + kx)*16 + ci0 + 8];
            uint32_t ah[4], al[4];
            hilo2(L00, ah[0], al[0]);
            hilo2(L10, ah[1], al[1]);
            hilo2(L01, ah[2], al[2]);
            hilo2(L11, ah[3], al[3]);

            #pragma unroll
            for (int cg = 0; cg < 4; cg++) {
                const int co = cg*8 + g;
                const int base = (kc*32 + co)*16;
                uint32_t bh0 = *(const uint32_t*)&sWh[base + ci0];
                uint32_t bh1 = *(const uint32_t*)&sWh[base + ci0 + 8];
                uint32_t bl0 = *(const uint32_t*)&sWl[base + ci0];
                uint32_t bl1 = *(const uint32_t*)&sWl[base + ci0 + 8];
                mma16816(acc[cg], ah, bh0, bh1);
                mma16816(acc[cg], ah, bl0, bl1);
                mma16816(acc[cg], al, bh0, bh1);
            }
        }

        const size_t rowbase = (size_t)oy * H3;
        // ---- fused heads for two pixels (p0: j01 = 0,1 ; p1: j01 = 2,3)
        #pragma unroll
        for (int px = 0; px < 2; px++) {
            const int pp = px ? p1 : p0;
            float o[6];
            #pragma unroll
            for (int k = 0; k < 6; k++) o[k] = 0.f;
            #pragma unroll
            for (int cg = 0; cg < 4; cg++) {
                #pragma unroll
                for (int j = 0; j < 2; j++) {
                    const int ch = cg*8 + ci0 + j;
                    float t = acc[cg][px*2 + j] + sBA[ch];
                    t = (t >= 0.f) ? t : sBA[32+ch]*t;
                    o[0] = fmaf(t, sHW[0][ch], o[0]);
                    o[1] = fmaf(t, sHW[1][ch], o[1]);
                    o[2] = fmaf(t, sHW[2][ch], o[2]);
                    o[3] = fmaf(t, sHW[3][ch], o[3]);
                    o[4] = fmaf(t, sHW[4][ch], o[4]);
                    o[5] = fmaf(t, sHW[5][ch], o[5]);
                }
            }
            #pragma unroll
            for (int off = 1; off <= 2; off <<= 1)
                #pragma unroll
                for (int k = 0; k < 6; k++)
                    o[k] += __shfl_xor_sync(0xffffffffu, o[k], off);

            float l0 = o[0] + sHB[0], l1 = o[1] + sHB[1];
            float m  = fmaxf(l0, l1);
            float e0 = expf(l0 - m), e1 = expf(l1 - m);
            float inv = 1.f / (e0 + e1);
            float pr0 = e0 * inv, pr1 = e1 * inv;

            if (pp < H3) {
                const size_t p = rowbase + pp;
                // lane q writes reg[q]; lanes 0,1 also write prob[q]
                regp[(size_t)(b*4+q)*P3 + p] = o[2+q] + sHB[2+q];
                if (q == 0) probp[(size_t)(b*2+0)*P3 + p] = pr0;
                if (q == 1) probp[(size_t)(b*2+1)*P3 + p] = pr1;
            }
        }
    }
}

// ---------------------------------------------------------------------------
extern "C" void kernel_launch(void* const* d_in, const int* in_sizes, int n_in,
                              void* d_out, int out_size)
{
    const float* x    = (const float*)d_in[0];
    const float* c1w  = (const float*)d_in[1];
    const float* c1b  = (const float*)d_in[2];
    const float* p1a  = (const float*)d_in[3];
    const float* c2w  = (const float*)d_in[4];
    const float* c2b  = (const float*)d_in[5];
    const float* p2a  = (const float*)d_in[6];
    const float* c3w  = (const float*)d_in[7];
    const float* c3b  = (const float*)d_in[8];
    const float* p3a  = (const float*)d_in[9];
    const float* c41w = (const float*)d_in[10];
    const float* c41b = (const float*)d_in[11];
    const float* c42w = (const float*)d_in[12];
    const float* c42b = (const float*)d_in[13];
    float* out = (float*)d_out;

    {
        dim3 blk(32, 4);
        dim3 grd((HP + 31) / 32, (HP + 3) / 4, B);
        k_conv1_pool<<<grd, blk>>>(x, c1w, c1b, p1a);
    }
    {
        dim3 grd((H2 + 127) / 128, (H2 + 3) / 4, B);
        k_conv2_mma<<<grd, 256>>>(c2w, c2b, p2a);
    }
    {
        dim3 grd((H3 + 127) / 128, (H3 + 3) / 4, B);
        k_conv3_heads<<<grd, 256>>>(c3w, c3b, p3a, c41w, c41b, c42w, c42b, out);
    }
}

// round 6
// speedup vs baseline: 2.8855x; 1.0477x over previous
#include <cuda_runtime.h>
#include <cuda_bf16.h>
#include <math.h>
#include <stdint.h>

// ---------------------------------------------------------------------------
// MTCNN P-Net forward.
// conv1: scalar FFMA2 (norm+conv+prelu+pool), sliding 2-row window (reg diet),
//        out channel-last padded [b][y][x][16]
// conv2: mma.sync bf16 hi/lo implicit GEMM (K=144, N=16), prefetch-pipelined
// conv3: mma.sync bf16 hi/lo (K=144, N=32) + fused 1x1 heads + softmax,
//        prefetch-pipelined
// ---------------------------------------------------------------------------

#define B       16
#define H0      720
#define HP      359
#define H2      357
#define H3      355
#define P3      (H3*H3)

typedef unsigned long long ull;

__device__ __forceinline__ ull pack2(float a, float b) {
    ull r;
    asm("mov.b64 %0, {%1,%2};" : "=l"(r)
        : "r"(__float_as_uint(a)), "r"(__float_as_uint(b)));
    return r;
}
__device__ __forceinline__ void unpack2(ull v, float& a, float& b) {
    unsigned lo, hi;
    asm("mov.b64 {%0,%1}, %2;" : "=r"(lo), "=r"(hi) : "l"(v));
    a = __uint_as_float(lo); b = __uint_as_float(hi);
}
__device__ __forceinline__ void fma2(ull& d, ull a, ull b) {
    asm("fma.rn.f32x2 %0, %1, %2, %3;" : "=l"(d) : "l"(a), "l"(b), "l"(d));
}

// scratch (channel-last, 16-ch padded)
__device__ float g_p1cl[(size_t)B*HP*HP*16];  // conv1+pool out
__device__ float g_c2cl[(size_t)B*H2*H2*16];  // conv2 out

// ======================= mma.sync helpers ==================================
__device__ __forceinline__ void hilo2(float2 v, uint32_t& hi, uint32_t& lo) {
    __nv_bfloat162 h = __floats2bfloat162_rn(v.x, v.y);
    float rx = v.x - __bfloat162float(h.x);
    float ry = v.y - __bfloat162float(h.y);
    __nv_bfloat162 l = __floats2bfloat162_rn(rx, ry);
    hi = *(uint32_t*)&h; lo = *(uint32_t*)&l;
}
__device__ __forceinline__ void mma16816(float* d, const uint32_t* a,
                                         uint32_t b0, uint32_t b1) {
    asm volatile(
        "mma.sync.aligned.m16n8k16.row.col.f32.bf16.bf16.f32 "
        "{%0,%1,%2,%3}, {%4,%5,%6,%7}, {%8,%9}, {%0,%1,%2,%3};"
        : "+f"(d[0]), "+f"(d[1]), "+f"(d[2]), "+f"(d[3])
        : "r"(a[0]), "r"(a[1]), "r"(a[2]), "r"(a[3]), "r"(b0), "r"(b1));
}

// ---------------------------------------------------------------------------
// Kernel 1: normalize + conv1(3x3,3->10) + PReLU + maxpool2 -> ch-last pad16
// Sliding 2-row packed window keeps register count low for occupancy.
// ---------------------------------------------------------------------------
struct ConvAcc { ull a[5][4]; };

__device__ __forceinline__ void conv1_taps(
    ull (&acc)[5][4], const ull sWp[5][3][9], int ci, int ky,
    const ull* top, const ull* bot)
{
    #pragma unroll
    for (int kx = 0; kx < 3; kx++) {
        #pragma unroll
        for (int cp = 0; cp < 5; cp++) {
            ull wp = sWp[cp][ci][ky*3+kx];
            fma2(acc[cp][0], wp, top[kx]);
            fma2(acc[cp][1], wp, top[kx+1]);
            fma2(acc[cp][2], wp, bot[kx]);
            fma2(acc[cp][3], wp, bot[kx+1]);
        }
    }
}

__global__ __launch_bounds__(128, 8) void k_conv1_pool(
    const float* __restrict__ x, const float* __restrict__ w1,
    const float* __restrict__ b1, const float* __restrict__ a1)
{
    __shared__ ull   sWp[5][3][9];
    __shared__ float sIn[3][10][66];
    __shared__ float sB[10], sA[10];

    const int b   = blockIdx.z;
    const int px0 = blockIdx.x * 32;
    const int py0 = blockIdx.y * 4;
    const int tid = threadIdx.y * 32 + threadIdx.x;

    for (int i = tid; i < 135; i += 128) {
        int cp = i / 27, ci = (i % 27) / 9, k = i % 9;
        sWp[cp][ci][k] = pack2(w1[(2*cp)*27 + ci*9 + k], w1[(2*cp+1)*27 + ci*9 + k]);
    }
    if (tid < 10) { sB[tid] = b1[tid]; sA[tid] = a1[tid]; }

    const int row0 = 2*py0, col0 = 2*px0;
    for (int i = tid; i < 3*10*66; i += 128) {
        int ci = i/660, r = (i%660)/66, c = i%66;
        int gr = row0 + r, gc = col0 + c;
        float v = 0.f;
        if (gr < H0 && gc < H0)
            v = (x[((b*3+ci)*H0 + gr)*H0 + gc] - 127.5f) * 0.0078125f;
        sIn[ci][r][c] = v;
    }
    __syncthreads();

    const int px = px0 + threadIdx.x;
    const int py = py0 + threadIdx.y;
    if (px >= HP || py >= HP) return;

    ull acc[5][4];
    #pragma unroll
    for (int cp = 0; cp < 5; cp++) {
        ull bb = pack2(sB[2*cp], sB[2*cp+1]);
        acc[cp][0]=bb; acc[cp][1]=bb; acc[cp][2]=bb; acc[cp][3]=bb;
    }

    const int lr = 2*threadIdx.y, lc = 2*threadIdx.x;
    #pragma unroll
    for (int ci = 0; ci < 3; ci++) {
        ull qa[4], qb[4];
        #pragma unroll
        for (int j = 0; j < 4; j++) { float v = sIn[ci][lr  ][lc+j]; qa[j] = pack2(v,v); }
        #pragma unroll
        for (int j = 0; j < 4; j++) { float v = sIn[ci][lr+1][lc+j]; qb[j] = pack2(v,v); }
        conv1_taps(acc, sWp, ci, 0, qa, qb);          // rows (lr, lr+1)
        #pragma unroll
        for (int j = 0; j < 4; j++) { float v = sIn[ci][lr+2][lc+j]; qa[j] = pack2(v,v); }
        conv1_taps(acc, sWp, ci, 1, qb, qa);          // rows (lr+1, lr+2)
        #pragma unroll
        for (int j = 0; j < 4; j++) { float v = sIn[ci][lr+3][lc+j]; qb[j] = pack2(v,v); }
        conv1_taps(acc, sWp, ci, 2, qa, qb);          // rows (lr+2, lr+3)
    }

    float v[16];
    #pragma unroll
    for (int cp = 0; cp < 5; cp++) {
        float a0 = sA[2*cp], a1v = sA[2*cp+1];
        float m0 = -INFINITY, m1 = -INFINITY;
        #pragma unroll
        for (int k = 0; k < 4; k++) {
            float v0, v1; unpack2(acc[cp][k], v0, v1);
            v0 = (v0 >= 0.f) ? v0 : a0*v0;
            v1 = (v1 >= 0.f) ? v1 : a1v*v1;
            m0 = fmaxf(m0, v0); m1 = fmaxf(m1, v1);
        }
        v[2*cp] = m0; v[2*cp+1] = m1;
    }
    #pragma unroll
    for (int c = 10; c < 16; c++) v[c] = 0.f;

    float* dst = &g_p1cl[((size_t)(b*HP + py)*HP + px)*16];
    #pragma unroll
    for (int q = 0; q < 4; q++)
        *(float4*)(dst + q*4) = make_float4(v[q*4],v[q*4+1],v[q*4+2],v[q*4+3]);
}

// ---------------------------------------------------------------------------
// Kernel 2: conv2 via mma.sync, prefetch-pipelined. Warp: 16px x 16co, K=144.
// ---------------------------------------------------------------------------
__global__ __launch_bounds__(256) void k_conv2_mma(
    const float* __restrict__ w, const float* __restrict__ bias,
    const float* __restrict__ alpha)
{
    __shared__ __nv_bfloat16 sWh[9*16*16];   // [kc][co][ci]
    __shared__ __nv_bfloat16 sWl[9*16*16];
    __shared__ float sBA[32];

    const int b    = blockIdx.z;
    const int ox0  = blockIdx.x * 128;
    const int oy0  = blockIdx.y * 4;
    const int tid  = threadIdx.x;
    const int wid  = tid >> 5;
    const int lane = tid & 31;

    for (int i = tid; i < 2304; i += 256) {
        int kc = i >> 8, co = (i >> 4) & 15, ci = i & 15;
        int ky = kc / 3, kx = kc % 3;
        float wv = (ci < 10) ? w[((co*10 + ci)*3 + ky)*3 + kx] : 0.f;
        __nv_bfloat16 h = __float2bfloat16(wv);
        sWh[i] = h;
        sWl[i] = __float2bfloat16(wv - __bfloat162float(h));
    }
    if (tid < 16) { sBA[tid] = bias[tid]; sBA[16+tid] = alpha[tid]; }
    __syncthreads();

    const int g   = lane >> 2;
    const int ci0 = (lane & 3) * 2;

    const int p0  = ox0 + wid * 16 + g;
    const int p1  = p0 + 8;
    const int p0c = min(p0, H2 - 1);
    const int p1c = min(p1, H2 - 1);

    for (int r = 0; r < 4; r++) {
        const int oy = oy0 + r;
        if (oy >= H2) break;

        const float* row[3];
        #pragma unroll
        for (int ky = 0; ky < 3; ky++)
            row[ky] = &g_p1cl[(size_t)(b*HP + oy + ky) * HP * 16];

        float acc[2][4];
        #pragma unroll
        for (int cg = 0; cg < 2; cg++)
            #pragma unroll
            for (int j = 0; j < 4; j++) acc[cg][j] = 0.f;

        float2 cur[4], nxt[4];
        cur[0] = *(const float2*)&row[0][(p0c)*16 + ci0];
        cur[1] = *(const float2*)&row[0][(p1c)*16 + ci0];
        cur[2] = *(const float2*)&row[0][(p0c)*16 + ci0 + 8];
        cur[3] = *(const float2*)&row[0][(p1c)*16 + ci0 + 8];

        #pragma unroll
        for (int kc = 0; kc < 9; kc++) {
            if (kc < 8) {
                const int ky = (kc+1) / 3, kx = (kc+1) % 3;
                const float* rp = row[ky];
                nxt[0] = *(const float2*)&rp[(p0c + kx)*16 + ci0];
                nxt[1] = *(const float2*)&rp[(p1c + kx)*16 + ci0];
                nxt[2] = *(const float2*)&rp[(p0c + kx)*16 + ci0 + 8];
                nxt[3] = *(const float2*)&rp[(p1c + kx)*16 + ci0 + 8];
            }
            uint32_t ah[4], al[4];
            hilo2(cur[0], ah[0], al[0]);
            hilo2(cur[1], ah[1], al[1]);
            hilo2(cur[2], ah[2], al[2]);
            hilo2(cur[3], ah[3], al[3]);

            #pragma unroll
            for (int cg = 0; cg < 2; cg++) {
                const int co = cg*8 + g;
                const int base = (kc*16 + co)*16;
                uint32_t bh0 = *(const uint32_t*)&sWh[base + ci0];
                uint32_t bh1 = *(const uint32_t*)&sWh[base + ci0 + 8];
                uint32_t bl0 = *(const uint32_t*)&sWl[base + ci0];
                uint32_t bl1 = *(const uint32_t*)&sWl[base + ci0 + 8];
                mma16816(acc[cg], ah, bh0, bh1);
                mma16816(acc[cg], ah, bl0, bl1);
                mma16816(acc[cg], al, bh0, bh1);
            }
            #pragma unroll
            for (int j = 0; j < 4; j++) cur[j] = nxt[j];
        }

        const size_t rowbase = (size_t)(b*H2 + oy) * H2;
        #pragma unroll
        for (int cg = 0; cg < 2; cg++) {
            const int co = cg*8 + ci0;
            const float b0 = sBA[co], b1 = sBA[co+1];
            const float a0 = sBA[16+co], a1 = sBA[16+co+1];
            float t0 = acc[cg][0] + b0, t1 = acc[cg][1] + b1;
            float t2 = acc[cg][2] + b0, t3 = acc[cg][3] + b1;
            float2 o01, o23;
            o01.x = (t0 >= 0.f) ? t0 : a0*t0;
            o01.y = (t1 >= 0.f) ? t1 : a1*t1;
            o23.x = (t2 >= 0.f) ? t2 : a0*t2;
            o23.y = (t3 >= 0.f) ? t3 : a1*t3;
            if (p0 < H2) *(float2*)&g_c2cl[(rowbase + p0)*16 + co] = o01;
            if (p1 < H2) *(float2*)&g_c2cl[(rowbase + p1)*16 + co] = o23;
        }
    }
}

// ---------------------------------------------------------------------------
// Kernel 3: conv3 (mma.sync, 16px x 32co per warp) + fused heads + softmax,
// prefetch-pipelined.
// ---------------------------------------------------------------------------
__global__ __launch_bounds__(256) void k_conv3_heads(
    const float* __restrict__ w, const float* __restrict__ bias,
    const float* __restrict__ alpha,
    const float* __restrict__ w41, const float* __restrict__ b41,
    const float* __restrict__ w42, const float* __restrict__ b42,
    float* __restrict__ out)
{
    __shared__ __nv_bfloat16 sWh[9*32*16];   // [kc][co][ci]
    __shared__ __nv_bfloat16 sWl[9*32*16];
    __shared__ float sBA[64];
    __shared__ float sHW[6][32];             // rows 0-1: w41, 2-5: w42
    __shared__ float sHB[6];

    const int b    = blockIdx.z;
    const int ox0  = blockIdx.x * 128;
    const int oy0  = blockIdx.y * 4;
    const int tid  = threadIdx.x;
    const int wid  = tid >> 5;
    const int lane = tid & 31;

    for (int i = tid; i < 4608; i += 256) {
        int kc = i >> 9, co = (i >> 4) & 31, ci = i & 15;
        int ky = kc / 3, kx = kc % 3;
        float wv = w[((co*16 + ci)*3 + ky)*3 + kx];
        __nv_bfloat16 h = __float2bfloat16(wv);
        sWh[i] = h;
        sWl[i] = __float2bfloat16(wv - __bfloat162float(h));
    }
    if (tid < 32) { sBA[tid] = bias[tid]; sBA[32+tid] = alpha[tid]; }
    if (tid < 64)  sHW[tid/32][tid%32] = w41[tid];
    if (tid >= 64 && tid < 192) sHW[2 + (tid-64)/32][(tid-64)%32] = w42[tid-64];
    if (tid < 2) sHB[tid] = b41[tid];
    if (tid >= 2 && tid < 6) sHB[tid] = b42[tid-2];
    __syncthreads();

    const int g   = lane >> 2;
    const int ci0 = (lane & 3) * 2;
    const int q   = lane & 3;

    const int p0  = ox0 + wid * 16 + g;
    const int p1  = p0 + 8;
    const int p0c = min(p0, H3 - 1);
    const int p1c = min(p1, H3 - 1);

    float* regp  = out;                      // [B,4,355,355]
    float* probp = out + (size_t)B * 4 * P3; // [B,2,355,355]

    for (int r = 0; r < 4; r++) {
        const int oy = oy0 + r;
        if (oy >= H3) break;

        const float* row[3];
        #pragma unroll
        for (int ky = 0; ky < 3; ky++)
            row[ky] = &g_c2cl[(size_t)(b*H2 + oy + ky) * H2 * 16];

        float acc[4][4];
        #pragma unroll
        for (int cg = 0; cg < 4; cg++)
            #pragma unroll
            for (int j = 0; j < 4; j++) acc[cg][j] = 0.f;

        float2 cur[4], nxt[4];
        cur[0] = *(const float2*)&row[0][(p0c)*16 + ci0];
        cur[1] = *(const float2*)&row[0][(p1c)*16 + ci0];
        cur[2] = *(const float2*)&row[0][(p0c)*16 + ci0 + 8];
        cur[3] = *(const float2*)&row[0][(p1c)*16 + ci0 + 8];

        #pragma unroll
        for (int kc = 0; kc < 9; kc++) {
            if (kc < 8) {
                const int ky = (kc+1) / 3, kx = (kc+1) % 3;
                const float* rp = row[ky];
                nxt[0] = *(const float2*)&rp[(p0c + kx)*16 + ci0];
                nxt[1] = *(const float2*)&rp[(p1c + kx)*16 + ci0];
                nxt[2] = *(const float2*)&rp[(p0c + kx)*16 + ci0 + 8];
                nxt[3] = *(const float2*)&rp[(p1c + kx)*16 + ci0 + 8];
            }
            uint32_t ah[4], al[4];
            hilo2(cur[0], ah[0], al[0]);
            hilo2(cur[1], ah[1], al[1]);
            hilo2(cur[2], ah[2], al[2]);
            hilo2(cur[3], ah[3], al[3]);

            #pragma unroll
            for (int cg = 0; cg < 4; cg++) {
                const int co = cg*8 + g;
                const int base = (kc*32 + co)*16;
                uint32_t bh0 = *(const uint32_t*)&sWh[base + ci0];
                uint32_t bh1 = *(const uint32_t*)&sWh[base + ci0 + 8];
                uint32_t bl0 = *(const uint32_t*)&sWl[base + ci0];
                uint32_t bl1 = *(const uint32_t*)&sWl[base + ci0 + 8];
                mma16816(acc[cg], ah, bh0, bh1);
                mma16816(acc[cg], ah, bl0, bl1);
                mma16816(acc[cg], al, bh0, bh1);
            }
            #pragma unroll
            for (int j = 0; j < 4; j++) cur[j] = nxt[j];
        }

        const size_t rowbase = (size_t)oy * H3;
        #pragma unroll
        for (int px = 0; px < 2; px++) {
            const int pp = px ? p1 : p0;
            float o[6];
            #pragma unroll
            for (int k = 0; k < 6; k++) o[k] = 0.f;
            #pragma unroll
            for (int cg = 0; cg < 4; cg++) {
                #pragma unroll
                for (int j = 0; j < 2; j++) {
                    const int ch = cg*8 + ci0 + j;
                    float t = acc[cg][px*2 + j] + sBA[ch];
                    t = (t >= 0.f) ? t : sBA[32+ch]*t;
                    o[0] = fmaf(t, sHW[0][ch], o[0]);
                    o[1] = fmaf(t, sHW[1][ch], o[1]);
                    o[2] = fmaf(t, sHW[2][ch], o[2]);
                    o[3] = fmaf(t, sHW[3][ch], o[3]);
                    o[4] = fmaf(t, sHW[4][ch], o[4]);
                    o[5] = fmaf(t, sHW[5][ch], o[5]);
                }
            }
            #pragma unroll
            for (int off = 1; off <= 2; off <<= 1)
                #pragma unroll
                for (int k = 0; k < 6; k++)
                    o[k] += __shfl_xor_sync(0xffffffffu, o[k], off);

            float l0 = o[0] + sHB[0], l1 = o[1] + sHB[1];
            float m  = fmaxf(l0, l1);
            float e0 = expf(l0 - m), e1 = expf(l1 - m);
            float inv = 1.f / (e0 + e1);
            float pr0 = e0 * inv, pr1 = e1 * inv;

            if (pp < H3) {
                const size_t p = rowbase + pp;
                regp[(size_t)(b*4+q)*P3 + p] = o[2+q] + sHB[2+q];
                if (q == 0) probp[(size_t)(b*2+0)*P3 + p] = pr0;
                if (q == 1) probp[(size_t)(b*2+1)*P3 + p] = pr1;
            }
        }
    }
}

// ---------------------------------------------------------------------------
extern "C" void kernel_launch(void* const* d_in, const int* in_sizes, int n_in,
                              void* d_out, int out_size)
{
    const float* x    = (const float*)d_in[0];
    const float* c1w  = (const float*)d_in[1];
    const float* c1b  = (const float*)d_in[2];
    const float* p1a  = (const float*)d_in[3];
    const float* c2w  = (const float*)d_in[4];
    const float* c2b  = (const float*)d_in[5];
    const float* p2a  = (const float*)d_in[6];
    const float* c3w  = (const float*)d_in[7];
    const float* c3b  = (const float*)d_in[8];
    const float* p3a  = (const float*)d_in[9];
    const float* c41w = (const float*)d_in[10];
    const float* c41b = (const float*)d_in[11];
    const float* c42w = (const float*)d_in[12];
    const float* c42b = (const float*)d_in[13];
    float* out = (float*)d_out;

    {
        dim3 blk(32, 4);
        dim3 grd((HP + 31) / 32, (HP + 3) / 4, B);
        k_conv1_pool<<<grd, blk>>>(x, c1w, c1b, p1a);
    }
    {
        dim3 grd((H2 + 127) / 128, (H2 + 3) / 4, B);
        k_conv2_mma<<<grd, 256>>>(c2w, c2b, p2a);
    }
    {
        dim3 grd((H3 + 127) / 128, (H3 + 3) / 4, B);
        k_conv3_heads<<<grd, 256>>>(c3w, c3b, p3a, c41w, c41b, c42w, c42b, out);
    }
}

// round 7
// speedup vs baseline: 3.1883x; 1.1049x over previous
#include <cuda_runtime.h>
#include <cuda_bf16.h>
#include <math.h>
#include <stdint.h>

// ---------------------------------------------------------------------------
// MTCNN P-Net forward.
// conv1: scalar FFMA2, smem tile pre-packed (v,v) -> pure LDS.64+FFMA2 loop
// conv2: mma.sync bf16 hi/lo (K=144,N=16), per-lane uint4 B-fragments
// conv3: mma.sync bf16 hi/lo (K=144,N=32) + fused heads, uint4 B-fragments
// ---------------------------------------------------------------------------

#define B       16
#define H0      720
#define HP      359
#define H2      357
#define H3      355
#define P3      (H3*H3)

typedef unsigned long long ull;

__device__ __forceinline__ ull pack2(float a, float b) {
    ull r;
    asm("mov.b64 %0, {%1,%2};" : "=l"(r)
        : "r"(__float_as_uint(a)), "r"(__float_as_uint(b)));
    return r;
}
__device__ __forceinline__ void unpack2(ull v, float& a, float& b) {
    unsigned lo, hi;
    asm("mov.b64 {%0,%1}, %2;" : "=r"(lo), "=r"(hi) : "l"(v));
    a = __uint_as_float(lo); b = __uint_as_float(hi);
}
__device__ __forceinline__ void fma2(ull& d, ull a, ull b) {
    asm("fma.rn.f32x2 %0, %1, %2, %3;" : "=l"(d) : "l"(a), "l"(b), "l"(d));
}

// scratch (channel-last, 16-ch padded)
__device__ float g_p1cl[(size_t)B*HP*HP*16];  // conv1+pool out
__device__ float g_c2cl[(size_t)B*H2*H2*16];  // conv2 out

// ======================= mma.sync helpers ==================================
__device__ __forceinline__ void hilo2(float2 v, uint32_t& hi, uint32_t& lo) {
    __nv_bfloat162 h = __floats2bfloat162_rn(v.x, v.y);
    float rx = v.x - __bfloat162float(h.x);
    float ry = v.y - __bfloat162float(h.y);
    __nv_bfloat162 l = __floats2bfloat162_rn(rx, ry);
    hi = *(uint32_t*)&h; lo = *(uint32_t*)&l;
}
__device__ __forceinline__ void mma16816(float* d, const uint32_t* a,
                                         uint32_t b0, uint32_t b1) {
    asm volatile(
        "mma.sync.aligned.m16n8k16.row.col.f32.bf16.bf16.f32 "
        "{%0,%1,%2,%3}, {%4,%5,%6,%7}, {%8,%9}, {%0,%1,%2,%3};"
        : "+f"(d[0]), "+f"(d[1]), "+f"(d[2]), "+f"(d[3])
        : "r"(a[0]), "r"(a[1]), "r"(a[2]), "r"(a[3]), "r"(b0), "r"(b1));
}

// bf16 hi/lo of a single weight value
__device__ __forceinline__ void whl(float wv, __nv_bfloat16& h, __nv_bfloat16& l) {
    h = __float2bfloat16(wv);
    l = __float2bfloat16(wv - __bfloat162float(h));
}

// ---------------------------------------------------------------------------
// Kernel 1: normalize + conv1(3x3,3->10) + PReLU + maxpool2 -> ch-last pad16
// smem tile pre-packed (v,v): inner loop is LDS.64 + FFMA2 only.
// ---------------------------------------------------------------------------
__device__ __forceinline__ void conv1_taps(
    ull (&acc)[5][4], const ull sWp[5][3][9], int ci, int ky,
    const ull* top, const ull* bot)
{
    #pragma unroll
    for (int kx = 0; kx < 3; kx++) {
        #pragma unroll
        for (int cp = 0; cp < 5; cp++) {
            ull wp = sWp[cp][ci][ky*3+kx];
            fma2(acc[cp][0], wp, top[kx]);
            fma2(acc[cp][1], wp, top[kx+1]);
            fma2(acc[cp][2], wp, bot[kx]);
            fma2(acc[cp][3], wp, bot[kx+1]);
        }
    }
}

__global__ __launch_bounds__(128, 8) void k_conv1_pool(
    const float* __restrict__ x, const float* __restrict__ w1,
    const float* __restrict__ b1, const float* __restrict__ a1)
{
    __shared__ ull   sWp[5][3][9];
    __shared__ ull   sIn[3][10][66];   // pre-packed (v,v)
    __shared__ float sB[10], sA[10];

    const int b   = blockIdx.z;
    const int px0 = blockIdx.x * 32;
    const int py0 = blockIdx.y * 4;
    const int tid = threadIdx.y * 32 + threadIdx.x;

    for (int i = tid; i < 135; i += 128) {
        int cp = i / 27, ci = (i % 27) / 9, k = i % 9;
        sWp[cp][ci][k] = pack2(w1[(2*cp)*27 + ci*9 + k], w1[(2*cp+1)*27 + ci*9 + k]);
    }
    if (tid < 10) { sB[tid] = b1[tid]; sA[tid] = a1[tid]; }

    const int row0 = 2*py0, col0 = 2*px0;
    for (int i = tid; i < 3*10*66; i += 128) {
        int ci = i/660, r = (i%660)/66, c = i%66;
        int gr = row0 + r, gc = col0 + c;
        float v = 0.f;
        if (gr < H0 && gc < H0)
            v = (x[((b*3+ci)*H0 + gr)*H0 + gc] - 127.5f) * 0.0078125f;
        sIn[ci][r][c] = pack2(v, v);
    }
    __syncthreads();

    const int px = px0 + threadIdx.x;
    const int py = py0 + threadIdx.y;
    if (px >= HP || py >= HP) return;

    ull acc[5][4];
    #pragma unroll
    for (int cp = 0; cp < 5; cp++) {
        ull bb = pack2(sB[2*cp], sB[2*cp+1]);
        acc[cp][0]=bb; acc[cp][1]=bb; acc[cp][2]=bb; acc[cp][3]=bb;
    }

    const int lr = 2*threadIdx.y, lc = 2*threadIdx.x;
    #pragma unroll
    for (int ci = 0; ci < 3; ci++) {
        ull qa[4], qb[4];
        #pragma unroll
        for (int j = 0; j < 4; j++) qa[j] = sIn[ci][lr  ][lc+j];
        #pragma unroll
        for (int j = 0; j < 4; j++) qb[j] = sIn[ci][lr+1][lc+j];
        conv1_taps(acc, sWp, ci, 0, qa, qb);
        #pragma unroll
        for (int j = 0; j < 4; j++) qa[j] = sIn[ci][lr+2][lc+j];
        conv1_taps(acc, sWp, ci, 1, qb, qa);
        #pragma unroll
        for (int j = 0; j < 4; j++) qb[j] = sIn[ci][lr+3][lc+j];
        conv1_taps(acc, sWp, ci, 2, qa, qb);
    }

    float v[16];
    #pragma unroll
    for (int cp = 0; cp < 5; cp++) {
        float a0 = sA[2*cp], a1v = sA[2*cp+1];
        float m0 = -INFINITY, m1 = -INFINITY;
        #pragma unroll
        for (int k = 0; k < 4; k++) {
            float v0, v1; unpack2(acc[cp][k], v0, v1);
            v0 = (v0 >= 0.f) ? v0 : a0*v0;
            v1 = (v1 >= 0.f) ? v1 : a1v*v1;
            m0 = fmaxf(m0, v0); m1 = fmaxf(m1, v1);
        }
        v[2*cp] = m0; v[2*cp+1] = m1;
    }
    #pragma unroll
    for (int c = 10; c < 16; c++) v[c] = 0.f;

    float* dst = &g_p1cl[((size_t)(b*HP + py)*HP + px)*16];
    #pragma unroll
    for (int q = 0; q < 4; q++)
        *(float4*)(dst + q*4) = make_float4(v[q*4],v[q*4+1],v[q*4+2],v[q*4+3]);
}

// ---------------------------------------------------------------------------
// Kernel 2: conv2 via mma.sync, per-lane uint4 B-frags. 16px x 16co, K=144.
// ---------------------------------------------------------------------------
__global__ __launch_bounds__(256) void k_conv2_mma(
    const float* __restrict__ w, const float* __restrict__ bias,
    const float* __restrict__ alpha)
{
    __shared__ uint4 sWf[9*2*32];    // [kc][cg][lane] = (bh0,bh1,bl0,bl1)
    __shared__ float sBA[32];

    const int b    = blockIdx.z;
    const int ox0  = blockIdx.x * 128;
    const int oy0  = blockIdx.y * 4;
    const int tid  = threadIdx.x;
    const int wid  = tid >> 5;
    const int lane = tid & 31;

    // stage per-lane fragments: frag f -> kc=f/64, cg=(f>>5)&1, lane=f&31
    for (int f = tid; f < 9*2*32; f += 256) {
        int kc = f >> 6, cg = (f >> 5) & 1, ln = f & 31;
        int g = ln >> 2, ci0 = (ln & 3) * 2;
        int co = cg*8 + g;
        int ky = kc / 3, kx = kc % 3;
        __nv_bfloat16 h0,l0,h1,l1,h2,l2,h3,l3;
        float w0 = (ci0   < 10) ? w[((co*10 + ci0  )*3 + ky)*3 + kx] : 0.f;
        float w1v= (ci0+1 < 10) ? w[((co*10 + ci0+1)*3 + ky)*3 + kx] : 0.f;
        float w2 = (ci0+8 < 10) ? w[((co*10 + ci0+8)*3 + ky)*3 + kx] : 0.f;
        float w3 = (ci0+9 < 10) ? w[((co*10 + ci0+9)*3 + ky)*3 + kx] : 0.f;
        whl(w0,h0,l0); whl(w1v,h1,l1); whl(w2,h2,l2); whl(w3,h3,l3);
        __nv_bfloat162 bh0 = {h0,h1}, bh1 = {h2,h3}, bl0 = {l0,l1}, bl1 = {l2,l3};
        sWf[f] = make_uint4(*(uint32_t*)&bh0, *(uint32_t*)&bh1,
                            *(uint32_t*)&bl0, *(uint32_t*)&bl1);
    }
    if (tid < 16) { sBA[tid] = bias[tid]; sBA[16+tid] = alpha[tid]; }
    __syncthreads();

    const int g   = lane >> 2;
    const int ci0 = (lane & 3) * 2;

    const int p0  = ox0 + wid * 16 + g;
    const int p1  = p0 + 8;
    const int p0c = min(p0, H2 - 1);
    const int p1c = min(p1, H2 - 1);

    for (int r = 0; r < 4; r++) {
        const int oy = oy0 + r;
        if (oy >= H2) break;

        const float* row[3];
        #pragma unroll
        for (int ky = 0; ky < 3; ky++)
            row[ky] = &g_p1cl[(size_t)(b*HP + oy + ky) * HP * 16];

        float acc[2][4];
        #pragma unroll
        for (int cg = 0; cg < 2; cg++)
            #pragma unroll
            for (int j = 0; j < 4; j++) acc[cg][j] = 0.f;

        float2 cur[4], nxt[4];
        cur[0] = *(const float2*)&row[0][(p0c)*16 + ci0];
        cur[1] = *(const float2*)&row[0][(p1c)*16 + ci0];
        cur[2] = *(const float2*)&row[0][(p0c)*16 + ci0 + 8];
        cur[3] = *(const float2*)&row[0][(p1c)*16 + ci0 + 8];

        #pragma unroll
        for (int kc = 0; kc < 9; kc++) {
            if (kc < 8) {
                const int ky = (kc+1) / 3, kx = (kc+1) % 3;
                const float* rp = row[ky];
                nxt[0] = *(const float2*)&rp[(p0c + kx)*16 + ci0];
                nxt[1] = *(const float2*)&rp[(p1c + kx)*16 + ci0];
                nxt[2] = *(const float2*)&rp[(p0c + kx)*16 + ci0 + 8];
                nxt[3] = *(const float2*)&rp[(p1c + kx)*16 + ci0 + 8];
            }
            uint32_t ah[4], al[4];
            hilo2(cur[0], ah[0], al[0]);
            hilo2(cur[1], ah[1], al[1]);
            hilo2(cur[2], ah[2], al[2]);
            hilo2(cur[3], ah[3], al[3]);

            #pragma unroll
            for (int cg = 0; cg < 2; cg++) {
                uint4 f = sWf[(kc*2 + cg)*32 + lane];
                mma16816(acc[cg], ah, f.x, f.y);
                mma16816(acc[cg], ah, f.z, f.w);
                mma16816(acc[cg], al, f.x, f.y);
            }
            #pragma unroll
            for (int j = 0; j < 4; j++) cur[j] = nxt[j];
        }

        const size_t rowbase = (size_t)(b*H2 + oy) * H2;
        #pragma unroll
        for (int cg = 0; cg < 2; cg++) {
            const int co = cg*8 + ci0;
            const float b0 = sBA[co], b1 = sBA[co+1];
            const float a0 = sBA[16+co], a1 = sBA[16+co+1];
            float t0 = acc[cg][0] + b0, t1 = acc[cg][1] + b1;
            float t2 = acc[cg][2] + b0, t3 = acc[cg][3] + b1;
            float2 o01, o23;
            o01.x = (t0 >= 0.f) ? t0 : a0*t0;
            o01.y = (t1 >= 0.f) ? t1 : a1*t1;
            o23.x = (t2 >= 0.f) ? t2 : a0*t2;
            o23.y = (t3 >= 0.f) ? t3 : a1*t3;
            if (p0 < H2) *(float2*)&g_c2cl[(rowbase + p0)*16 + co] = o01;
            if (p1 < H2) *(float2*)&g_c2cl[(rowbase + p1)*16 + co] = o23;
        }
    }
}

// ---------------------------------------------------------------------------
// Kernel 3: conv3 (16px x 32co per warp) + fused heads, uint4 B-frags.
// ---------------------------------------------------------------------------
__global__ __launch_bounds__(256) void k_conv3_heads(
    const float* __restrict__ w, const float* __restrict__ bias,
    const float* __restrict__ alpha,
    const float* __restrict__ w41, const float* __restrict__ b41,
    const float* __restrict__ w42, const float* __restrict__ b42,
    float* __restrict__ out)
{
    __shared__ uint4 sWf[9*4*32];    // [kc][cg][lane]
    __shared__ float sBA[64];
    __shared__ float sHW[6][32];
    __shared__ float sHB[6];

    const int b    = blockIdx.z;
    const int ox0  = blockIdx.x * 128;
    const int oy0  = blockIdx.y * 4;
    const int tid  = threadIdx.x;
    const int wid  = tid >> 5;
    const int lane = tid & 31;

    for (int f = tid; f < 9*4*32; f += 256) {
        int kc = f >> 7, cg = (f >> 5) & 3, ln = f & 31;
        int g = ln >> 2, ci0 = (ln & 3) * 2;
        int co = cg*8 + g;
        int ky = kc / 3, kx = kc % 3;
        __nv_bfloat16 h0,l0,h1,l1,h2,l2,h3,l3;
        whl(w[((co*16 + ci0  )*3 + ky)*3 + kx], h0, l0);
        whl(w[((co*16 + ci0+1)*3 + ky)*3 + kx], h1, l1);
        whl(w[((co*16 + ci0+8)*3 + ky)*3 + kx], h2, l2);
        whl(w[((co*16 + ci0+9)*3 + ky)*3 + kx], h3, l3);
        __nv_bfloat162 bh0 = {h0,h1}, bh1 = {h2,h3}, bl0 = {l0,l1}, bl1 = {l2,l3};
        sWf[f] = make_uint4(*(uint32_t*)&bh0, *(uint32_t*)&bh1,
                            *(uint32_t*)&bl0, *(uint32_t*)&bl1);
    }
    if (tid < 32) { sBA[tid] = bias[tid]; sBA[32+tid] = alpha[tid]; }
    if (tid < 64)  sHW[tid/32][tid%32] = w41[tid];
    if (tid >= 64 && tid < 192) sHW[2 + (tid-64)/32][(tid-64)%32] = w42[tid-64];
    if (tid < 2) sHB[tid] = b41[tid];
    if (tid >= 2 && tid < 6) sHB[tid] = b42[tid-2];
    __syncthreads();

    const int g   = lane >> 2;
    const int ci0 = (lane & 3) * 2;
    const int q   = lane & 3;

    const int p0  = ox0 + wid * 16 + g;
    const int p1  = p0 + 8;
    const int p0c = min(p0, H3 - 1);
    const int p1c = min(p1, H3 - 1);

    float* regp  = out;
    float* probp = out + (size_t)B * 4 * P3;

    for (int r = 0; r < 4; r++) {
        const int oy = oy0 + r;
        if (oy >= H3) break;

        const float* row[3];
        #pragma unroll
        for (int ky = 0; ky < 3; ky++)
            row[ky] = &g_c2cl[(size_t)(b*H2 + oy + ky) * H2 * 16];

        float acc[4][4];
        #pragma unroll
        for (int cg = 0; cg < 4; cg++)
            #pragma unroll
            for (int j = 0; j < 4; j++) acc[cg][j] = 0.f;

        float2 cur[4], nxt[4];
        cur[0] = *(const float2*)&row[0][(p0c)*16 + ci0];
        cur[1] = *(const float2*)&row[0][(p1c)*16 + ci0];
        cur[2] = *(const float2*)&row[0][(p0c)*16 + ci0 + 8];
        cur[3] = *(const float2*)&row[0][(p1c)*16 + ci0 + 8];

        #pragma unroll
        for (int kc = 0; kc < 9; kc++) {
            if (kc < 8) {
                const int ky = (kc+1) / 3, kx = (kc+1) % 3;
                const float* rp = row[ky];
                nxt[0] = *(const float2*)&rp[(p0c + kx)*16 + ci0];
                nxt[1] = *(const float2*)&rp[(p1c + kx)*16 + ci0];
                nxt[2] = *(const float2*)&rp[(p0c + kx)*16 + ci0 + 8];
                nxt[3] = *(const float2*)&rp[(p1c + kx)*16 + ci0 + 8];
            }
            uint32_t ah[4], al[4];
            hilo2(cur[0], ah[0], al[0]);
            hilo2(cur[1], ah[1], al[1]);
            hilo2(cur[2], ah[2], al[2]);
            hilo2(cur[3], ah[3], al[3]);

            #pragma unroll
            for (int cg = 0; cg < 4; cg++) {
                uint4 f = sWf[(kc*4 + cg)*32 + lane];
                mma16816(acc[cg], ah, f.x, f.y);
                mma16816(acc[cg], ah, f.z, f.w);
                mma16816(acc[cg], al, f.x, f.y);
            }
            #pragma unroll
            for (int j = 0; j < 4; j++) cur[j] = nxt[j];
        }

        const size_t rowbase = (size_t)oy * H3;
        #pragma unroll
        for (int px = 0; px < 2; px++) {
            const int pp = px ? p1 : p0;
            float o[6];
            #pragma unroll
            for (int k = 0; k < 6; k++) o[k] = 0.f;
            #pragma unroll
            for (int cg = 0; cg < 4; cg++) {
                #pragma unroll
                for (int j = 0; j < 2; j++) {
                    const int ch = cg*8 + ci0 + j;
                    float t = acc[cg][px*2 + j] + sBA[ch];
                    t = (t >= 0.f) ? t : sBA[32+ch]*t;
                    o[0] = fmaf(t, sHW[0][ch], o[0]);
                    o[1] = fmaf(t, sHW[1][ch], o[1]);
                    o[2] = fmaf(t, sHW[2][ch], o[2]);
                    o[3] = fmaf(t, sHW[3][ch], o[3]);
                    o[4] = fmaf(t, sHW[4][ch], o[4]);
                    o[5] = fmaf(t, sHW[5][ch], o[5]);
                }
            }
            #pragma unroll
            for (int off = 1; off <= 2; off <<= 1)
                #pragma unroll
                for (int k = 0; k < 6; k++)
                    o[k] += __shfl_xor_sync(0xffffffffu, o[k], off);

            float l0 = o[0] + sHB[0], l1 = o[1] + sHB[1];
            float m  = fmaxf(l0, l1);
            float e0 = expf(l0 - m), e1 = expf(l1 - m);
            float inv = 1.f / (e0 + e1);
            float pr0 = e0 * inv, pr1 = e1 * inv;

            if (pp < H3) {
                const size_t p = rowbase + pp;
                regp[(size_t)(b*4+q)*P3 + p] = o[2+q] + sHB[2+q];
                if (q == 0) probp[(size_t)(b*2+0)*P3 + p] = pr0;
                if (q == 1) probp[(size_t)(b*2+1)*P3 + p] = pr1;
            }
        }
    }
}

// ---------------------------------------------------------------------------
extern "C" void kernel_launch(void* const* d_in, const int* in_sizes, int n_in,
                              void* d_out, int out_size)
{
    const float* x    = (const float*)d_in[0];
    const float* c1w  = (const float*)d_in[1];
    const float* c1b  = (const float*)d_in[2];
    const float* p1a  = (const float*)d_in[3];
    const float* c2w  = (const float*)d_in[4];
    const float* c2b  = (const float*)d_in[5];
    const float* p2a  = (const float*)d_in[6];
    const float* c3w  = (const float*)d_in[7];
    const float* c3b  = (const float*)d_in[8];
    const float* p3a  = (const float*)d_in[9];
    const float* c41w = (const float*)d_in[10];
    const float* c41b = (const float*)d_in[11];
    const float* c42w = (const float*)d_in[12];
    const float* c42b = (const float*)d_in[13];
    float* out = (float*)d_out;

    {
        dim3 blk(32, 4);
        dim3 grd((HP + 31) / 32, (HP + 3) / 4, B);
        k_conv1_pool<<<grd, blk>>>(x, c1w, c1b, p1a);
    }
    {
        dim3 grd((H2 + 127) / 128, (H2 + 3) / 4, B);
        k_conv2_mma<<<grd, 256>>>(c2w, c2b, p2a);
    }
    {
        dim3 grd((H3 + 127) / 128, (H3 + 3) / 4, B);
        k_conv3_heads<<<grd, 256>>>(c3w, c3b, p3a, c41w, c41b, c42w, c42b, out);
    }
}

// round 8
// speedup vs baseline: 3.5834x; 1.1239x over previous
#include <cuda_runtime.h>
#include <cuda_bf16.h>
#include <math.h>
#include <stdint.h>

// ---------------------------------------------------------------------------
// MTCNN P-Net forward.
// Producer kernels store activations pre-split into bf16 hi/lo interleaved
// pairs ([hi(2k,2k+1), lo(2k,2k+1)] uint32s, 64B/pixel). Consumers load MMA
// fragments directly (LDG.64 -> {ah,al}) with zero in-loop conversions.
// conv1: scalar FFMA2, div-free smem staging
// conv2: mma.sync bf16 hi/lo (K=144,N=16), uint4 B-frags
// conv3: mma.sync bf16 hi/lo (K=144,N=32) + fused heads/softmax
// ---------------------------------------------------------------------------

#define B       16
#define H0      720
#define HP      359
#define H2      357
#define H3      355
#define P3      (H3*H3)

typedef unsigned long long ull;

__device__ __forceinline__ ull pack2(float a, float b) {
    ull r;
    asm("mov.b64 %0, {%1,%2};" : "=l"(r)
        : "r"(__float_as_uint(a)), "r"(__float_as_uint(b)));
    return r;
}
__device__ __forceinline__ void unpack2(ull v, float& a, float& b) {
    unsigned lo, hi;
    asm("mov.b64 {%0,%1}, %2;" : "=r"(lo), "=r"(hi) : "l"(v));
    a = __uint_as_float(lo); b = __uint_as_float(hi);
}
__device__ __forceinline__ void fma2(ull& d, ull a, ull b) {
    asm("fma.rn.f32x2 %0, %1, %2, %3;" : "=l"(d) : "l"(a), "l"(b), "l"(d));
}

// activations: per pixel 16 uint32 = 8 pairs x {hi, lo} bf16x2
__device__ uint32_t g_p1hl[(size_t)B*HP*HP*16];
__device__ uint32_t g_c2hl[(size_t)B*H2*H2*16];

// ======================= mma.sync helpers ==================================
__device__ __forceinline__ void hilo2(float2 v, uint32_t& hi, uint32_t& lo) {
    __nv_bfloat162 h = __floats2bfloat162_rn(v.x, v.y);
    float rx = v.x - __bfloat162float(h.x);
    float ry = v.y - __bfloat162float(h.y);
    __nv_bfloat162 l = __floats2bfloat162_rn(rx, ry);
    hi = *(uint32_t*)&h; lo = *(uint32_t*)&l;
}
__device__ __forceinline__ void mma16816(float* d, const uint32_t* a,
                                         uint32_t b0, uint32_t b1) {
    asm volatile(
        "mma.sync.aligned.m16n8k16.row.col.f32.bf16.bf16.f32 "
        "{%0,%1,%2,%3}, {%4,%5,%6,%7}, {%8,%9}, {%0,%1,%2,%3};"
        : "+f"(d[0]), "+f"(d[1]), "+f"(d[2]), "+f"(d[3])
        : "r"(a[0]), "r"(a[1]), "r"(a[2]), "r"(a[3]), "r"(b0), "r"(b1));
}
__device__ __forceinline__ void whl(float wv, __nv_bfloat16& h, __nv_bfloat16& l) {
    h = __float2bfloat16(wv);
    l = __float2bfloat16(wv - __bfloat162float(h));
}

// ---------------------------------------------------------------------------
// Kernel 1: normalize + conv1(3x3,3->10) + PReLU + maxpool2 -> hl pairs
// ---------------------------------------------------------------------------
__device__ __forceinline__ void conv1_taps(
    ull (&acc)[5][4], const ull sWp[5][3][9], int ci, int ky,
    const ull* top, const ull* bot)
{
    #pragma unroll
    for (int kx = 0; kx < 3; kx++) {
        #pragma unroll
        for (int cp = 0; cp < 5; cp++) {
            ull wp = sWp[cp][ci][ky*3+kx];
            fma2(acc[cp][0], wp, top[kx]);
            fma2(acc[cp][1], wp, top[kx+1]);
            fma2(acc[cp][2], wp, bot[kx]);
            fma2(acc[cp][3], wp, bot[kx+1]);
        }
    }
}

__global__ __launch_bounds__(128, 8) void k_conv1_pool(
    const float* __restrict__ x, const float* __restrict__ w1,
    const float* __restrict__ b1, const float* __restrict__ a1)
{
    __shared__ ull   sWp[5][3][9];
    __shared__ ull   sIn[3][10][66];   // pre-packed (v,v)
    __shared__ float sB[10], sA[10];

    const int b   = blockIdx.z;
    const int px0 = blockIdx.x * 32;
    const int py0 = blockIdx.y * 4;
    const int tid = threadIdx.y * 32 + threadIdx.x;

    for (int i = tid; i < 135; i += 128) {
        int cp = i / 27, ci = (i % 27) / 9, k = i % 9;
        sWp[cp][ci][k] = pack2(w1[(2*cp)*27 + ci*9 + k], w1[(2*cp+1)*27 + ci*9 + k]);
    }
    if (tid < 10) { sB[tid] = b1[tid]; sA[tid] = a1[tid]; }

    const int row0 = 2*py0, col0 = 2*px0;

    // div-free staging: 64 cols x 2 rows mapping (shift/AND only)
    {
        const int c  = tid & 63;
        const int r2 = tid >> 6;
        const int gc = col0 + c;
        const bool cok = (gc < H0);
        #pragma unroll
        for (int ci = 0; ci < 3; ci++) {
            #pragma unroll
            for (int r = 0; r < 5; r++) {
                const int rr = 2*r + r2;
                const int gr = row0 + rr;
                float v = 0.f;
                if (cok && gr < H0)
                    v = (x[((b*3+ci)*H0 + gr)*H0 + gc] - 127.5f) * 0.0078125f;
                sIn[ci][rr][c] = pack2(v, v);
            }
        }
        // halo cols 64,65: 3 ci * 10 rows * 2 cols = 60 elems
        if (tid < 60) {
            int ci = tid / 20, rem = tid % 20;
            int rr = rem >> 1, c2 = 64 + (rem & 1);
            int gr = row0 + rr, gc2 = col0 + c2;
            float v = 0.f;
            if (gr < H0 && gc2 < H0)
                v = (x[((b*3+ci)*H0 + gr)*H0 + gc2] - 127.5f) * 0.0078125f;
            sIn[ci][rr][c2] = pack2(v, v);
        }
    }
    __syncthreads();

    const int px = px0 + threadIdx.x;
    const int py = py0 + threadIdx.y;
    if (px >= HP || py >= HP) return;

    ull acc[5][4];
    #pragma unroll
    for (int cp = 0; cp < 5; cp++) {
        ull bb = pack2(sB[2*cp], sB[2*cp+1]);
        acc[cp][0]=bb; acc[cp][1]=bb; acc[cp][2]=bb; acc[cp][3]=bb;
    }

    const int lr = 2*threadIdx.y, lc = 2*threadIdx.x;
    #pragma unroll
    for (int ci = 0; ci < 3; ci++) {
        ull qa[4], qb[4];
        #pragma unroll
        for (int j = 0; j < 4; j++) qa[j] = sIn[ci][lr  ][lc+j];
        #pragma unroll
        for (int j = 0; j < 4; j++) qb[j] = sIn[ci][lr+1][lc+j];
        conv1_taps(acc, sWp, ci, 0, qa, qb);
        #pragma unroll
        for (int j = 0; j < 4; j++) qa[j] = sIn[ci][lr+2][lc+j];
        conv1_taps(acc, sWp, ci, 1, qb, qa);
        #pragma unroll
        for (int j = 0; j < 4; j++) qb[j] = sIn[ci][lr+3][lc+j];
        conv1_taps(acc, sWp, ci, 2, qa, qb);
    }

    float v[16];
    #pragma unroll
    for (int cp = 0; cp < 5; cp++) {
        float a0 = sA[2*cp], a1v = sA[2*cp+1];
        float m0 = -INFINITY, m1 = -INFINITY;
        #pragma unroll
        for (int k = 0; k < 4; k++) {
            float v0, v1; unpack2(acc[cp][k], v0, v1);
            v0 = (v0 >= 0.f) ? v0 : a0*v0;
            v1 = (v1 >= 0.f) ? v1 : a1v*v1;
            m0 = fmaxf(m0, v0); m1 = fmaxf(m1, v1);
        }
        v[2*cp] = m0; v[2*cp+1] = m1;
    }
    #pragma unroll
    for (int c = 10; c < 16; c++) v[c] = 0.f;

    // split once into interleaved {hi, lo} pairs
    uint32_t hl[16];
    #pragma unroll
    for (int qd = 0; qd < 8; qd++)
        hilo2(make_float2(v[2*qd], v[2*qd+1]), hl[2*qd], hl[2*qd+1]);

    uint4* dst = (uint4*)&g_p1hl[((size_t)(b*HP + py)*HP + px)*16];
    #pragma unroll
    for (int qd = 0; qd < 4; qd++)
        dst[qd] = make_uint4(hl[qd*4], hl[qd*4+1], hl[qd*4+2], hl[qd*4+3]);
}

// ---------------------------------------------------------------------------
// Kernel 2: conv2 via mma.sync, hl-pair A loads. 16px x 16co, K=144.
// ---------------------------------------------------------------------------
__global__ __launch_bounds__(256) void k_conv2_mma(
    const float* __restrict__ w, const float* __restrict__ bias,
    const float* __restrict__ alpha)
{
    __shared__ uint4 sWf[9*2*32];    // [kc][cg][lane] = (bh0,bh1,bl0,bl1)
    __shared__ float sBA[32];

    const int b    = blockIdx.z;
    const int ox0  = blockIdx.x * 128;
    const int oy0  = blockIdx.y * 4;
    const int tid  = threadIdx.x;
    const int wid  = tid >> 5;
    const int lane = tid & 31;

    for (int f = tid; f < 9*2*32; f += 256) {
        int kc = f >> 6, cg = (f >> 5) & 1, ln = f & 31;
        int g = ln >> 2, ci0 = (ln & 3) * 2;
        int co = cg*8 + g;
        int ky = kc / 3, kx = kc % 3;
        __nv_bfloat16 h0,l0,h1,l1,h2,l2,h3,l3;
        float w0 = (ci0   < 10) ? w[((co*10 + ci0  )*3 + ky)*3 + kx] : 0.f;
        float w1v= (ci0+1 < 10) ? w[((co*10 + ci0+1)*3 + ky)*3 + kx] : 0.f;
        float w2 = (ci0+8 < 10) ? w[((co*10 + ci0+8)*3 + ky)*3 + kx] : 0.f;
        float w3 = (ci0+9 < 10) ? w[((co*10 + ci0+9)*3 + ky)*3 + kx] : 0.f;
        whl(w0,h0,l0); whl(w1v,h1,l1); whl(w2,h2,l2); whl(w3,h3,l3);
        __nv_bfloat162 bh0 = {h0,h1}, bh1 = {h2,h3}, bl0 = {l0,l1}, bl1 = {l2,l3};
        sWf[f] = make_uint4(*(uint32_t*)&bh0, *(uint32_t*)&bh1,
                            *(uint32_t*)&bl0, *(uint32_t*)&bl1);
    }
    if (tid < 16) { sBA[tid] = bias[tid]; sBA[16+tid] = alpha[tid]; }
    __syncthreads();

    const int g   = lane >> 2;
    const int ci0 = (lane & 3) * 2;

    const int p0  = ox0 + wid * 16 + g;
    const int p1  = p0 + 8;
    const int p0c = min(p0, H2 - 1);
    const int p1c = min(p1, H2 - 1);

    for (int r = 0; r < 4; r++) {
        const int oy = oy0 + r;
        if (oy >= H2) break;

        const uint32_t* row[3];
        #pragma unroll
        for (int ky = 0; ky < 3; ky++)
            row[ky] = &g_p1hl[(size_t)(b*HP + oy + ky) * HP * 16];

        float acc[2][4];
        #pragma unroll
        for (int cg = 0; cg < 2; cg++)
            #pragma unroll
            for (int j = 0; j < 4; j++) acc[cg][j] = 0.f;

        uint2 cur[4], nxt[4];
        cur[0] = *(const uint2*)&row[0][(p0c)*16 + ci0];
        cur[1] = *(const uint2*)&row[0][(p1c)*16 + ci0];
        cur[2] = *(const uint2*)&row[0][(p0c)*16 + ci0 + 8];
        cur[3] = *(const uint2*)&row[0][(p1c)*16 + ci0 + 8];

        #pragma unroll
        for (int kc = 0; kc < 9; kc++) {
            if (kc < 8) {
                const int ky = (kc+1) / 3, kx = (kc+1) % 3;
                const uint32_t* rp = row[ky];
                nxt[0] = *(const uint2*)&rp[(p0c + kx)*16 + ci0];
                nxt[1] = *(const uint2*)&rp[(p1c + kx)*16 + ci0];
                nxt[2] = *(const uint2*)&rp[(p0c + kx)*16 + ci0 + 8];
                nxt[3] = *(const uint2*)&rp[(p1c + kx)*16 + ci0 + 8];
            }
            uint32_t ah[4] = {cur[0].x, cur[1].x, cur[2].x, cur[3].x};
            uint32_t al[4] = {cur[0].y, cur[1].y, cur[2].y, cur[3].y};

            #pragma unroll
            for (int cg = 0; cg < 2; cg++) {
                uint4 f = sWf[(kc*2 + cg)*32 + lane];
                mma16816(acc[cg], ah, f.x, f.y);
                mma16816(acc[cg], ah, f.z, f.w);
                mma16816(acc[cg], al, f.x, f.y);
            }
            #pragma unroll
            for (int j = 0; j < 4; j++) cur[j] = nxt[j];
        }

        const size_t rowbase = (size_t)(b*H2 + oy) * H2;
        #pragma unroll
        for (int cg = 0; cg < 2; cg++) {
            const int co = cg*8 + ci0;
            const float b0 = sBA[co], b1 = sBA[co+1];
            const float a0 = sBA[16+co], a1 = sBA[16+co+1];
            float t0 = acc[cg][0] + b0, t1 = acc[cg][1] + b1;
            float t2 = acc[cg][2] + b0, t3 = acc[cg][3] + b1;
            float2 o01, o23;
            o01.x = (t0 >= 0.f) ? t0 : a0*t0;
            o01.y = (t1 >= 0.f) ? t1 : a1*t1;
            o23.x = (t2 >= 0.f) ? t2 : a0*t2;
            o23.y = (t3 >= 0.f) ? t3 : a1*t3;
            uint2 s0, s1;
            hilo2(o01, s0.x, s0.y);
            hilo2(o23, s1.x, s1.y);
            if (p0 < H2) *(uint2*)&g_c2hl[(rowbase + p0)*16 + co] = s0;
            if (p1 < H2) *(uint2*)&g_c2hl[(rowbase + p1)*16 + co] = s1;
        }
    }
}

// ---------------------------------------------------------------------------
// Kernel 3: conv3 (16px x 32co per warp) + fused heads, hl-pair A loads.
// ---------------------------------------------------------------------------
__global__ __launch_bounds__(256) void k_conv3_heads(
    const float* __restrict__ w, const float* __restrict__ bias,
    const float* __restrict__ alpha,
    const float* __restrict__ w41, const float* __restrict__ b41,
    const float* __restrict__ w42, const float* __restrict__ b42,
    float* __restrict__ out)
{
    __shared__ uint4 sWf[9*4*32];    // [kc][cg][lane]
    __shared__ float sBA[64];
    __shared__ float sHW[6][32];
    __shared__ float sHB[6];

    const int b    = blockIdx.z;
    const int ox0  = blockIdx.x * 128;
    const int oy0  = blockIdx.y * 4;
    const int tid  = threadIdx.x;
    const int wid  = tid >> 5;
    const int lane = tid & 31;

    for (int f = tid; f < 9*4*32; f += 256) {
        int kc = f >> 7, cg = (f >> 5) & 3, ln = f & 31;
        int g = ln >> 2, ci0 = (ln & 3) * 2;
        int co = cg*8 + g;
        int ky = kc / 3, kx = kc % 3;
        __nv_bfloat16 h0,l0,h1,l1,h2,l2,h3,l3;
        whl(w[((co*16 + ci0  )*3 + ky)*3 + kx], h0, l0);
        whl(w[((co*16 + ci0+1)*3 + ky)*3 + kx], h1, l1);
        whl(w[((co*16 + ci0+8)*3 + ky)*3 + kx], h2, l2);
        whl(w[((co*16 + ci0+9)*3 + ky)*3 + kx], h3, l3);
        __nv_bfloat162 bh0 = {h0,h1}, bh1 = {h2,h3}, bl0 = {l0,l1}, bl1 = {l2,l3};
        sWf[f] = make_uint4(*(uint32_t*)&bh0, *(uint32_t*)&bh1,
                            *(uint32_t*)&bl0, *(uint32_t*)&bl1);
    }
    if (tid < 32) { sBA[tid] = bias[tid]; sBA[32+tid] = alpha[tid]; }
    if (tid < 64)  sHW[tid/32][tid%32] = w41[tid];
    if (tid >= 64 && tid < 192) sHW[2 + (tid-64)/32][(tid-64)%32] = w42[tid-64];
    if (tid < 2) sHB[tid] = b41[tid];
    if (tid >= 2 && tid < 6) sHB[tid] = b42[tid-2];
    __syncthreads();

    const int g   = lane >> 2;
    const int ci0 = (lane & 3) * 2;
    const int q   = lane & 3;

    const int p0  = ox0 + wid * 16 + g;
    const int p1  = p0 + 8;
    const int p0c = min(p0, H3 - 1);
    const int p1c = min(p1, H3 - 1);

    float* regp  = out;
    float* probp = out + (size_t)B * 4 * P3;

    for (int r = 0; r < 4; r++) {
        const int oy = oy0 + r;
        if (oy >= H3) break;

        const uint32_t* row[3];
        #pragma unroll
        for (int ky = 0; ky < 3; ky++)
            row[ky] = &g_c2hl[(size_t)(b*H2 + oy + ky) * H2 * 16];

        float acc[4][4];
        #pragma unroll
        for (int cg = 0; cg < 4; cg++)
            #pragma unroll
            for (int j = 0; j < 4; j++) acc[cg][j] = 0.f;

        uint2 cur[4], nxt[4];
        cur[0] = *(const uint2*)&row[0][(p0c)*16 + ci0];
        cur[1] = *(const uint2*)&row[0][(p1c)*16 + ci0];
        cur[2] = *(const uint2*)&row[0][(p0c)*16 + ci0 + 8];
        cur[3] = *(const uint2*)&row[0][(p1c)*16 + ci0 + 8];

        #pragma unroll
        for (int kc = 0; kc < 9; kc++) {
            if (kc < 8) {
                const int ky = (kc+1) / 3, kx = (kc+1) % 3;
                const uint32_t* rp = row[ky];
                nxt[0] = *(const uint2*)&rp[(p0c + kx)*16 + ci0];
                nxt[1] = *(const uint2*)&rp[(p1c + kx)*16 + ci0];
                nxt[2] = *(const uint2*)&rp[(p0c + kx)*16 + ci0 + 8];
                nxt[3] = *(const uint2*)&rp[(p1c + kx)*16 + ci0 + 8];
            }
            uint32_t ah[4] = {cur[0].x, cur[1].x, cur[2].x, cur[3].x};
            uint32_t al[4] = {cur[0].y, cur[1].y, cur[2].y, cur[3].y};

            #pragma unroll
            for (int cg = 0; cg < 4; cg++) {
                uint4 f = sWf[(kc*4 + cg)*32 + lane];
                mma16816(acc[cg], ah, f.x, f.y);
                mma16816(acc[cg], ah, f.z, f.w);
                mma16816(acc[cg], al, f.x, f.y);
            }
            #pragma unroll
            for (int j = 0; j < 4; j++) cur[j] = nxt[j];
        }

        const size_t rowbase = (size_t)oy * H3;
        #pragma unroll
        for (int px = 0; px < 2; px++) {
            const int pp = px ? p1 : p0;
            float o[6];
            #pragma unroll
            for (int k = 0; k < 6; k++) o[k] = 0.f;
            #pragma unroll
            for (int cg = 0; cg < 4; cg++) {
                #pragma unroll
                for (int j = 0; j < 2; j++) {
                    const int ch = cg*8 + ci0 + j;
                    float t = acc[cg][px*2 + j] + sBA[ch];
                    t = (t >= 0.f) ? t : sBA[32+ch]*t;
                    o[0] = fmaf(t, sHW[0][ch], o[0]);
                    o[1] = fmaf(t, sHW[1][ch], o[1]);
                    o[2] = fmaf(t, sHW[2][ch], o[2]);
                    o[3] = fmaf(t, sHW[3][ch], o[3]);
                    o[4] = fmaf(t, sHW[4][ch], o[4]);
                    o[5] = fmaf(t, sHW[5][ch], o[5]);
                }
            }
            #pragma unroll
            for (int off = 1; off <= 2; off <<= 1)
                #pragma unroll
                for (int k = 0; k < 6; k++)
                    o[k] += __shfl_xor_sync(0xffffffffu, o[k], off);

            float l0 = o[0] + sHB[0], l1 = o[1] + sHB[1];
            float m  = fmaxf(l0, l1);
            float e0 = expf(l0 - m), e1 = expf(l1 - m);
            float inv = 1.f / (e0 + e1);
            float pr0 = e0 * inv, pr1 = e1 * inv;

            if (pp < H3) {
                const size_t p = rowbase + pp;
                regp[(size_t)(b*4+q)*P3 + p] = o[2+q] + sHB[2+q];
                if (q == 0) probp[(size_t)(b*2+0)*P3 + p] = pr0;
                if (q == 1) probp[(size_t)(b*2+1)*P3 + p] = pr1;
            }
        }
    }
}

// ---------------------------------------------------------------------------
extern "C" void kernel_launch(void* const* d_in, const int* in_sizes, int n_in,
                              void* d_out, int out_size)
{
    const float* x    = (const float*)d_in[0];
    const float* c1w  = (const float*)d_in[1];
    const float* c1b  = (const float*)d_in[2];
    const float* p1a  = (const float*)d_in[3];
    const float* c2w  = (const float*)d_in[4];
    const float* c2b  = (const float*)d_in[5];
    const float* p2a  = (const float*)d_in[6];
    const float* c3w  = (const float*)d_in[7];
    const float* c3b  = (const float*)d_in[8];
    const float* p3a  = (const float*)d_in[9];
    const float* c41w = (const float*)d_in[10];
    const float* c41b = (const float*)d_in[11];
    const float* c42w = (const float*)d_in[12];
    const float* c42b = (const float*)d_in[13];
    float* out = (float*)d_out;

    {
        dim3 blk(32, 4);
        dim3 grd((HP + 31) / 32, (HP + 3) / 4, B);
        k_conv1_pool<<<grd, blk>>>(x, c1w, c1b, p1a);
    }
    {
        dim3 grd((H2 + 127) / 128, (H2 + 3) / 4, B);
        k_conv2_mma<<<grd, 256>>>(c2w, c2b, p2a);
    }
    {
        dim3 grd((H3 + 127) / 128, (H3 + 3) / 4, B);
        k_conv3_heads<<<grd, 256>>>(c3w, c3b, p3a, c41w, c41b, c42w, c42b, out);
    }
}

// round 10
// speedup vs baseline: 3.5977x; 1.0040x over previous
#include <cuda_runtime.h>
#include <cuda_bf16.h>
#include <math.h>
#include <stdint.h>

// ---------------------------------------------------------------------------
// MTCNN P-Net forward.
// Activations stored pre-split into bf16 hi/lo interleaved pairs (64B/pixel).
// conv1: scalar FFMA2, div-free staging.
// conv2/conv3: mma.sync bf16 hi/lo implicit GEMM, K restructured into 3
// ky-batches of 12 independent loads, double-buffered (MLP 12 vs 4).
// conv3 fuses 1x1 heads + softmax.
// ---------------------------------------------------------------------------

#define B       16
#define H0      720
#define HP      359
#define H2      357
#define H3      355
#define P3      (H3*H3)

typedef unsigned long long ull;

__device__ __forceinline__ ull pack2(float a, float b) {
    ull r;
    asm("mov.b64 %0, {%1,%2};" : "=l"(r)
        : "r"(__float_as_uint(a)), "r"(__float_as_uint(b)));
    return r;
}
__device__ __forceinline__ void unpack2(ull v, float& a, float& b) {
    unsigned lo, hi;
    asm("mov.b64 {%0,%1}, %2;" : "=r"(lo), "=r"(hi) : "l"(v));
    a = __uint_as_float(lo); b = __uint_as_float(hi);
}
__device__ __forceinline__ void fma2(ull& d, ull a, ull b) {
    asm("fma.rn.f32x2 %0, %1, %2, %3;" : "=l"(d) : "l"(a), "l"(b), "l"(d));
}

// activations: per pixel 16 uint32 = 8 pairs x {hi, lo} bf16x2
__device__ uint32_t g_p1hl[(size_t)B*HP*HP*16];
__device__ uint32_t g_c2hl[(size_t)B*H2*H2*16];

// ======================= mma.sync helpers ==================================
__device__ __forceinline__ void hilo2(float2 v, uint32_t& hi, uint32_t& lo) {
    __nv_bfloat162 h = __floats2bfloat162_rn(v.x, v.y);
    float rx = v.x - __bfloat162float(h.x);
    float ry = v.y - __bfloat162float(h.y);
    __nv_bfloat162 l = __floats2bfloat162_rn(rx, ry);
    hi = *(uint32_t*)&h; lo = *(uint32_t*)&l;
}
__device__ __forceinline__ void mma16816(float* d, const uint32_t* a,
                                         uint32_t b0, uint32_t b1) {
    asm volatile(
        "mma.sync.aligned.m16n8k16.row.col.f32.bf16.bf16.f32 "
        "{%0,%1,%2,%3}, {%4,%5,%6,%7}, {%8,%9}, {%0,%1,%2,%3};"
        : "+f"(d[0]), "+f"(d[1]), "+f"(d[2]), "+f"(d[3])
        : "r"(a[0]), "r"(a[1]), "r"(a[2]), "r"(a[3]), "r"(b0), "r"(b1));
}
__device__ __forceinline__ void whl(float wv, __nv_bfloat16& h, __nv_bfloat16& l) {
    h = __float2bfloat16(wv);
    l = __float2bfloat16(wv - __bfloat162float(h));
}

// load one ky-batch: 12 uint2 (kx=0..2  x  {p0,p1} x {ci0, ci0+8})
__device__ __forceinline__ void load_ky(uint2 (&L)[12], const uint32_t* rp,
                                        int p0c, int p1c, int ci0) {
    #pragma unroll
    for (int kx = 0; kx < 3; kx++) {
        L[kx*4+0] = *(const uint2*)&rp[(p0c + kx)*16 + ci0];
        L[kx*4+1] = *(const uint2*)&rp[(p1c + kx)*16 + ci0];
        L[kx*4+2] = *(const uint2*)&rp[(p0c + kx)*16 + ci0 + 8];
        L[kx*4+3] = *(const uint2*)&rp[(p1c + kx)*16 + ci0 + 8];
    }
}

// ---------------------------------------------------------------------------
// Kernel 1: normalize + conv1(3x3,3->10) + PReLU + maxpool2 -> hl pairs
// ---------------------------------------------------------------------------
__device__ __forceinline__ void conv1_taps(
    ull (&acc)[5][4], const ull sWp[5][3][9], int ci, int ky,
    const ull* top, const ull* bot)
{
    #pragma unroll
    for (int kx = 0; kx < 3; kx++) {
        #pragma unroll
        for (int cp = 0; cp < 5; cp++) {
            ull wp = sWp[cp][ci][ky*3+kx];
            fma2(acc[cp][0], wp, top[kx]);
            fma2(acc[cp][1], wp, top[kx+1]);
            fma2(acc[cp][2], wp, bot[kx]);
            fma2(acc[cp][3], wp, bot[kx+1]);
        }
    }
}

__global__ __launch_bounds__(128, 8) void k_conv1_pool(
    const float* __restrict__ x, const float* __restrict__ w1,
    const float* __restrict__ b1, const float* __restrict__ a1)
{
    __shared__ ull   sWp[5][3][9];
    __shared__ ull   sIn[3][10][66];
    __shared__ float sB[10], sA[10];

    const int b   = blockIdx.z;
    const int px0 = blockIdx.x * 32;
    const int py0 = blockIdx.y * 4;
    const int tid = threadIdx.y * 32 + threadIdx.x;

    for (int i = tid; i < 135; i += 128) {
        int cp = i / 27, ci = (i % 27) / 9, k = i % 9;
        sWp[cp][ci][k] = pack2(w1[(2*cp)*27 + ci*9 + k], w1[(2*cp+1)*27 + ci*9 + k]);
    }
    if (tid < 10) { sB[tid] = b1[tid]; sA[tid] = a1[tid]; }

    const int row0 = 2*py0, col0 = 2*px0;
    {
        const int c  = tid & 63;
        const int r2 = tid >> 6;
        const int gc = col0 + c;
        const bool cok = (gc < H0);
        #pragma unroll
        for (int ci = 0; ci < 3; ci++) {
            #pragma unroll
            for (int r = 0; r < 5; r++) {
                const int rr = 2*r + r2;
                const int gr = row0 + rr;
                float v = 0.f;
                if (cok && gr < H0)
                    v = (x[((b*3+ci)*H0 + gr)*H0 + gc] - 127.5f) * 0.0078125f;
                sIn[ci][rr][c] = pack2(v, v);
            }
        }
        if (tid < 60) {
            int ci = tid / 20, rem = tid % 20;
            int rr = rem >> 1, c2 = 64 + (rem & 1);
            int gr = row0 + rr, gc2 = col0 + c2;
            float v = 0.f;
            if (gr < H0 && gc2 < H0)
                v = (x[((b*3+ci)*H0 + gr)*H0 + gc2] - 127.5f) * 0.0078125f;
            sIn[ci][rr][c2] = pack2(v, v);
        }
    }
    __syncthreads();

    const int px = px0 + threadIdx.x;
    const int py = py0 + threadIdx.y;
    if (px >= HP || py >= HP) return;

    ull acc[5][4];
    #pragma unroll
    for (int cp = 0; cp < 5; cp++) {
        ull bb = pack2(sB[2*cp], sB[2*cp+1]);
        acc[cp][0]=bb; acc[cp][1]=bb; acc[cp][2]=bb; acc[cp][3]=bb;
    }

    const int lr = 2*threadIdx.y, lc = 2*threadIdx.x;
    #pragma unroll
    for (int ci = 0; ci < 3; ci++) {
        ull qa[4], qb[4];
        #pragma unroll
        for (int j = 0; j < 4; j++) qa[j] = sIn[ci][lr  ][lc+j];
        #pragma unroll
        for (int j = 0; j < 4; j++) qb[j] = sIn[ci][lr+1][lc+j];
        conv1_taps(acc, sWp, ci, 0, qa, qb);
        #pragma unroll
        for (int j = 0; j < 4; j++) qa[j] = sIn[ci][lr+2][lc+j];
        conv1_taps(acc, sWp, ci, 1, qb, qa);
        #pragma unroll
        for (int j = 0; j < 4; j++) qb[j] = sIn[ci][lr+3][lc+j];
        conv1_taps(acc, sWp, ci, 2, qa, qb);
    }

    float v[16];
    #pragma unroll
    for (int cp = 0; cp < 5; cp++) {
        float a0 = sA[2*cp], a1v = sA[2*cp+1];
        float m0 = -INFINITY, m1 = -INFINITY;
        #pragma unroll
        for (int k = 0; k < 4; k++) {
            float v0, v1; unpack2(acc[cp][k], v0, v1);
            v0 = (v0 >= 0.f) ? v0 : a0*v0;
            v1 = (v1 >= 0.f) ? v1 : a1v*v1;
            m0 = fmaxf(m0, v0); m1 = fmaxf(m1, v1);
        }
        v[2*cp] = m0; v[2*cp+1] = m1;
    }
    #pragma unroll
    for (int c = 10; c < 16; c++) v[c] = 0.f;

    uint32_t hl[16];
    #pragma unroll
    for (int qd = 0; qd < 8; qd++)
        hilo2(make_float2(v[2*qd], v[2*qd+1]), hl[2*qd], hl[2*qd+1]);

    uint4* dst = (uint4*)&g_p1hl[((size_t)(b*HP + py)*HP + px)*16];
    #pragma unroll
    for (int qd = 0; qd < 4; qd++)
        dst[qd] = make_uint4(hl[qd*4], hl[qd*4+1], hl[qd*4+2], hl[qd*4+3]);
}

// ---------------------------------------------------------------------------
// Kernel 2: conv2 via mma.sync, ky-batched loads. 16px x 16co, K=144.
// ---------------------------------------------------------------------------
__device__ __forceinline__ void mma_ky2(float (&acc)[2][4], const uint2 (&L)[12],
                                        const uint4* sWf, int kcb, int lane) {
    #pragma unroll
    for (int kx = 0; kx < 3; kx++) {
        uint32_t ah[4] = {L[kx*4+0].x, L[kx*4+1].x, L[kx*4+2].x, L[kx*4+3].x};
        uint32_t al[4] = {L[kx*4+0].y, L[kx*4+1].y, L[kx*4+2].y, L[kx*4+3].y};
        #pragma unroll
        for (int cg = 0; cg < 2; cg++) {
            uint4 f = sWf[((kcb+kx)*2 + cg)*32 + lane];
            mma16816(acc[cg], ah, f.x, f.y);
            mma16816(acc[cg], ah, f.z, f.w);
            mma16816(acc[cg], al, f.x, f.y);
        }
    }
}

__global__ __launch_bounds__(256) void k_conv2_mma(
    const float* __restrict__ w, const float* __restrict__ bias,
    const float* __restrict__ alpha)
{
    __shared__ uint4 sWf[9*2*32];
    __shared__ float sBA[32];

    const int b    = blockIdx.z;
    const int ox0  = blockIdx.x * 128;
    const int oy0  = blockIdx.y * 4;
    const int tid  = threadIdx.x;
    const int wid  = tid >> 5;
    const int lane = tid & 31;

    for (int f = tid; f < 9*2*32; f += 256) {
        int kc = f >> 6, cg = (f >> 5) & 1, ln = f & 31;
        int g = ln >> 2, ci0 = (ln & 3) * 2;
        int co = cg*8 + g;
        int ky = kc / 3, kx = kc % 3;
        __nv_bfloat16 h0,l0,h1,l1,h2,l2,h3,l3;
        float w0 = (ci0   < 10) ? w[((co*10 + ci0  )*3 + ky)*3 + kx] : 0.f;
        float w1v= (ci0+1 < 10) ? w[((co*10 + ci0+1)*3 + ky)*3 + kx] : 0.f;
        float w2 = (ci0+8 < 10) ? w[((co*10 + ci0+8)*3 + ky)*3 + kx] : 0.f;
        float w3 = (ci0+9 < 10) ? w[((co*10 + ci0+9)*3 + ky)*3 + kx] : 0.f;
        whl(w0,h0,l0); whl(w1v,h1,l1); whl(w2,h2,l2); whl(w3,h3,l3);
        __nv_bfloat162 bh0 = {h0,h1}, bh1 = {h2,h3}, bl0 = {l0,l1}, bl1 = {l2,l3};
        sWf[f] = make_uint4(*(uint32_t*)&bh0, *(uint32_t*)&bh1,
                            *(uint32_t*)&bl0, *(uint32_t*)&bl1);
    }
    if (tid < 16) { sBA[tid] = bias[tid]; sBA[16+tid] = alpha[tid]; }
    __syncthreads();

    const int g   = lane >> 2;
    const int ci0 = (lane & 3) * 2;

    const int p0  = ox0 + wid * 16 + g;
    const int p1  = p0 + 8;
    const int p0c = min(p0, H2 - 1);
    const int p1c = min(p1, H2 - 1);

    for (int r = 0; r < 4; r++) {
        const int oy = oy0 + r;
        if (oy >= H2) break;

        const uint32_t* row0 = &g_p1hl[(size_t)(b*HP + oy    ) * HP * 16];
        const uint32_t* row1 = &g_p1hl[(size_t)(b*HP + oy + 1) * HP * 16];
        const uint32_t* row2 = &g_p1hl[(size_t)(b*HP + oy + 2) * HP * 16];

        float acc[2][4];
        #pragma unroll
        for (int cg = 0; cg < 2; cg++)
            #pragma unroll
            for (int j = 0; j < 4; j++) acc[cg][j] = 0.f;

        uint2 A0[12], A1[12];
        load_ky(A0, row0, p0c, p1c, ci0);
        load_ky(A1, row1, p0c, p1c, ci0);
        mma_ky2(acc, A0, sWf, 0, lane);
        load_ky(A0, row2, p0c, p1c, ci0);
        mma_ky2(acc, A1, sWf, 3, lane);
        mma_ky2(acc, A0, sWf, 6, lane);

        const size_t rowbase = (size_t)(b*H2 + oy) * H2;
        #pragma unroll
        for (int cg = 0; cg < 2; cg++) {
            const int co = cg*8 + ci0;
            const float b0 = sBA[co], b1 = sBA[co+1];
            const float a0 = sBA[16+co], a1 = sBA[16+co+1];
            float t0 = acc[cg][0] + b0, t1 = acc[cg][1] + b1;
            float t2 = acc[cg][2] + b0, t3 = acc[cg][3] + b1;
            float2 o01, o23;
            o01.x = (t0 >= 0.f) ? t0 : a0*t0;
            o01.y = (t1 >= 0.f) ? t1 : a1*t1;
            o23.x = (t2 >= 0.f) ? t2 : a0*t2;
            o23.y = (t3 >= 0.f) ? t3 : a1*t3;
            uint2 s0, s1;
            hilo2(o01, s0.x, s0.y);
            hilo2(o23, s1.x, s1.y);
            if (p0 < H2) *(uint2*)&g_c2hl[(rowbase + p0)*16 + co] = s0;
            if (p1 < H2) *(uint2*)&g_c2hl[(rowbase + p1)*16 + co] = s1;
        }
    }
}

// ---------------------------------------------------------------------------
// Kernel 3: conv3 (16px x 32co per warp) + fused heads, ky-batched loads.
// ---------------------------------------------------------------------------
__device__ __forceinline__ void mma_ky4(float (&acc)[4][4], const uint2 (&L)[12],
                                        const uint4* sWf, int kcb, int lane) {
    #pragma unroll
    for (int kx = 0; kx < 3; kx++) {
        uint32_t ah[4] = {L[kx*4+0].x, L[kx*4+1].x, L[kx*4+2].x, L[kx*4+3].x};
        uint32_t al[4] = {L[kx*4+0].y, L[kx*4+1].y, L[kx*4+2].y, L[kx*4+3].y};
        #pragma unroll
        for (int cg = 0; cg < 4; cg++) {
            uint4 f = sWf[((kcb+kx)*4 + cg)*32 + lane];
            mma16816(acc[cg], ah, f.x, f.y);
            mma16816(acc[cg], ah, f.z, f.w);
            mma16816(acc[cg], al, f.x, f.y);
        }
    }
}

__global__ __launch_bounds__(256) void k_conv3_heads(
    const float* __restrict__ w, const float* __restrict__ bias,
    const float* __restrict__ alpha,
    const float* __restrict__ w41, const float* __restrict__ b41,
    const float* __restrict__ w42, const float* __restrict__ b42,
    float* __restrict__ out)
{
    __shared__ uint4 sWf[9*4*32];
    __shared__ float sBA[64];
    __shared__ float sHW[6][32];
    __shared__ float sHB[6];

    const int b    = blockIdx.z;
    const int ox0  = blockIdx.x * 128;
    const int oy0  = blockIdx.y * 4;
    const int tid  = threadIdx.x;
    const int wid  = tid >> 5;
    const int lane = tid & 31;

    for (int f = tid; f < 9*4*32; f += 256) {
        int kc = f >> 7, cg = (f >> 5) & 3, ln = f & 31;
        int g = ln >> 2, ci0 = (ln & 3) * 2;
        int co = cg*8 + g;
        int ky = kc / 3, kx = kc % 3;
        __nv_bfloat16 h0,l0,h1,l1,h2,l2,h3,l3;
        whl(w[((co*16 + ci0  )*3 + ky)*3 + kx], h0, l0);
        whl(w[((co*16 + ci0+1)*3 + ky)*3 + kx], h1, l1);
        whl(w[((co*16 + ci0+8)*3 + ky)*3 + kx], h2, l2);
        whl(w[((co*16 + ci0+9)*3 + ky)*3 + kx], h3, l3);
        __nv_bfloat162 bh0 = {h0,h1}, bh1 = {h2,h3}, bl0 = {l0,l1}, bl1 = {l2,l3};
        sWf[f] = make_uint4(*(uint32_t*)&bh0, *(uint32_t*)&bh1,
                            *(uint32_t*)&bl0, *(uint32_t*)&bl1);
    }
    if (tid < 32) { sBA[tid] = bias[tid]; sBA[32+tid] = alpha[tid]; }
    if (tid < 64)  sHW[tid/32][tid%32] = w41[tid];
    if (tid >= 64 && tid < 192) sHW[2 + (tid-64)/32][(tid-64)%32] = w42[tid-64];
    if (tid < 2) sHB[tid] = b41[tid];
    if (tid >= 2 && tid < 6) sHB[tid] = b42[tid-2];
    __syncthreads();

    const int g   = lane >> 2;
    const int ci0 = (lane & 3) * 2;
    const int q   = lane & 3;

    const int p0  = ox0 + wid * 16 + g;
    const int p1  = p0 + 8;
    const int p0c = min(p0, H3 - 1);
    const int p1c = min(p1, H3 - 1);

    float* regp  = out;
    float* probp = out + (size_t)B * 4 * P3;

    for (int r = 0; r < 4; r++) {
        const int oy = oy0 + r;
        if (oy >= H3) break;

        const uint32_t* row0 = &g_c2hl[(size_t)(b*H2 + oy    ) * H2 * 16];
        const uint32_t* row1 = &g_c2hl[(size_t)(b*H2 + oy + 1) * H2 * 16];
        const uint32_t* row2 = &g_c2hl[(size_t)(b*H2 + oy + 2) * H2 * 16];

        float acc[4][4];
        #pragma unroll
        for (int cg = 0; cg < 4; cg++)
            #pragma unroll
            for (int j = 0; j < 4; j++) acc[cg][j] = 0.f;

        uint2 A0[12], A1[12];
        load_ky(A0, row0, p0c, p1c, ci0);
        load_ky(A1, row1, p0c, p1c, ci0);
        mma_ky4(acc, A0, sWf, 0, lane);
        load_ky(A0, row2, p0c, p1c, ci0);
        mma_ky4(acc, A1, sWf, 3, lane);
        mma_ky4(acc, A0, sWf, 6, lane);

        const size_t rowbase = (size_t)oy * H3;
        #pragma unroll
        for (int px = 0; px < 2; px++) {
            const int pp = px ? p1 : p0;
            float o[6];
            #pragma unroll
            for (int k = 0; k < 6; k++) o[k] = 0.f;
            #pragma unroll
            for (int cg = 0; cg < 4; cg++) {
                #pragma unroll
                for (int j = 0; j < 2; j++) {
                    const int ch = cg*8 + ci0 + j;
                    float t = acc[cg][px*2 + j] + sBA[ch];
                    t = (t >= 0.f) ? t : sBA[32+ch]*t;
                    o[0] = fmaf(t, sHW[0][ch], o[0]);
                    o[1] = fmaf(t, sHW[1][ch], o[1]);
                    o[2] = fmaf(t, sHW[2][ch], o[2]);
                    o[3] = fmaf(t, sHW[3][ch], o[3]);
                    o[4] = fmaf(t, sHW[4][ch], o[4]);
                    o[5] = fmaf(t, sHW[5][ch], o[5]);
                }
            }
            #pragma unroll
            for (int off = 1; off <= 2; off <<= 1)
                #pragma unroll
                for (int k = 0; k < 6; k++)
                    o[k] += __shfl_xor_sync(0xffffffffu, o[k], off);

            float l0 = o[0] + sHB[0], l1 = o[1] + sHB[1];
            float m  = fmaxf(l0, l1);
            float e0 = expf(l0 - m), e1 = expf(l1 - m);
            float inv = 1.f / (e0 + e1);
            float pr0 = e0 * inv, pr1 = e1 * inv;

            if (pp < H3) {
                const size_t p = rowbase + pp;
                regp[(size_t)(b*4+q)*P3 + p] = o[2+q] + sHB[2+q];
                if (q == 0) probp[(size_t)(b*2+0)*P3 + p] = pr0;
                if (q == 1) probp[(size_t)(b*2+1)*P3 + p] = pr1;
            }
        }
    }
}

// ---------------------------------------------------------------------------
extern "C" void kernel_launch(void* const* d_in, const int* in_sizes, int n_in,
                              void* d_out, int out_size)
{
    const float* x    = (const float*)d_in[0];
    const float* c1w  = (const float*)d_in[1];
    const float* c1b  = (const float*)d_in[2];
    const float* p1a  = (const float*)d_in[3];
    const float* c2w  = (const float*)d_in[4];
    const float* c2b  = (const float*)d_in[5];
    const float* p2a  = (const float*)d_in[6];
    const float* c3w  = (const float*)d_in[7];
    const float* c3b  = (const float*)d_in[8];
    const float* p3a  = (const float*)d_in[9];
    const float* c41w = (const float*)d_in[10];
    const float* c41b = (const float*)d_in[11];
    const float* c42w = (const float*)d_in[12];
    const float* c42b = (const float*)d_in[13];
    float* out = (float*)d_out;

    {
        dim3 blk(32, 4);
        dim3 grd((HP + 31) / 32, (HP + 3) / 4, B);
        k_conv1_pool<<<grd, blk>>>(x, c1w, c1b, p1a);
    }
    {
        dim3 grd((H2 + 127) / 128, (H2 + 3) / 4, B);
        k_conv2_mma<<<grd, 256>>>(c2w, c2b, p2a);
    }
    {
        dim3 grd((H3 + 127) / 128, (H3 + 3) / 4, B);
        k_conv3_heads<<<grd, 256>>>(c3w, c3b, p3a, c41w, c41b, c42w, c42b, out);
    }
}

// round 11
// speedup vs baseline: 3.7274x; 1.0361x over previous
#include <cuda_runtime.h>
#include <cuda_bf16.h>
#include <math.h>
#include <stdint.h>

// ---------------------------------------------------------------------------
// MTCNN P-Net forward.
// Activations stored pre-split into bf16 hi/lo interleaved pairs (64B/pixel).
// conv1: scalar FFMA2, div-free staging.
// conv2: mma.sync bf16 hi/lo, ROW-PAIRED (4 acc chains, same-acc distance 4).
// conv3: mma.sync bf16 hi/lo, term-outer/cg-inner order (distance 4) + fused
//        1x1 heads + softmax.
// ---------------------------------------------------------------------------

#define B       16
#define H0      720
#define HP      359
#define H2      357
#define H3      355
#define P3      (H3*H3)

typedef unsigned long long ull;

__device__ __forceinline__ ull pack2(float a, float b) {
    ull r;
    asm("mov.b64 %0, {%1,%2};" : "=l"(r)
        : "r"(__float_as_uint(a)), "r"(__float_as_uint(b)));
    return r;
}
__device__ __forceinline__ void unpack2(ull v, float& a, float& b) {
    unsigned lo, hi;
    asm("mov.b64 {%0,%1}, %2;" : "=r"(lo), "=r"(hi) : "l"(v));
    a = __uint_as_float(lo); b = __uint_as_float(hi);
}
__device__ __forceinline__ void fma2(ull& d, ull a, ull b) {
    asm("fma.rn.f32x2 %0, %1, %2, %3;" : "=l"(d) : "l"(a), "l"(b), "l"(d));
}

// activations: per pixel 16 uint32 = 8 pairs x {hi, lo} bf16x2
__device__ uint32_t g_p1hl[(size_t)B*HP*HP*16];
__device__ uint32_t g_c2hl[(size_t)B*H2*H2*16];

// ======================= mma.sync helpers ==================================
__device__ __forceinline__ void hilo2(float2 v, uint32_t& hi, uint32_t& lo) {
    __nv_bfloat162 h = __floats2bfloat162_rn(v.x, v.y);
    float rx = v.x - __bfloat162float(h.x);
    float ry = v.y - __bfloat162float(h.y);
    __nv_bfloat162 l = __floats2bfloat162_rn(rx, ry);
    hi = *(uint32_t*)&h; lo = *(uint32_t*)&l;
}
__device__ __forceinline__ void mma16816(float* d, const uint32_t* a,
                                         uint32_t b0, uint32_t b1) {
    asm volatile(
        "mma.sync.aligned.m16n8k16.row.col.f32.bf16.bf16.f32 "
        "{%0,%1,%2,%3}, {%4,%5,%6,%7}, {%8,%9}, {%0,%1,%2,%3};"
        : "+f"(d[0]), "+f"(d[1]), "+f"(d[2]), "+f"(d[3])
        : "r"(a[0]), "r"(a[1]), "r"(a[2]), "r"(a[3]), "r"(b0), "r"(b1));
}
__device__ __forceinline__ void whl(float wv, __nv_bfloat16& h, __nv_bfloat16& l) {
    h = __float2bfloat16(wv);
    l = __float2bfloat16(wv - __bfloat162float(h));
}

// load one row-batch: 12 uint2 (kx=0..2  x  {p0,p1} x {ci0, ci0+8})
__device__ __forceinline__ void load_ky(uint2 (&L)[12], const uint32_t* rp,
                                        int p0c, int p1c, int ci0) {
    #pragma unroll
    for (int kx = 0; kx < 3; kx++) {
        L[kx*4+0] = *(const uint2*)&rp[(p0c + kx)*16 + ci0];
        L[kx*4+1] = *(const uint2*)&rp[(p1c + kx)*16 + ci0];
        L[kx*4+2] = *(const uint2*)&rp[(p0c + kx)*16 + ci0 + 8];
        L[kx*4+3] = *(const uint2*)&rp[(p1c + kx)*16 + ci0 + 8];
    }
}

// ---------------------------------------------------------------------------
// Kernel 1: normalize + conv1(3x3,3->10) + PReLU + maxpool2 -> hl pairs
// ---------------------------------------------------------------------------
__device__ __forceinline__ void conv1_taps(
    ull (&acc)[5][4], const ull sWp[5][3][9], int ci, int ky,
    const ull* top, const ull* bot)
{
    #pragma unroll
    for (int kx = 0; kx < 3; kx++) {
        #pragma unroll
        for (int cp = 0; cp < 5; cp++) {
            ull wp = sWp[cp][ci][ky*3+kx];
            fma2(acc[cp][0], wp, top[kx]);
            fma2(acc[cp][1], wp, top[kx+1]);
            fma2(acc[cp][2], wp, bot[kx]);
            fma2(acc[cp][3], wp, bot[kx+1]);
        }
    }
}

__global__ __launch_bounds__(128, 8) void k_conv1_pool(
    const float* __restrict__ x, const float* __restrict__ w1,
    const float* __restrict__ b1, const float* __restrict__ a1)
{
    __shared__ ull   sWp[5][3][9];
    __shared__ ull   sIn[3][10][66];
    __shared__ float sB[10], sA[10];

    const int b   = blockIdx.z;
    const int px0 = blockIdx.x * 32;
    const int py0 = blockIdx.y * 4;
    const int tid = threadIdx.y * 32 + threadIdx.x;

    for (int i = tid; i < 135; i += 128) {
        int cp = i / 27, ci = (i % 27) / 9, k = i % 9;
        sWp[cp][ci][k] = pack2(w1[(2*cp)*27 + ci*9 + k], w1[(2*cp+1)*27 + ci*9 + k]);
    }
    if (tid < 10) { sB[tid] = b1[tid]; sA[tid] = a1[tid]; }

    const int row0 = 2*py0, col0 = 2*px0;
    {
        const int c  = tid & 63;
        const int r2 = tid >> 6;
        const int gc = col0 + c;
        const bool cok = (gc < H0);
        #pragma unroll
        for (int ci = 0; ci < 3; ci++) {
            #pragma unroll
            for (int r = 0; r < 5; r++) {
                const int rr = 2*r + r2;
                const int gr = row0 + rr;
                float v = 0.f;
                if (cok && gr < H0)
                    v = (x[((b*3+ci)*H0 + gr)*H0 + gc] - 127.5f) * 0.0078125f;
                sIn[ci][rr][c] = pack2(v, v);
            }
        }
        if (tid < 60) {
            int ci = tid / 20, rem = tid % 20;
            int rr = rem >> 1, c2 = 64 + (rem & 1);
            int gr = row0 + rr, gc2 = col0 + c2;
            float v = 0.f;
            if (gr < H0 && gc2 < H0)
                v = (x[((b*3+ci)*H0 + gr)*H0 + gc2] - 127.5f) * 0.0078125f;
            sIn[ci][rr][c2] = pack2(v, v);
        }
    }
    __syncthreads();

    const int px = px0 + threadIdx.x;
    const int py = py0 + threadIdx.y;
    if (px >= HP || py >= HP) return;

    ull acc[5][4];
    #pragma unroll
    for (int cp = 0; cp < 5; cp++) {
        ull bb = pack2(sB[2*cp], sB[2*cp+1]);
        acc[cp][0]=bb; acc[cp][1]=bb; acc[cp][2]=bb; acc[cp][3]=bb;
    }

    const int lr = 2*threadIdx.y, lc = 2*threadIdx.x;
    #pragma unroll
    for (int ci = 0; ci < 3; ci++) {
        ull qa[4], qb[4];
        #pragma unroll
        for (int j = 0; j < 4; j++) qa[j] = sIn[ci][lr  ][lc+j];
        #pragma unroll
        for (int j = 0; j < 4; j++) qb[j] = sIn[ci][lr+1][lc+j];
        conv1_taps(acc, sWp, ci, 0, qa, qb);
        #pragma unroll
        for (int j = 0; j < 4; j++) qa[j] = sIn[ci][lr+2][lc+j];
        conv1_taps(acc, sWp, ci, 1, qb, qa);
        #pragma unroll
        for (int j = 0; j < 4; j++) qb[j] = sIn[ci][lr+3][lc+j];
        conv1_taps(acc, sWp, ci, 2, qa, qb);
    }

    float v[16];
    #pragma unroll
    for (int cp = 0; cp < 5; cp++) {
        float a0 = sA[2*cp], a1v = sA[2*cp+1];
        float m0 = -INFINITY, m1 = -INFINITY;
        #pragma unroll
        for (int k = 0; k < 4; k++) {
            float v0, v1; unpack2(acc[cp][k], v0, v1);
            v0 = (v0 >= 0.f) ? v0 : a0*v0;
            v1 = (v1 >= 0.f) ? v1 : a1v*v1;
            m0 = fmaxf(m0, v0); m1 = fmaxf(m1, v1);
        }
        v[2*cp] = m0; v[2*cp+1] = m1;
    }
    #pragma unroll
    for (int c = 10; c < 16; c++) v[c] = 0.f;

    uint32_t hl[16];
    #pragma unroll
    for (int qd = 0; qd < 8; qd++)
        hilo2(make_float2(v[2*qd], v[2*qd+1]), hl[2*qd], hl[2*qd+1]);

    uint4* dst = (uint4*)&g_p1hl[((size_t)(b*HP + py)*HP + px)*16];
    #pragma unroll
    for (int qd = 0; qd < 4; qd++)
        dst[qd] = make_uint4(hl[qd*4], hl[qd*4+1], hl[qd*4+2], hl[qd*4+3]);
}

// ---------------------------------------------------------------------------
// Kernel 2: conv2 via mma.sync, ROW-PAIRED. 16px x 16co x 2 rows per iter.
// acc[row][cg]: 4 independent chains; per input row, term-outer ordering.
// ---------------------------------------------------------------------------
template<int L>
__device__ __forceinline__ void proc2(float (&acc)[2][2][4], const uint2 (&Ld)[12],
                                      const uint4* __restrict__ sWf, int lane)
{
    #pragma unroll
    for (int kx = 0; kx < 3; kx++) {
        uint32_t ah[4] = {Ld[kx*4+0].x, Ld[kx*4+1].x, Ld[kx*4+2].x, Ld[kx*4+3].x};
        uint32_t al[4] = {Ld[kx*4+0].y, Ld[kx*4+1].y, Ld[kx*4+2].y, Ld[kx*4+3].y};
        uint4 fA0, fA1, fB0, fB1;
        if (L < 3) {
            fA0 = sWf[((L*3+kx)*2 + 0)*32 + lane];
            fA1 = sWf[((L*3+kx)*2 + 1)*32 + lane];
        }
        if (L >= 1) {
            fB0 = sWf[(((L-1)*3+kx)*2 + 0)*32 + lane];
            fB1 = sWf[(((L-1)*3+kx)*2 + 1)*32 + lane];
        }
        // term 0 (hi*hi)
        if (L < 3)  { mma16816(acc[0][0], ah, fA0.x, fA0.y);
                      mma16816(acc[0][1], ah, fA1.x, fA1.y); }
        if (L >= 1) { mma16816(acc[1][0], ah, fB0.x, fB0.y);
                      mma16816(acc[1][1], ah, fB1.x, fB1.y); }
        // term 1 (hi*lo)
        if (L < 3)  { mma16816(acc[0][0], ah, fA0.z, fA0.w);
                      mma16816(acc[0][1], ah, fA1.z, fA1.w); }
        if (L >= 1) { mma16816(acc[1][0], ah, fB0.z, fB0.w);
                      mma16816(acc[1][1], ah, fB1.z, fB1.w); }
        // term 2 (lo*hi)
        if (L < 3)  { mma16816(acc[0][0], al, fA0.x, fA0.y);
                      mma16816(acc[0][1], al, fA1.x, fA1.y); }
        if (L >= 1) { mma16816(acc[1][0], al, fB0.x, fB0.y);
                      mma16816(acc[1][1], al, fB1.x, fB1.y); }
    }
}

__global__ __launch_bounds__(256) void k_conv2_mma(
    const float* __restrict__ w, const float* __restrict__ bias,
    const float* __restrict__ alpha)
{
    __shared__ uint4 sWf[9*2*32];
    __shared__ float sBA[32];

    const int b    = blockIdx.z;
    const int ox0  = blockIdx.x * 128;
    const int oy0  = blockIdx.y * 4;
    const int tid  = threadIdx.x;
    const int wid  = tid >> 5;
    const int lane = tid & 31;

    for (int f = tid; f < 9*2*32; f += 256) {
        int kc = f >> 6, cg = (f >> 5) & 1, ln = f & 31;
        int g = ln >> 2, ci0 = (ln & 3) * 2;
        int co = cg*8 + g;
        int ky = kc / 3, kx = kc % 3;
        __nv_bfloat16 h0,l0,h1,l1,h2,l2,h3,l3;
        float w0 = (ci0   < 10) ? w[((co*10 + ci0  )*3 + ky)*3 + kx] : 0.f;
        float w1v= (ci0+1 < 10) ? w[((co*10 + ci0+1)*3 + ky)*3 + kx] : 0.f;
        float w2 = (ci0+8 < 10) ? w[((co*10 + ci0+8)*3 + ky)*3 + kx] : 0.f;
        float w3 = (ci0+9 < 10) ? w[((co*10 + ci0+9)*3 + ky)*3 + kx] : 0.f;
        whl(w0,h0,l0); whl(w1v,h1,l1); whl(w2,h2,l2); whl(w3,h3,l3);
        __nv_bfloat162 bh0 = {h0,h1}, bh1 = {h2,h3}, bl0 = {l0,l1}, bl1 = {l2,l3};
        sWf[f] = make_uint4(*(uint32_t*)&bh0, *(uint32_t*)&bh1,
                            *(uint32_t*)&bl0, *(uint32_t*)&bl1);
    }
    if (tid < 16) { sBA[tid] = bias[tid]; sBA[16+tid] = alpha[tid]; }
    __syncthreads();

    const int g   = lane >> 2;
    const int ci0 = (lane & 3) * 2;

    const int p0  = ox0 + wid * 16 + g;
    const int p1  = p0 + 8;
    const int p0c = min(p0, H2 - 1);
    const int p1c = min(p1, H2 - 1);

    #pragma unroll
    for (int r2 = 0; r2 < 2; r2++) {
        const int oyA = oy0 + 2*r2;

        const uint32_t* rows[4];
        #pragma unroll
        for (int l = 0; l < 4; l++)
            rows[l] = &g_p1hl[(size_t)(b*HP + min(oyA + l, HP - 1)) * HP * 16];

        float acc[2][2][4];
        #pragma unroll
        for (int rr = 0; rr < 2; rr++)
            #pragma unroll
            for (int cg = 0; cg < 2; cg++)
                #pragma unroll
                for (int j = 0; j < 4; j++) acc[rr][cg][j] = 0.f;

        uint2 A0[12], A1[12];
        load_ky(A0, rows[0], p0c, p1c, ci0);
        load_ky(A1, rows[1], p0c, p1c, ci0);
        proc2<0>(acc, A0, sWf, lane);
        load_ky(A0, rows[2], p0c, p1c, ci0);
        proc2<1>(acc, A1, sWf, lane);
        load_ky(A1, rows[3], p0c, p1c, ci0);
        proc2<2>(acc, A0, sWf, lane);
        proc2<3>(acc, A1, sWf, lane);

        #pragma unroll
        for (int rr = 0; rr < 2; rr++) {
            const int oy = oyA + rr;
            if (oy >= H2) break;
            const size_t rowbase = (size_t)(b*H2 + oy) * H2;
            #pragma unroll
            for (int cg = 0; cg < 2; cg++) {
                const int co = cg*8 + ci0;
                const float b0 = sBA[co], b1 = sBA[co+1];
                const float a0 = sBA[16+co], a1 = sBA[16+co+1];
                float t0 = acc[rr][cg][0] + b0, t1 = acc[rr][cg][1] + b1;
                float t2 = acc[rr][cg][2] + b0, t3 = acc[rr][cg][3] + b1;
                float2 o01, o23;
                o01.x = (t0 >= 0.f) ? t0 : a0*t0;
                o01.y = (t1 >= 0.f) ? t1 : a1*t1;
                o23.x = (t2 >= 0.f) ? t2 : a0*t2;
                o23.y = (t3 >= 0.f) ? t3 : a1*t3;
                uint2 s0, s1;
                hilo2(o01, s0.x, s0.y);
                hilo2(o23, s1.x, s1.y);
                if (p0 < H2) *(uint2*)&g_c2hl[(rowbase + p0)*16 + co] = s0;
                if (p1 < H2) *(uint2*)&g_c2hl[(rowbase + p1)*16 + co] = s1;
            }
        }
    }
}

// ---------------------------------------------------------------------------
// Kernel 3: conv3 (16px x 32co per warp) + fused heads.
// Per kx: 4 weight frags loaded, then term-outer/cg-inner (same-acc dist 4).
// ---------------------------------------------------------------------------
__device__ __forceinline__ void mma_ky4(float (&acc)[4][4], const uint2 (&L)[12],
                                        const uint4* __restrict__ sWf, int kcb,
                                        int lane) {
    #pragma unroll
    for (int kx = 0; kx < 3; kx++) {
        uint32_t ah[4] = {L[kx*4+0].x, L[kx*4+1].x, L[kx*4+2].x, L[kx*4+3].x};
        uint32_t al[4] = {L[kx*4+0].y, L[kx*4+1].y, L[kx*4+2].y, L[kx*4+3].y};
        uint4 f0 = sWf[((kcb+kx)*4 + 0)*32 + lane];
        uint4 f1 = sWf[((kcb+kx)*4 + 1)*32 + lane];
        uint4 f2 = sWf[((kcb+kx)*4 + 2)*32 + lane];
        uint4 f3 = sWf[((kcb+kx)*4 + 3)*32 + lane];
        mma16816(acc[0], ah, f0.x, f0.y);
        mma16816(acc[1], ah, f1.x, f1.y);
        mma16816(acc[2], ah, f2.x, f2.y);
        mma16816(acc[3], ah, f3.x, f3.y);
        mma16816(acc[0], ah, f0.z, f0.w);
        mma16816(acc[1], ah, f1.z, f1.w);
        mma16816(acc[2], ah, f2.z, f2.w);
        mma16816(acc[3], ah, f3.z, f3.w);
        mma16816(acc[0], al, f0.x, f0.y);
        mma16816(acc[1], al, f1.x, f1.y);
        mma16816(acc[2], al, f2.x, f2.y);
        mma16816(acc[3], al, f3.x, f3.y);
    }
}

__global__ __launch_bounds__(256) void k_conv3_heads(
    const float* __restrict__ w, const float* __restrict__ bias,
    const float* __restrict__ alpha,
    const float* __restrict__ w41, const float* __restrict__ b41,
    const float* __restrict__ w42, const float* __restrict__ b42,
    float* __restrict__ out)
{
    __shared__ uint4 sWf[9*4*32];
    __shared__ float sBA[64];
    __shared__ float sHW[6][32];
    __shared__ float sHB[6];

    const int b    = blockIdx.z;
    const int ox0  = blockIdx.x * 128;
    const int oy0  = blockIdx.y * 4;
    const int tid  = threadIdx.x;
    const int wid  = tid >> 5;
    const int lane = tid & 31;

    for (int f = tid; f < 9*4*32; f += 256) {
        int kc = f >> 7, cg = (f >> 5) & 3, ln = f & 31;
        int g = ln >> 2, ci0 = (ln & 3) * 2;
        int co = cg*8 + g;
        int ky = kc / 3, kx = kc % 3;
        __nv_bfloat16 h0,l0,h1,l1,h2,l2,h3,l3;
        whl(w[((co*16 + ci0  )*3 + ky)*3 + kx], h0, l0);
        whl(w[((co*16 + ci0+1)*3 + ky)*3 + kx], h1, l1);
        whl(w[((co*16 + ci0+8)*3 + ky)*3 + kx], h2, l2);
        whl(w[((co*16 + ci0+9)*3 + ky)*3 + kx], h3, l3);
        __nv_bfloat162 bh0 = {h0,h1}, bh1 = {h2,h3}, bl0 = {l0,l1}, bl1 = {l2,l3};
        sWf[f] = make_uint4(*(uint32_t*)&bh0, *(uint32_t*)&bh1,
                            *(uint32_t*)&bl0, *(uint32_t*)&bl1);
    }
    if (tid < 32) { sBA[tid] = bias[tid]; sBA[32+tid] = alpha[tid]; }
    if (tid < 64)  sHW[tid/32][tid%32] = w41[tid];
    if (tid >= 64 && tid < 192) sHW[2 + (tid-64)/32][(tid-64)%32] = w42[tid-64];
    if (tid < 2) sHB[tid] = b41[tid];
    if (tid >= 2 && tid < 6) sHB[tid] = b42[tid-2];
    __syncthreads();

    const int g   = lane >> 2;
    const int ci0 = (lane & 3) * 2;
    const int q   = lane & 3;

    const int p0  = ox0 + wid * 16 + g;
    const int p1  = p0 + 8;
    const int p0c = min(p0, H3 - 1);
    const int p1c = min(p1, H3 - 1);

    float* regp  = out;
    float* probp = out + (size_t)B * 4 * P3;

    for (int r = 0; r < 4; r++) {
        const int oy = oy0 + r;
        if (oy >= H3) break;

        const uint32_t* row0 = &g_c2hl[(size_t)(b*H2 + oy    ) * H2 * 16];
        const uint32_t* row1 = &g_c2hl[(size_t)(b*H2 + oy + 1) * H2 * 16];
        const uint32_t* row2 = &g_c2hl[(size_t)(b*H2 + oy + 2) * H2 * 16];

        float acc[4][4];
        #pragma unroll
        for (int cg = 0; cg < 4; cg++)
            #pragma unroll
            for (int j = 0; j < 4; j++) acc[cg][j] = 0.f;

        uint2 A0[12], A1[12];
        load_ky(A0, row0, p0c, p1c, ci0);
        load_ky(A1, row1, p0c, p1c, ci0);
        mma_ky4(acc, A0, sWf, 0, lane);
        load_ky(A0, row2, p0c, p1c, ci0);
        mma_ky4(acc, A1, sWf, 3, lane);
        mma_ky4(acc, A0, sWf, 6, lane);

        const size_t rowbase = (size_t)oy * H3;
        #pragma unroll
        for (int px = 0; px < 2; px++) {
            const int pp = px ? p1 : p0;
            float o[6];
            #pragma unroll
            for (int k = 0; k < 6; k++) o[k] = 0.f;
            #pragma unroll
            for (int cg = 0; cg < 4; cg++) {
                #pragma unroll
                for (int j = 0; j < 2; j++) {
                    const int ch = cg*8 + ci0 + j;
                    float t = acc[cg][px*2 + j] + sBA[ch];
                    t = (t >= 0.f) ? t : sBA[32+ch]*t;
                    o[0] = fmaf(t, sHW[0][ch], o[0]);
                    o[1] = fmaf(t, sHW[1][ch], o[1]);
                    o[2] = fmaf(t, sHW[2][ch], o[2]);
                    o[3] = fmaf(t, sHW[3][ch], o[3]);
                    o[4] = fmaf(t, sHW[4][ch], o[4]);
                    o[5] = fmaf(t, sHW[5][ch], o[5]);
                }
            }
            #pragma unroll
            for (int off = 1; off <= 2; off <<= 1)
                #pragma unroll
                for (int k = 0; k < 6; k++)
                    o[k] += __shfl_xor_sync(0xffffffffu, o[k], off);

            float l0 = o[0] + sHB[0], l1 = o[1] + sHB[1];
            float m  = fmaxf(l0, l1);
            float e0 = expf(l0 - m), e1 = expf(l1 - m);
            float inv = 1.f / (e0 + e1);
            float pr0 = e0 * inv, pr1 = e1 * inv;

            if (pp < H3) {
                const size_t p = rowbase + pp;
                regp[(size_t)(b*4+q)*P3 + p] = o[2+q] + sHB[2+q];
                if (q == 0) probp[(size_t)(b*2+0)*P3 + p] = pr0;
                if (q == 1) probp[(size_t)(b*2+1)*P3 + p] = pr1;
            }
        }
    }
}

// ---------------------------------------------------------------------------
extern "C" void kernel_launch(void* const* d_in, const int* in_sizes, int n_in,
                              void* d_out, int out_size)
{
    const float* x    = (const float*)d_in[0];
    const float* c1w  = (const float*)d_in[1];
    const float* c1b  = (const float*)d_in[2];
    const float* p1a  = (const float*)d_in[3];
    const float* c2w  = (const float*)d_in[4];
    const float* c2b  = (const float*)d_in[5];
    const float* p2a  = (const float*)d_in[6];
    const float* c3w  = (const float*)d_in[7];
    const float* c3b  = (const float*)d_in[8];
    const float* p3a  = (const float*)d_in[9];
    const float* c41w = (const float*)d_in[10];
    const float* c41b = (const float*)d_in[11];
    const float* c42w = (const float*)d_in[12];
    const float* c42b = (const float*)d_in[13];
    float* out = (float*)d_out;

    {
        dim3 blk(32, 4);
        dim3 grd((HP + 31) / 32, (HP + 3) / 4, B);
        k_conv1_pool<<<grd, blk>>>(x, c1w, c1b, p1a);
    }
    {
        dim3 grd((H2 + 127) / 128, (H2 + 3) / 4, B);
        k_conv2_mma<<<grd, 256>>>(c2w, c2b, p2a);
    }
    {
        dim3 grd((H3 + 127) / 128, (H3 + 3) / 4, B);
        k_conv3_heads<<<grd, 256>>>(c3w, c3b, p3a, c41w, c41b, c42w, c42b, out);
    }
}

// round 12
// speedup vs baseline: 4.1949x; 1.1254x over previous
#include <cuda_runtime.h>
#include <cuda_fp16.h>
#include <math.h>
#include <stdint.h>

// ---------------------------------------------------------------------------
// MTCNN P-Net forward.
// Activations stored pre-split into fp16 hi/lo interleaved pairs (64B/pixel).
// Weights rounded once to fp16 (error ~2^-12, rel_err ~1e-4 << 1e-3).
// conv1: scalar FFMA2, div-free staging.
// conv2: mma.sync fp16 2-term, ROW-PAIRED (4 acc chains).
// conv3: mma.sync fp16 2-term, term-outer/cg-inner + fused heads + softmax.
// ---------------------------------------------------------------------------

#define B       16
#define H0      720
#define HP      359
#define H2      357
#define H3      355
#define P3      (H3*H3)

typedef unsigned long long ull;

__device__ __forceinline__ ull pack2(float a, float b) {
    ull r;
    asm("mov.b64 %0, {%1,%2};" : "=l"(r)
        : "r"(__float_as_uint(a)), "r"(__float_as_uint(b)));
    return r;
}
__device__ __forceinline__ void unpack2(ull v, float& a, float& b) {
    unsigned lo, hi;
    asm("mov.b64 {%0,%1}, %2;" : "=r"(lo), "=r"(hi) : "l"(v));
    a = __uint_as_float(lo); b = __uint_as_float(hi);
}
__device__ __forceinline__ void fma2(ull& d, ull a, ull b) {
    asm("fma.rn.f32x2 %0, %1, %2, %3;" : "=l"(d) : "l"(a), "l"(b), "l"(d));
}

// activations: per pixel 16 uint32 = 8 ch-pairs x {hi, lo} fp16x2
__device__ uint32_t g_p1hl[(size_t)B*HP*HP*16];
__device__ uint32_t g_c2hl[(size_t)B*H2*H2*16];

// ======================= mma.sync helpers (fp16) ===========================
__device__ __forceinline__ void hilo2h(float2 v, uint32_t& hi, uint32_t& lo) {
    __half2 h = __floats2half2_rn(v.x, v.y);
    float rx = v.x - __half2float(__low2half(h));
    float ry = v.y - __half2float(__high2half(h));
    __half2 l = __floats2half2_rn(rx, ry);
    hi = *(uint32_t*)&h; lo = *(uint32_t*)&l;
}
__device__ __forceinline__ void mma16816h(float* d, const uint32_t* a,
                                          uint32_t b0, uint32_t b1) {
    asm volatile(
        "mma.sync.aligned.m16n8k16.row.col.f32.f16.f16.f32 "
        "{%0,%1,%2,%3}, {%4,%5,%6,%7}, {%8,%9}, {%0,%1,%2,%3};"
        : "+f"(d[0]), "+f"(d[1]), "+f"(d[2]), "+f"(d[3])
        : "r"(a[0]), "r"(a[1]), "r"(a[2]), "r"(a[3]), "r"(b0), "r"(b1));
}

// load one row-batch: 12 uint2 (kx=0..2  x  {p0,p1} x {ci0, ci0+8})
__device__ __forceinline__ void load_ky(uint2 (&L)[12], const uint32_t* rp,
                                        int p0c, int p1c, int ci0) {
    #pragma unroll
    for (int kx = 0; kx < 3; kx++) {
        L[kx*4+0] = *(const uint2*)&rp[(p0c + kx)*16 + ci0];
        L[kx*4+1] = *(const uint2*)&rp[(p1c + kx)*16 + ci0];
        L[kx*4+2] = *(const uint2*)&rp[(p0c + kx)*16 + ci0 + 8];
        L[kx*4+3] = *(const uint2*)&rp[(p1c + kx)*16 + ci0 + 8];
    }
}

// ---------------------------------------------------------------------------
// Kernel 1: normalize + conv1(3x3,3->10) + PReLU + maxpool2 -> fp16 hl pairs
// ---------------------------------------------------------------------------
__device__ __forceinline__ void conv1_taps(
    ull (&acc)[5][4], const ull sWp[5][3][9], int ci, int ky,
    const ull* top, const ull* bot)
{
    #pragma unroll
    for (int kx = 0; kx < 3; kx++) {
        #pragma unroll
        for (int cp = 0; cp < 5; cp++) {
            ull wp = sWp[cp][ci][ky*3+kx];
            fma2(acc[cp][0], wp, top[kx]);
            fma2(acc[cp][1], wp, top[kx+1]);
            fma2(acc[cp][2], wp, bot[kx]);
            fma2(acc[cp][3], wp, bot[kx+1]);
        }
    }
}

__global__ __launch_bounds__(128, 8) void k_conv1_pool(
    const float* __restrict__ x, const float* __restrict__ w1,
    const float* __restrict__ b1, const float* __restrict__ a1)
{
    __shared__ ull   sWp[5][3][9];
    __shared__ ull   sIn[3][10][66];
    __shared__ float sB[10], sA[10];

    const int b   = blockIdx.z;
    const int px0 = blockIdx.x * 32;
    const int py0 = blockIdx.y * 4;
    const int tid = threadIdx.y * 32 + threadIdx.x;

    for (int i = tid; i < 135; i += 128) {
        int cp = i / 27, ci = (i % 27) / 9, k = i % 9;
        sWp[cp][ci][k] = pack2(w1[(2*cp)*27 + ci*9 + k], w1[(2*cp+1)*27 + ci*9 + k]);
    }
    if (tid < 10) { sB[tid] = b1[tid]; sA[tid] = a1[tid]; }

    const int row0 = 2*py0, col0 = 2*px0;
    {
        const int c  = tid & 63;
        const int r2 = tid >> 6;
        const int gc = col0 + c;
        const bool cok = (gc < H0);
        #pragma unroll
        for (int ci = 0; ci < 3; ci++) {
            #pragma unroll
            for (int r = 0; r < 5; r++) {
                const int rr = 2*r + r2;
                const int gr = row0 + rr;
                float v = 0.f;
                if (cok && gr < H0)
                    v = (x[((b*3+ci)*H0 + gr)*H0 + gc] - 127.5f) * 0.0078125f;
                sIn[ci][rr][c] = pack2(v, v);
            }
        }
        if (tid < 60) {
            int ci = tid / 20, rem = tid % 20;
            int rr = rem >> 1, c2 = 64 + (rem & 1);
            int gr = row0 + rr, gc2 = col0 + c2;
            float v = 0.f;
            if (gr < H0 && gc2 < H0)
                v = (x[((b*3+ci)*H0 + gr)*H0 + gc2] - 127.5f) * 0.0078125f;
            sIn[ci][rr][c2] = pack2(v, v);
        }
    }
    __syncthreads();

    const int px = px0 + threadIdx.x;
    const int py = py0 + threadIdx.y;
    if (px >= HP || py >= HP) return;

    ull acc[5][4];
    #pragma unroll
    for (int cp = 0; cp < 5; cp++) {
        ull bb = pack2(sB[2*cp], sB[2*cp+1]);
        acc[cp][0]=bb; acc[cp][1]=bb; acc[cp][2]=bb; acc[cp][3]=bb;
    }

    const int lr = 2*threadIdx.y, lc = 2*threadIdx.x;
    #pragma unroll
    for (int ci = 0; ci < 3; ci++) {
        ull qa[4], qb[4];
        #pragma unroll
        for (int j = 0; j < 4; j++) qa[j] = sIn[ci][lr  ][lc+j];
        #pragma unroll
        for (int j = 0; j < 4; j++) qb[j] = sIn[ci][lr+1][lc+j];
        conv1_taps(acc, sWp, ci, 0, qa, qb);
        #pragma unroll
        for (int j = 0; j < 4; j++) qa[j] = sIn[ci][lr+2][lc+j];
        conv1_taps(acc, sWp, ci, 1, qb, qa);
        #pragma unroll
        for (int j = 0; j < 4; j++) qb[j] = sIn[ci][lr+3][lc+j];
        conv1_taps(acc, sWp, ci, 2, qa, qb);
    }

    float v[16];
    #pragma unroll
    for (int cp = 0; cp < 5; cp++) {
        float a0 = sA[2*cp], a1v = sA[2*cp+1];
        float m0 = -INFINITY, m1 = -INFINITY;
        #pragma unroll
        for (int k = 0; k < 4; k++) {
            float v0, v1; unpack2(acc[cp][k], v0, v1);
            v0 = (v0 >= 0.f) ? v0 : a0*v0;
            v1 = (v1 >= 0.f) ? v1 : a1v*v1;
            m0 = fmaxf(m0, v0); m1 = fmaxf(m1, v1);
        }
        v[2*cp] = m0; v[2*cp+1] = m1;
    }
    #pragma unroll
    for (int c = 10; c < 16; c++) v[c] = 0.f;

    uint32_t hl[16];
    #pragma unroll
    for (int qd = 0; qd < 8; qd++)
        hilo2h(make_float2(v[2*qd], v[2*qd+1]), hl[2*qd], hl[2*qd+1]);

    uint4* dst = (uint4*)&g_p1hl[((size_t)(b*HP + py)*HP + px)*16];
    #pragma unroll
    for (int qd = 0; qd < 4; qd++)
        dst[qd] = make_uint4(hl[qd*4], hl[qd*4+1], hl[qd*4+2], hl[qd*4+3]);
}

// ---------------------------------------------------------------------------
// Kernel 2: conv2 via mma.sync fp16 2-term, ROW-PAIRED.
// ---------------------------------------------------------------------------
template<int L>
__device__ __forceinline__ void proc2(float (&acc)[2][2][4], const uint2 (&Ld)[12],
                                      const uint2* __restrict__ sWf, int lane)
{
    #pragma unroll
    for (int kx = 0; kx < 3; kx++) {
        uint32_t ah[4] = {Ld[kx*4+0].x, Ld[kx*4+1].x, Ld[kx*4+2].x, Ld[kx*4+3].x};
        uint32_t al[4] = {Ld[kx*4+0].y, Ld[kx*4+1].y, Ld[kx*4+2].y, Ld[kx*4+3].y};
        uint2 fA0, fA1, fB0, fB1;
        if (L < 3) {
            fA0 = sWf[((L*3+kx)*2 + 0)*32 + lane];
            fA1 = sWf[((L*3+kx)*2 + 1)*32 + lane];
        }
        if (L >= 1) {
            fB0 = sWf[(((L-1)*3+kx)*2 + 0)*32 + lane];
            fB1 = sWf[(((L-1)*3+kx)*2 + 1)*32 + lane];
        }
        // term 0 (Ah * B)
        if (L < 3)  { mma16816h(acc[0][0], ah, fA0.x, fA0.y);
                      mma16816h(acc[0][1], ah, fA1.x, fA1.y); }
        if (L >= 1) { mma16816h(acc[1][0], ah, fB0.x, fB0.y);
                      mma16816h(acc[1][1], ah, fB1.x, fB1.y); }
        // term 1 (Al * B)
        if (L < 3)  { mma16816h(acc[0][0], al, fA0.x, fA0.y);
                      mma16816h(acc[0][1], al, fA1.x, fA1.y); }
        if (L >= 1) { mma16816h(acc[1][0], al, fB0.x, fB0.y);
                      mma16816h(acc[1][1], al, fB1.x, fB1.y); }
    }
}

__global__ __launch_bounds__(256) void k_conv2_mma(
    const float* __restrict__ w, const float* __restrict__ bias,
    const float* __restrict__ alpha)
{
    __shared__ uint2 sWf[9*2*32];
    __shared__ float sBA[32];

    const int b    = blockIdx.z;
    const int ox0  = blockIdx.x * 128;
    const int oy0  = blockIdx.y * 4;
    const int tid  = threadIdx.x;
    const int wid  = tid >> 5;
    const int lane = tid & 31;

    for (int f = tid; f < 9*2*32; f += 256) {
        int kc = f >> 6, cg = (f >> 5) & 1, ln = f & 31;
        int g = ln >> 2, ci0 = (ln & 3) * 2;
        int co = cg*8 + g;
        int ky = kc / 3, kx = kc % 3;
        float w0 = (ci0   < 10) ? w[((co*10 + ci0  )*3 + ky)*3 + kx] : 0.f;
        float w1v= (ci0+1 < 10) ? w[((co*10 + ci0+1)*3 + ky)*3 + kx] : 0.f;
        float w2 = (ci0+8 < 10) ? w[((co*10 + ci0+8)*3 + ky)*3 + kx] : 0.f;
        float w3 = (ci0+9 < 10) ? w[((co*10 + ci0+9)*3 + ky)*3 + kx] : 0.f;
        __half2 b0 = __floats2half2_rn(w0, w1v);
        __half2 b1 = __floats2half2_rn(w2, w3);
        sWf[f] = make_uint2(*(uint32_t*)&b0, *(uint32_t*)&b1);
    }
    if (tid < 16) { sBA[tid] = bias[tid]; sBA[16+tid] = alpha[tid]; }
    __syncthreads();

    const int g   = lane >> 2;
    const int ci0 = (lane & 3) * 2;

    const int p0  = ox0 + wid * 16 + g;
    const int p1  = p0 + 8;
    const int p0c = min(p0, H2 - 1);
    const int p1c = min(p1, H2 - 1);

    #pragma unroll
    for (int r2 = 0; r2 < 2; r2++) {
        const int oyA = oy0 + 2*r2;

        const uint32_t* rows[4];
        #pragma unroll
        for (int l = 0; l < 4; l++)
            rows[l] = &g_p1hl[(size_t)(b*HP + min(oyA + l, HP - 1)) * HP * 16];

        float acc[2][2][4];
        #pragma unroll
        for (int rr = 0; rr < 2; rr++)
            #pragma unroll
            for (int cg = 0; cg < 2; cg++)
                #pragma unroll
                for (int j = 0; j < 4; j++) acc[rr][cg][j] = 0.f;

        uint2 A0[12], A1[12];
        load_ky(A0, rows[0], p0c, p1c, ci0);
        load_ky(A1, rows[1], p0c, p1c, ci0);
        proc2<0>(acc, A0, sWf, lane);
        load_ky(A0, rows[2], p0c, p1c, ci0);
        proc2<1>(acc, A1, sWf, lane);
        load_ky(A1, rows[3], p0c, p1c, ci0);
        proc2<2>(acc, A0, sWf, lane);
        proc2<3>(acc, A1, sWf, lane);

        #pragma unroll
        for (int rr = 0; rr < 2; rr++) {
            const int oy = oyA + rr;
            if (oy >= H2) break;
            const size_t rowbase = (size_t)(b*H2 + oy) * H2;
            #pragma unroll
            for (int cg = 0; cg < 2; cg++) {
                const int co = cg*8 + ci0;
                const float b0 = sBA[co], b1 = sBA[co+1];
                const float a0 = sBA[16+co], a1 = sBA[16+co+1];
                float t0 = acc[rr][cg][0] + b0, t1 = acc[rr][cg][1] + b1;
                float t2 = acc[rr][cg][2] + b0, t3 = acc[rr][cg][3] + b1;
                float2 o01, o23;
                o01.x = (t0 >= 0.f) ? t0 : a0*t0;
                o01.y = (t1 >= 0.f) ? t1 : a1*t1;
                o23.x = (t2 >= 0.f) ? t2 : a0*t2;
                o23.y = (t3 >= 0.f) ? t3 : a1*t3;
                uint2 s0, s1;
                hilo2h(o01, s0.x, s0.y);
                hilo2h(o23, s1.x, s1.y);
                if (p0 < H2) *(uint2*)&g_c2hl[(rowbase + p0)*16 + co] = s0;
                if (p1 < H2) *(uint2*)&g_c2hl[(rowbase + p1)*16 + co] = s1;
            }
        }
    }
}

// ---------------------------------------------------------------------------
// Kernel 3: conv3 (16px x 32co per warp) + fused heads, fp16 2-term.
// ---------------------------------------------------------------------------
__device__ __forceinline__ void mma_ky4(float (&acc)[4][4], const uint2 (&L)[12],
                                        const uint2* __restrict__ sWf, int kcb,
                                        int lane) {
    #pragma unroll
    for (int kx = 0; kx < 3; kx++) {
        uint32_t ah[4] = {L[kx*4+0].x, L[kx*4+1].x, L[kx*4+2].x, L[kx*4+3].x};
        uint32_t al[4] = {L[kx*4+0].y, L[kx*4+1].y, L[kx*4+2].y, L[kx*4+3].y};
        uint2 f0 = sWf[((kcb+kx)*4 + 0)*32 + lane];
        uint2 f1 = sWf[((kcb+kx)*4 + 1)*32 + lane];
        uint2 f2 = sWf[((kcb+kx)*4 + 2)*32 + lane];
        uint2 f3 = sWf[((kcb+kx)*4 + 3)*32 + lane];
        mma16816h(acc[0], ah, f0.x, f0.y);
        mma16816h(acc[1], ah, f1.x, f1.y);
        mma16816h(acc[2], ah, f2.x, f2.y);
        mma16816h(acc[3], ah, f3.x, f3.y);
        mma16816h(acc[0], al, f0.x, f0.y);
        mma16816h(acc[1], al, f1.x, f1.y);
        mma16816h(acc[2], al, f2.x, f2.y);
        mma16816h(acc[3], al, f3.x, f3.y);
    }
}

__global__ __launch_bounds__(256) void k_conv3_heads(
    const float* __restrict__ w, const float* __restrict__ bias,
    const float* __restrict__ alpha,
    const float* __restrict__ w41, const float* __restrict__ b41,
    const float* __restrict__ w42, const float* __restrict__ b42,
    float* __restrict__ out)
{
    __shared__ uint2 sWf[9*4*32];
    __shared__ float sBA[64];
    __shared__ float sHW[6][32];
    __shared__ float sHB[6];

    const int b    = blockIdx.z;
    const int ox0  = blockIdx.x * 128;
    const int oy0  = blockIdx.y * 4;
    const int tid  = threadIdx.x;
    const int wid  = tid >> 5;
    const int lane = tid & 31;

    for (int f = tid; f < 9*4*32; f += 256) {
        int kc = f >> 7, cg = (f >> 5) & 3, ln = f & 31;
        int g = ln >> 2, ci0 = (ln & 3) * 2;
        int co = cg*8 + g;
        int ky = kc / 3, kx = kc % 3;
        __half2 b0 = __floats2half2_rn(w[((co*16 + ci0  )*3 + ky)*3 + kx],
                                       w[((co*16 + ci0+1)*3 + ky)*3 + kx]);
        __half2 b1 = __floats2half2_rn(w[((co*16 + ci0+8)*3 + ky)*3 + kx],
                                       w[((co*16 + ci0+9)*3 + ky)*3 + kx]);
        sWf[f] = make_uint2(*(uint32_t*)&b0, *(uint32_t*)&b1);
    }
    if (tid < 32) { sBA[tid] = bias[tid]; sBA[32+tid] = alpha[tid]; }
    if (tid < 64)  sHW[tid/32][tid%32] = w41[tid];
    if (tid >= 64 && tid < 192) sHW[2 + (tid-64)/32][(tid-64)%32] = w42[tid-64];
    if (tid < 2) sHB[tid] = b41[tid];
    if (tid >= 2 && tid < 6) sHB[tid] = b42[tid-2];
    __syncthreads();

    const int g   = lane >> 2;
    const int ci0 = (lane & 3) * 2;
    const int q   = lane & 3;

    const int p0  = ox0 + wid * 16 + g;
    const int p1  = p0 + 8;
    const int p0c = min(p0, H3 - 1);
    const int p1c = min(p1, H3 - 1);

    float* regp  = out;
    float* probp = out + (size_t)B * 4 * P3;

    for (int r = 0; r < 4; r++) {
        const int oy = oy0 + r;
        if (oy >= H3) break;

        const uint32_t* row0 = &g_c2hl[(size_t)(b*H2 + oy    ) * H2 * 16];
        const uint32_t* row1 = &g_c2hl[(size_t)(b*H2 + oy + 1) * H2 * 16];
        const uint32_t* row2 = &g_c2hl[(size_t)(b*H2 + oy + 2) * H2 * 16];

        float acc[4][4];
        #pragma unroll
        for (int cg = 0; cg < 4; cg++)
            #pragma unroll
            for (int j = 0; j < 4; j++) acc[cg][j] = 0.f;

        uint2 A0[12], A1[12];
        load_ky(A0, row0, p0c, p1c, ci0);
        load_ky(A1, row1, p0c, p1c, ci0);
        mma_ky4(acc, A0, sWf, 0, lane);
        load_ky(A0, row2, p0c, p1c, ci0);
        mma_ky4(acc, A1, sWf, 3, lane);
        mma_ky4(acc, A0, sWf, 6, lane);

        const size_t rowbase = (size_t)oy * H3;
        #pragma unroll
        for (int px = 0; px < 2; px++) {
            const int pp = px ? p1 : p0;
            float o[6];
            #pragma unroll
            for (int k = 0; k < 6; k++) o[k] = 0.f;
            #pragma unroll
            for (int cg = 0; cg < 4; cg++) {
                #pragma unroll
                for (int j = 0; j < 2; j++) {
                    const int ch = cg*8 + ci0 + j;
                    float t = acc[cg][px*2 + j] + sBA[ch];
                    t = (t >= 0.f) ? t : sBA[32+ch]*t;
                    o[0] = fmaf(t, sHW[0][ch], o[0]);
                    o[1] = fmaf(t, sHW[1][ch], o[1]);
                    o[2] = fmaf(t, sHW[2][ch], o[2]);
                    o[3] = fmaf(t, sHW[3][ch], o[3]);
                    o[4] = fmaf(t, sHW[4][ch], o[4]);
                    o[5] = fmaf(t, sHW[5][ch], o[5]);
                }
            }
            #pragma unroll
            for (int off = 1; off <= 2; off <<= 1)
                #pragma unroll
                for (int k = 0; k < 6; k++)
                    o[k] += __shfl_xor_sync(0xffffffffu, o[k], off);

            float l0 = o[0] + sHB[0], l1 = o[1] + sHB[1];
            float m  = fmaxf(l0, l1);
            float e0 = expf(l0 - m), e1 = expf(l1 - m);
            float inv = 1.f / (e0 + e1);
            float pr0 = e0 * inv, pr1 = e1 * inv;

            if (pp < H3) {
                const size_t p = rowbase + pp;
                regp[(size_t)(b*4+q)*P3 + p] = o[2+q] + sHB[2+q];
                if (q == 0) probp[(size_t)(b*2+0)*P3 + p] = pr0;
                if (q == 1) probp[(size_t)(b*2+1)*P3 + p] = pr1;
            }
        }
    }
}

// ---------------------------------------------------------------------------
extern "C" void kernel_launch(void* const* d_in, const int* in_sizes, int n_in,
                              void* d_out, int out_size)
{
    const float* x    = (const float*)d_in[0];
    const float* c1w  = (const float*)d_in[1];
    const float* c1b  = (const float*)d_in[2];
    const float* p1a  = (const float*)d_in[3];
    const float* c2w  = (const float*)d_in[4];
    const float* c2b  = (const float*)d_in[5];
    const float* p2a  = (const float*)d_in[6];
    const float* c3w  = (const float*)d_in[7];
    const float* c3b  = (const float*)d_in[8];
    const float* p3a  = (const float*)d_in[9];
    const float* c41w = (const float*)d_in[10];
    const float* c41b = (const float*)d_in[11];
    const float* c42w = (const float*)d_in[12];
    const float* c42b = (const float*)d_in[13];
    float* out = (float*)d_out;

    {
        dim3 blk(32, 4);
        dim3 grd((HP + 31) / 32, (HP + 3) / 4, B);
        k_conv1_pool<<<grd, blk>>>(x, c1w, c1b, p1a);
    }
    {
        dim3 grd((H2 + 127) / 128, (H2 + 3) / 4, B);
        k_conv2_mma<<<grd, 256>>>(c2w, c2b, p2a);
    }
    {
        dim3 grd((H3 + 127) / 128, (H3 + 3) / 4, B);
        k_conv3_heads<<<grd, 256>>>(c3w, c3b, p3a, c41w, c41b, c42w, c42b, out);
    }
}

// round 13
// speedup vs baseline: 5.2615x; 1.2543x over previous
#include <cuda_runtime.h>
#include <cuda_fp16.h>
#include <math.h>
#include <stdint.h>

// ---------------------------------------------------------------------------
// MTCNN P-Net forward. PURE fp16 tensor-core path (1-term):
// activations stored as fp16 (8 x half2 = 32B/pixel), weights fp16.
// conv1: scalar FFMA2 (fp32), div-free staging -> fp16 ch-last out.
// conv2: mma.sync fp16, ROW-PAIRED (4 acc chains).
// conv3: mma.sync fp16, cg-inner (distance 4) + fused heads + softmax.
// ---------------------------------------------------------------------------

#define B       16
#define H0      720
#define HP      359
#define H2      357
#define H3      355
#define P3      (H3*H3)

typedef unsigned long long ull;

__device__ __forceinline__ ull pack2(float a, float b) {
    ull r;
    asm("mov.b64 %0, {%1,%2};" : "=l"(r)
        : "r"(__float_as_uint(a)), "r"(__float_as_uint(b)));
    return r;
}
__device__ __forceinline__ void unpack2(ull v, float& a, float& b) {
    unsigned lo, hi;
    asm("mov.b64 {%0,%1}, %2;" : "=r"(lo), "=r"(hi) : "l"(v));
    a = __uint_as_float(lo); b = __uint_as_float(hi);
}
__device__ __forceinline__ void fma2(ull& d, ull a, ull b) {
    asm("fma.rn.f32x2 %0, %1, %2, %3;" : "=l"(d) : "l"(a), "l"(b), "l"(d));
}

// activations: per pixel 8 uint32 = 8 ch-pairs fp16x2 (32B/pixel)
__device__ uint32_t g_p1h[(size_t)B*HP*HP*8];
__device__ uint32_t g_c2h[(size_t)B*H2*H2*8];

// ======================= mma.sync helpers (fp16) ===========================
__device__ __forceinline__ void mma16816h(float* d, const uint32_t* a,
                                          uint32_t b0, uint32_t b1) {
    asm volatile(
        "mma.sync.aligned.m16n8k16.row.col.f32.f16.f16.f32 "
        "{%0,%1,%2,%3}, {%4,%5,%6,%7}, {%8,%9}, {%0,%1,%2,%3};"
        : "+f"(d[0]), "+f"(d[1]), "+f"(d[2]), "+f"(d[3])
        : "r"(a[0]), "r"(a[1]), "r"(a[2]), "r"(a[3]), "r"(b0), "r"(b1));
}

// load one row-batch: 12 uint32 frag regs (kx 0..2 x {p0,p1} x {q4, q4+4})
__device__ __forceinline__ void load_ky1(uint32_t (&L)[12], const uint32_t* rp,
                                         int p0c, int p1c, int q4) {
    #pragma unroll
    for (int kx = 0; kx < 3; kx++) {
        L[kx*4+0] = rp[(p0c + kx)*8 + q4];
        L[kx*4+1] = rp[(p1c + kx)*8 + q4];
        L[kx*4+2] = rp[(p0c + kx)*8 + q4 + 4];
        L[kx*4+3] = rp[(p1c + kx)*8 + q4 + 4];
    }
}

// ---------------------------------------------------------------------------
// Kernel 1: normalize + conv1(3x3,3->10) + PReLU + maxpool2 -> fp16 ch-last
// ---------------------------------------------------------------------------
__device__ __forceinline__ void conv1_taps(
    ull (&acc)[5][4], const ull sWp[5][3][9], int ci, int ky,
    const ull* top, const ull* bot)
{
    #pragma unroll
    for (int kx = 0; kx < 3; kx++) {
        #pragma unroll
        for (int cp = 0; cp < 5; cp++) {
            ull wp = sWp[cp][ci][ky*3+kx];
            fma2(acc[cp][0], wp, top[kx]);
            fma2(acc[cp][1], wp, top[kx+1]);
            fma2(acc[cp][2], wp, bot[kx]);
            fma2(acc[cp][3], wp, bot[kx+1]);
        }
    }
}

__global__ __launch_bounds__(128, 8) void k_conv1_pool(
    const float* __restrict__ x, const float* __restrict__ w1,
    const float* __restrict__ b1, const float* __restrict__ a1)
{
    __shared__ ull   sWp[5][3][9];
    __shared__ ull   sIn[3][10][66];
    __shared__ float sB[10], sA[10];

    const int b   = blockIdx.z;
    const int px0 = blockIdx.x * 32;
    const int py0 = blockIdx.y * 4;
    const int tid = threadIdx.y * 32 + threadIdx.x;

    for (int i = tid; i < 135; i += 128) {
        int cp = i / 27, ci = (i % 27) / 9, k = i % 9;
        sWp[cp][ci][k] = pack2(w1[(2*cp)*27 + ci*9 + k], w1[(2*cp+1)*27 + ci*9 + k]);
    }
    if (tid < 10) { sB[tid] = b1[tid]; sA[tid] = a1[tid]; }

    const int row0 = 2*py0, col0 = 2*px0;
    {
        const int c  = tid & 63;
        const int r2 = tid >> 6;
        const int gc = col0 + c;
        const bool cok = (gc < H0);
        #pragma unroll
        for (int ci = 0; ci < 3; ci++) {
            #pragma unroll
            for (int r = 0; r < 5; r++) {
                const int rr = 2*r + r2;
                const int gr = row0 + rr;
                float v = 0.f;
                if (cok && gr < H0)
                    v = (x[((b*3+ci)*H0 + gr)*H0 + gc] - 127.5f) * 0.0078125f;
                sIn[ci][rr][c] = pack2(v, v);
            }
        }
        if (tid < 60) {
            int ci = tid / 20, rem = tid % 20;
            int rr = rem >> 1, c2 = 64 + (rem & 1);
            int gr = row0 + rr, gc2 = col0 + c2;
            float v = 0.f;
            if (gr < H0 && gc2 < H0)
                v = (x[((b*3+ci)*H0 + gr)*H0 + gc2] - 127.5f) * 0.0078125f;
            sIn[ci][rr][c2] = pack2(v, v);
        }
    }
    __syncthreads();

    const int px = px0 + threadIdx.x;
    const int py = py0 + threadIdx.y;
    if (px >= HP || py >= HP) return;

    ull acc[5][4];
    #pragma unroll
    for (int cp = 0; cp < 5; cp++) {
        ull bb = pack2(sB[2*cp], sB[2*cp+1]);
        acc[cp][0]=bb; acc[cp][1]=bb; acc[cp][2]=bb; acc[cp][3]=bb;
    }

    const int lr = 2*threadIdx.y, lc = 2*threadIdx.x;
    #pragma unroll
    for (int ci = 0; ci < 3; ci++) {
        ull qa[4], qb[4];
        #pragma unroll
        for (int j = 0; j < 4; j++) qa[j] = sIn[ci][lr  ][lc+j];
        #pragma unroll
        for (int j = 0; j < 4; j++) qb[j] = sIn[ci][lr+1][lc+j];
        conv1_taps(acc, sWp, ci, 0, qa, qb);
        #pragma unroll
        for (int j = 0; j < 4; j++) qa[j] = sIn[ci][lr+2][lc+j];
        conv1_taps(acc, sWp, ci, 1, qb, qa);
        #pragma unroll
        for (int j = 0; j < 4; j++) qb[j] = sIn[ci][lr+3][lc+j];
        conv1_taps(acc, sWp, ci, 2, qa, qb);
    }

    float v[16];
    #pragma unroll
    for (int cp = 0; cp < 5; cp++) {
        float a0 = sA[2*cp], a1v = sA[2*cp+1];
        float m0 = -INFINITY, m1 = -INFINITY;
        #pragma unroll
        for (int k = 0; k < 4; k++) {
            float v0, v1; unpack2(acc[cp][k], v0, v1);
            v0 = (v0 >= 0.f) ? v0 : a0*v0;
            v1 = (v1 >= 0.f) ? v1 : a1v*v1;
            m0 = fmaxf(m0, v0); m1 = fmaxf(m1, v1);
        }
        v[2*cp] = m0; v[2*cp+1] = m1;
    }
    #pragma unroll
    for (int c = 10; c < 16; c++) v[c] = 0.f;

    uint32_t h[8];
    #pragma unroll
    for (int qd = 0; qd < 8; qd++) {
        __half2 hh = __floats2half2_rn(v[2*qd], v[2*qd+1]);
        h[qd] = *(uint32_t*)&hh;
    }

    uint4* dst = (uint4*)&g_p1h[((size_t)(b*HP + py)*HP + px)*8];
    dst[0] = make_uint4(h[0], h[1], h[2], h[3]);
    dst[1] = make_uint4(h[4], h[5], h[6], h[7]);
}

// ---------------------------------------------------------------------------
// Kernel 2: conv2 via mma.sync fp16 1-term, ROW-PAIRED.
// ---------------------------------------------------------------------------
template<int L>
__device__ __forceinline__ void proc2(float (&acc)[2][2][4], const uint32_t (&Ld)[12],
                                      const uint2* __restrict__ sWf, int lane)
{
    #pragma unroll
    for (int kx = 0; kx < 3; kx++) {
        uint32_t ah[4] = {Ld[kx*4+0], Ld[kx*4+1], Ld[kx*4+2], Ld[kx*4+3]};
        uint2 fA0, fA1, fB0, fB1;
        if (L < 3) {
            fA0 = sWf[((L*3+kx)*2 + 0)*32 + lane];
            fA1 = sWf[((L*3+kx)*2 + 1)*32 + lane];
        }
        if (L >= 1) {
            fB0 = sWf[(((L-1)*3+kx)*2 + 0)*32 + lane];
            fB1 = sWf[(((L-1)*3+kx)*2 + 1)*32 + lane];
        }
        if (L < 3)  { mma16816h(acc[0][0], ah, fA0.x, fA0.y);
                      mma16816h(acc[0][1], ah, fA1.x, fA1.y); }
        if (L >= 1) { mma16816h(acc[1][0], ah, fB0.x, fB0.y);
                      mma16816h(acc[1][1], ah, fB1.x, fB1.y); }
    }
}

__global__ __launch_bounds__(256) void k_conv2_mma(
    const float* __restrict__ w, const float* __restrict__ bias,
    const float* __restrict__ alpha)
{
    __shared__ uint2 sWf[9*2*32];
    __shared__ float sBA[32];

    const int b    = blockIdx.z;
    const int ox0  = blockIdx.x * 128;
    const int oy0  = blockIdx.y * 4;
    const int tid  = threadIdx.x;
    const int wid  = tid >> 5;
    const int lane = tid & 31;

    for (int f = tid; f < 9*2*32; f += 256) {
        int kc = f >> 6, cg = (f >> 5) & 1, ln = f & 31;
        int g = ln >> 2, ci0 = (ln & 3) * 2;
        int co = cg*8 + g;
        int ky = kc / 3, kx = kc % 3;
        float w0 = (ci0   < 10) ? w[((co*10 + ci0  )*3 + ky)*3 + kx] : 0.f;
        float w1v= (ci0+1 < 10) ? w[((co*10 + ci0+1)*3 + ky)*3 + kx] : 0.f;
        float w2 = (ci0+8 < 10) ? w[((co*10 + ci0+8)*3 + ky)*3 + kx] : 0.f;
        float w3 = (ci0+9 < 10) ? w[((co*10 + ci0+9)*3 + ky)*3 + kx] : 0.f;
        __half2 b0 = __floats2half2_rn(w0, w1v);
        __half2 b1 = __floats2half2_rn(w2, w3);
        sWf[f] = make_uint2(*(uint32_t*)&b0, *(uint32_t*)&b1);
    }
    if (tid < 16) { sBA[tid] = bias[tid]; sBA[16+tid] = alpha[tid]; }
    __syncthreads();

    const int q4  = lane & 3;
    const int g   = lane >> 2;
    const int ci0 = q4 * 2;

    const int p0  = ox0 + wid * 16 + g;
    const int p1  = p0 + 8;
    const int p0c = min(p0, H2 - 1);
    const int p1c = min(p1, H2 - 1);

    #pragma unroll
    for (int r2 = 0; r2 < 2; r2++) {
        const int oyA = oy0 + 2*r2;

        const uint32_t* rows[4];
        #pragma unroll
        for (int l = 0; l < 4; l++)
            rows[l] = &g_p1h[(size_t)(b*HP + min(oyA + l, HP - 1)) * HP * 8];

        float acc[2][2][4];
        #pragma unroll
        for (int rr = 0; rr < 2; rr++)
            #pragma unroll
            for (int cg = 0; cg < 2; cg++)
                #pragma unroll
                for (int j = 0; j < 4; j++) acc[rr][cg][j] = 0.f;

        uint32_t A0[12], A1[12];
        load_ky1(A0, rows[0], p0c, p1c, q4);
        load_ky1(A1, rows[1], p0c, p1c, q4);
        proc2<0>(acc, A0, sWf, lane);
        load_ky1(A0, rows[2], p0c, p1c, q4);
        proc2<1>(acc, A1, sWf, lane);
        load_ky1(A1, rows[3], p0c, p1c, q4);
        proc2<2>(acc, A0, sWf, lane);
        proc2<3>(acc, A1, sWf, lane);

        #pragma unroll
        for (int rr = 0; rr < 2; rr++) {
            const int oy = oyA + rr;
            if (oy >= H2) break;
            const size_t rowbase = (size_t)(b*H2 + oy) * H2;
            #pragma unroll
            for (int cg = 0; cg < 2; cg++) {
                const int co = cg*8 + ci0;
                const float b0 = sBA[co], b1 = sBA[co+1];
                const float a0 = sBA[16+co], a1 = sBA[16+co+1];
                float t0 = acc[rr][cg][0] + b0, t1 = acc[rr][cg][1] + b1;
                float t2 = acc[rr][cg][2] + b0, t3 = acc[rr][cg][3] + b1;
                float o00 = (t0 >= 0.f) ? t0 : a0*t0;
                float o01 = (t1 >= 0.f) ? t1 : a1*t1;
                float o10 = (t2 >= 0.f) ? t2 : a0*t2;
                float o11 = (t3 >= 0.f) ? t3 : a1*t3;
                __half2 s0 = __floats2half2_rn(o00, o01);
                __half2 s1 = __floats2half2_rn(o10, o11);
                if (p0 < H2) g_c2h[(rowbase + p0)*8 + cg*4 + q4] = *(uint32_t*)&s0;
                if (p1 < H2) g_c2h[(rowbase + p1)*8 + cg*4 + q4] = *(uint32_t*)&s1;
            }
        }
    }
}

// ---------------------------------------------------------------------------
// Kernel 3: conv3 (16px x 32co per warp) + fused heads, fp16 1-term.
// ---------------------------------------------------------------------------
__device__ __forceinline__ void mma_ky4(float (&acc)[4][4], const uint32_t (&L)[12],
                                        const uint2* __restrict__ sWf, int kcb,
                                        int lane) {
    #pragma unroll
    for (int kx = 0; kx < 3; kx++) {
        uint32_t ah[4] = {L[kx*4+0], L[kx*4+1], L[kx*4+2], L[kx*4+3]};
        uint2 f0 = sWf[((kcb+kx)*4 + 0)*32 + lane];
        uint2 f1 = sWf[((kcb+kx)*4 + 1)*32 + lane];
        uint2 f2 = sWf[((kcb+kx)*4 + 2)*32 + lane];
        uint2 f3 = sWf[((kcb+kx)*4 + 3)*32 + lane];
        mma16816h(acc[0], ah, f0.x, f0.y);
        mma16816h(acc[1], ah, f1.x, f1.y);
        mma16816h(acc[2], ah, f2.x, f2.y);
        mma16816h(acc[3], ah, f3.x, f3.y);
    }
}

__global__ __launch_bounds__(256) void k_conv3_heads(
    const float* __restrict__ w, const float* __restrict__ bias,
    const float* __restrict__ alpha,
    const float* __restrict__ w41, const float* __restrict__ b41,
    const float* __restrict__ w42, const float* __restrict__ b42,
    float* __restrict__ out)
{
    __shared__ uint2 sWf[9*4*32];
    __shared__ float sBA[64];
    __shared__ float sHW[6][32];
    __shared__ float sHB[6];

    const int b    = blockIdx.z;
    const int ox0  = blockIdx.x * 128;
    const int oy0  = blockIdx.y * 4;
    const int tid  = threadIdx.x;
    const int wid  = tid >> 5;
    const int lane = tid & 31;

    for (int f = tid; f < 9*4*32; f += 256) {
        int kc = f >> 7, cg = (f >> 5) & 3, ln = f & 31;
        int g = ln >> 2, ci0 = (ln & 3) * 2;
        int co = cg*8 + g;
        int ky = kc / 3, kx = kc % 3;
        __half2 b0 = __floats2half2_rn(w[((co*16 + ci0  )*3 + ky)*3 + kx],
                                       w[((co*16 + ci0+1)*3 + ky)*3 + kx]);
        __half2 b1 = __floats2half2_rn(w[((co*16 + ci0+8)*3 + ky)*3 + kx],
                                       w[((co*16 + ci0+9)*3 + ky)*3 + kx]);
        sWf[f] = make_uint2(*(uint32_t*)&b0, *(uint32_t*)&b1);
    }
    if (tid < 32) { sBA[tid] = bias[tid]; sBA[32+tid] = alpha[tid]; }
    if (tid < 64)  sHW[tid/32][tid%32] = w41[tid];
    if (tid >= 64 && tid < 192) sHW[2 + (tid-64)/32][(tid-64)%32] = w42[tid-64];
    if (tid < 2) sHB[tid] = b41[tid];
    if (tid >= 2 && tid < 6) sHB[tid] = b42[tid-2];
    __syncthreads();

    const int q4  = lane & 3;
    const int g   = lane >> 2;
    const int ci0 = q4 * 2;
    const int q   = q4;

    const int p0  = ox0 + wid * 16 + g;
    const int p1  = p0 + 8;
    const int p0c = min(p0, H3 - 1);
    const int p1c = min(p1, H3 - 1);

    float* regp  = out;
    float* probp = out + (size_t)B * 4 * P3;

    for (int r = 0; r < 4; r++) {
        const int oy = oy0 + r;
        if (oy >= H3) break;

        const uint32_t* row0 = &g_c2h[(size_t)(b*H2 + oy    ) * H2 * 8];
        const uint32_t* row1 = &g_c2h[(size_t)(b*H2 + oy + 1) * H2 * 8];
        const uint32_t* row2 = &g_c2h[(size_t)(b*H2 + oy + 2) * H2 * 8];

        float acc[4][4];
        #pragma unroll
        for (int cg = 0; cg < 4; cg++)
            #pragma unroll
            for (int j = 0; j < 4; j++) acc[cg][j] = 0.f;

        uint32_t A0[12], A1[12];
        load_ky1(A0, row0, p0c, p1c, q4);
        load_ky1(A1, row1, p0c, p1c, q4);
        mma_ky4(acc, A0, sWf, 0, lane);
        load_ky1(A0, row2, p0c, p1c, q4);
        mma_ky4(acc, A1, sWf, 3, lane);
        mma_ky4(acc, A0, sWf, 6, lane);

        const size_t rowbase = (size_t)oy * H3;
        #pragma unroll
        for (int px = 0; px < 2; px++) {
            const int pp = px ? p1 : p0;
            float o[6];
            #pragma unroll
            for (int k = 0; k < 6; k++) o[k] = 0.f;
            #pragma unroll
            for (int cg = 0; cg < 4; cg++) {
                #pragma unroll
                for (int j = 0; j < 2; j++) {
                    const int ch = cg*8 + ci0 + j;
                    float t = acc[cg][px*2 + j] + sBA[ch];
                    t = (t >= 0.f) ? t : sBA[32+ch]*t;
                    o[0] = fmaf(t, sHW[0][ch], o[0]);
                    o[1] = fmaf(t, sHW[1][ch], o[1]);
                    o[2] = fmaf(t, sHW[2][ch], o[2]);
                    o[3] = fmaf(t, sHW[3][ch], o[3]);
                    o[4] = fmaf(t, sHW[4][ch], o[4]);
                    o[5] = fmaf(t, sHW[5][ch], o[5]);
                }
            }
            #pragma unroll
            for (int off = 1; off <= 2; off <<= 1)
                #pragma unroll
                for (int k = 0; k < 6; k++)
                    o[k] += __shfl_xor_sync(0xffffffffu, o[k], off);

            float l0 = o[0] + sHB[0], l1 = o[1] + sHB[1];
            float m  = fmaxf(l0, l1);
            float e0 = expf(l0 - m), e1 = expf(l1 - m);
            float inv = 1.f / (e0 + e1);
            float pr0 = e0 * inv, pr1 = e1 * inv;

            if (pp < H3) {
                const size_t p = rowbase + pp;
                regp[(size_t)(b*4+q)*P3 + p] = o[2+q] + sHB[2+q];
                if (q == 0) probp[(size_t)(b*2+0)*P3 + p] = pr0;
                if (q == 1) probp[(size_t)(b*2+1)*P3 + p] = pr1;
            }
        }
    }
}

// ---------------------------------------------------------------------------
extern "C" void kernel_launch(void* const* d_in, const int* in_sizes, int n_in,
                              void* d_out, int out_size)
{
    const float* x    = (const float*)d_in[0];
    const float* c1w  = (const float*)d_in[1];
    const float* c1b  = (const float*)d_in[2];
    const float* p1a  = (const float*)d_in[3];
    const float* c2w  = (const float*)d_in[4];
    const float* c2b  = (const float*)d_in[5];
    const float* p2a  = (const float*)d_in[6];
    const float* c3w  = (const float*)d_in[7];
    const float* c3b  = (const float*)d_in[8];
    const float* p3a  = (const float*)d_in[9];
    const float* c41w = (const float*)d_in[10];
    const float* c41b = (const float*)d_in[11];
    const float* c42w = (const float*)d_in[12];
    const float* c42b = (const float*)d_in[13];
    float* out = (float*)d_out;

    {
        dim3 blk(32, 4);
        dim3 grd((HP + 31) / 32, (HP + 3) / 4, B);
        k_conv1_pool<<<grd, blk>>>(x, c1w, c1b, p1a);
    }
    {
        dim3 grd((H2 + 127) / 128, (H2 + 3) / 4, B);
        k_conv2_mma<<<grd, 256>>>(c2w, c2b, p2a);
    }
    {
        dim3 grd((H3 + 127) / 128, (H3 + 3) / 4, B);
        k_conv3_heads<<<grd, 256>>>(c3w, c3b, p3a, c41w, c41b, c42w, c42b, out);
    }
}

// round 14
// speedup vs baseline: 5.7017x; 1.0837x over previous
#include <cuda_runtime.h>
#include <cuda_fp16.h>
#include <math.h>
#include <stdint.h>

// ---------------------------------------------------------------------------
// MTCNN P-Net forward. Pure fp16 tensor-core path.
// conv1: scalar FFMA2, normalization folded into weights/bias.
// conv2/conv3: mma.sync fp16, ROW-STREAMING: 4 output rows' accumulators live,
// each of the 6 input rows loaded ONCE (12 LDG) and fed to <=3 output rows.
// conv3 fuses 1x1 heads + softmax.
// ---------------------------------------------------------------------------

#define B       16
#define H0      720
#define HP      359
#define H2      357
#define H3      355
#define P3      (H3*H3)

typedef unsigned long long ull;

__device__ __forceinline__ ull pack2(float a, float b) {
    ull r;
    asm("mov.b64 %0, {%1,%2};" : "=l"(r)
        : "r"(__float_as_uint(a)), "r"(__float_as_uint(b)));
    return r;
}
__device__ __forceinline__ void unpack2(ull v, float& a, float& b) {
    unsigned lo, hi;
    asm("mov.b64 {%0,%1}, %2;" : "=r"(lo), "=r"(hi) : "l"(v));
    a = __uint_as_float(lo); b = __uint_as_float(hi);
}
__device__ __forceinline__ void fma2(ull& d, ull a, ull b) {
    asm("fma.rn.f32x2 %0, %1, %2, %3;" : "=l"(d) : "l"(a), "l"(b), "l"(d));
}

// activations: per pixel 8 uint32 = 8 ch-pairs fp16x2 (32B/pixel)
__device__ uint32_t g_p1h[(size_t)B*HP*HP*8];
__device__ uint32_t g_c2h[(size_t)B*H2*H2*8];

// ======================= mma.sync helpers (fp16) ===========================
__device__ __forceinline__ void mma16816h(float* d, const uint32_t* a,
                                          uint32_t b0, uint32_t b1) {
    asm volatile(
        "mma.sync.aligned.m16n8k16.row.col.f32.f16.f16.f32 "
        "{%0,%1,%2,%3}, {%4,%5,%6,%7}, {%8,%9}, {%0,%1,%2,%3};"
        : "+f"(d[0]), "+f"(d[1]), "+f"(d[2]), "+f"(d[3])
        : "r"(a[0]), "r"(a[1]), "r"(a[2]), "r"(a[3]), "r"(b0), "r"(b1));
}

// load one input-row batch: 12 uint32 frag regs (kx 0..2 x {p0,p1} x {q4,q4+4})
__device__ __forceinline__ void load_ky1(uint32_t (&L)[12], const uint32_t* rp,
                                         int p0c, int p1c, int q4) {
    #pragma unroll
    for (int kx = 0; kx < 3; kx++) {
        L[kx*4+0] = rp[(p0c + kx)*8 + q4];
        L[kx*4+1] = rp[(p1c + kx)*8 + q4];
        L[kx*4+2] = rp[(p0c + kx)*8 + q4 + 4];
        L[kx*4+3] = rp[(p1c + kx)*8 + q4 + 4];
    }
}

// ---------------------------------------------------------------------------
// Kernel 1: conv1(3x3,3->10) + PReLU + maxpool2 -> fp16 ch-last
// normalization (x-127.5)*s folded into weights and bias.
// ---------------------------------------------------------------------------
__device__ __forceinline__ void conv1_taps(
    ull (&acc)[5][4], const ull sWp[5][3][9], int ci, int ky,
    const ull* top, const ull* bot)
{
    #pragma unroll
    for (int kx = 0; kx < 3; kx++) {
        #pragma unroll
        for (int cp = 0; cp < 5; cp++) {
            ull wp = sWp[cp][ci][ky*3+kx];
            fma2(acc[cp][0], wp, top[kx]);
            fma2(acc[cp][1], wp, top[kx+1]);
            fma2(acc[cp][2], wp, bot[kx]);
            fma2(acc[cp][3], wp, bot[kx+1]);
        }
    }
}

__global__ __launch_bounds__(128, 8) void k_conv1_pool(
    const float* __restrict__ x, const float* __restrict__ w1,
    const float* __restrict__ b1, const float* __restrict__ a1)
{
    __shared__ ull   sWp[5][3][9];
    __shared__ ull   sIn[3][10][66];
    __shared__ float sB[10], sA[10];

    const int b   = blockIdx.z;
    const int px0 = blockIdx.x * 32;
    const int py0 = blockIdx.y * 4;
    const int tid = threadIdx.y * 32 + threadIdx.x;
    const float SC = 0.0078125f;

    for (int i = tid; i < 135; i += 128) {
        int cp = i / 27, ci = (i % 27) / 9, k = i % 9;
        sWp[cp][ci][k] = pack2(w1[(2*cp)*27 + ci*9 + k] * SC,
                               w1[(2*cp+1)*27 + ci*9 + k] * SC);
    }
    if (tid < 10) {
        float s = 0.f;
        #pragma unroll
        for (int k = 0; k < 27; k++) s += w1[tid*27 + k];
        sB[tid] = b1[tid] - 127.5f * SC * s;
        sA[tid] = a1[tid];
    }

    const int row0 = 2*py0, col0 = 2*px0;
    {
        const int c  = tid & 63;
        const int r2 = tid >> 6;
        const int gc = col0 + c;
        const bool cok = (gc < H0);
        #pragma unroll
        for (int ci = 0; ci < 3; ci++) {
            #pragma unroll
            for (int r = 0; r < 5; r++) {
                const int rr = 2*r + r2;
                const int gr = row0 + rr;
                float v = 0.f;
                if (cok && gr < H0) v = x[((b*3+ci)*H0 + gr)*H0 + gc];
                sIn[ci][rr][c] = pack2(v, v);
            }
        }
        if (tid < 60) {
            int ci = tid / 20, rem = tid % 20;
            int rr = rem >> 1, c2 = 64 + (rem & 1);
            int gr = row0 + rr, gc2 = col0 + c2;
            float v = 0.f;
            if (gr < H0 && gc2 < H0) v = x[((b*3+ci)*H0 + gr)*H0 + gc2];
            sIn[ci][rr][c2] = pack2(v, v);
        }
    }
    __syncthreads();

    const int px = px0 + threadIdx.x;
    const int py = py0 + threadIdx.y;
    if (px >= HP || py >= HP) return;

    ull acc[5][4];
    #pragma unroll
    for (int cp = 0; cp < 5; cp++) {
        ull bb = pack2(sB[2*cp], sB[2*cp+1]);
        acc[cp][0]=bb; acc[cp][1]=bb; acc[cp][2]=bb; acc[cp][3]=bb;
    }

    const int lr = 2*threadIdx.y, lc = 2*threadIdx.x;
    #pragma unroll
    for (int ci = 0; ci < 3; ci++) {
        ull qa[4], qb[4];
        #pragma unroll
        for (int j = 0; j < 4; j++) qa[j] = sIn[ci][lr  ][lc+j];
        #pragma unroll
        for (int j = 0; j < 4; j++) qb[j] = sIn[ci][lr+1][lc+j];
        conv1_taps(acc, sWp, ci, 0, qa, qb);
        #pragma unroll
        for (int j = 0; j < 4; j++) qa[j] = sIn[ci][lr+2][lc+j];
        conv1_taps(acc, sWp, ci, 1, qb, qa);
        #pragma unroll
        for (int j = 0; j < 4; j++) qb[j] = sIn[ci][lr+3][lc+j];
        conv1_taps(acc, sWp, ci, 2, qa, qb);
    }

    float v[16];
    #pragma unroll
    for (int cp = 0; cp < 5; cp++) {
        float a0 = sA[2*cp], a1v = sA[2*cp+1];
        float m0 = -INFINITY, m1 = -INFINITY;
        #pragma unroll
        for (int k = 0; k < 4; k++) {
            float v0, v1; unpack2(acc[cp][k], v0, v1);
            v0 = (v0 >= 0.f) ? v0 : a0*v0;
            v1 = (v1 >= 0.f) ? v1 : a1v*v1;
            m0 = fmaxf(m0, v0); m1 = fmaxf(m1, v1);
        }
        v[2*cp] = m0; v[2*cp+1] = m1;
    }
    #pragma unroll
    for (int c = 10; c < 16; c++) v[c] = 0.f;

    uint32_t h[8];
    #pragma unroll
    for (int qd = 0; qd < 8; qd++) {
        __half2 hh = __floats2half2_rn(v[2*qd], v[2*qd+1]);
        h[qd] = *(uint32_t*)&hh;
    }

    uint4* dst = (uint4*)&g_p1h[((size_t)(b*HP + py)*HP + px)*8];
    dst[0] = make_uint4(h[0], h[1], h[2], h[3]);
    dst[1] = make_uint4(h[4], h[5], h[6], h[7]);
}

// ---------------------------------------------------------------------------
// Kernel 2: conv2 via mma.sync fp16, ROW-STREAMING (4 rows, 6 input rows).
// ---------------------------------------------------------------------------
__global__ __launch_bounds__(256, 2) void k_conv2_mma(
    const float* __restrict__ w, const float* __restrict__ bias,
    const float* __restrict__ alpha)
{
    __shared__ uint2 sWf[9*2*32];
    __shared__ float sBA[32];

    const int b    = blockIdx.z;
    const int ox0  = blockIdx.x * 128;
    const int oy0  = blockIdx.y * 4;
    const int tid  = threadIdx.x;
    const int wid  = tid >> 5;
    const int lane = tid & 31;

    for (int f = tid; f < 9*2*32; f += 256) {
        int kc = f >> 6, cg = (f >> 5) & 1, ln = f & 31;
        int g = ln >> 2, ci0 = (ln & 3) * 2;
        int co = cg*8 + g;
        int ky = kc / 3, kx = kc % 3;
        float w0 = (ci0   < 10) ? w[((co*10 + ci0  )*3 + ky)*3 + kx] : 0.f;
        float w1v= (ci0+1 < 10) ? w[((co*10 + ci0+1)*3 + ky)*3 + kx] : 0.f;
        float w2 = (ci0+8 < 10) ? w[((co*10 + ci0+8)*3 + ky)*3 + kx] : 0.f;
        float w3 = (ci0+9 < 10) ? w[((co*10 + ci0+9)*3 + ky)*3 + kx] : 0.f;
        __half2 b0 = __floats2half2_rn(w0, w1v);
        __half2 b1 = __floats2half2_rn(w2, w3);
        sWf[f] = make_uint2(*(uint32_t*)&b0, *(uint32_t*)&b1);
    }
    if (tid < 16) { sBA[tid] = bias[tid]; sBA[16+tid] = alpha[tid]; }
    __syncthreads();

    const int q4  = lane & 3;
    const int g   = lane >> 2;
    const int ci0 = q4 * 2;

    const int p0  = ox0 + wid * 16 + g;
    const int p1  = p0 + 8;
    const int p0c = min(p0, H2 - 1);
    const int p1c = min(p1, H2 - 1);

    float acc[4][2][4];
    #pragma unroll
    for (int r = 0; r < 4; r++)
        #pragma unroll
        for (int cg = 0; cg < 2; cg++)
            #pragma unroll
            for (int j = 0; j < 4; j++) acc[r][cg][j] = 0.f;

    uint32_t cur[12], nxt[12];
    load_ky1(cur, &g_p1h[(size_t)(b*HP + min(oy0, HP-1)) * HP * 8], p0c, p1c, q4);

    #pragma unroll
    for (int i = 0; i < 6; i++) {
        if (i < 5)
            load_ky1(nxt, &g_p1h[(size_t)(b*HP + min(oy0+i+1, HP-1)) * HP * 8],
                     p0c, p1c, q4);
        #pragma unroll
        for (int kx = 0; kx < 3; kx++) {
            uint32_t ah[4] = {cur[kx*4+0], cur[kx*4+1], cur[kx*4+2], cur[kx*4+3]};
            #pragma unroll
            for (int r = 0; r < 4; r++) {
                if (r > i || r < i - 2) continue;
                const int kc = 3*(i - r) + kx;
                uint2 f0 = sWf[(kc*2 + 0)*32 + lane];
                uint2 f1 = sWf[(kc*2 + 1)*32 + lane];
                mma16816h(acc[r][0], ah, f0.x, f0.y);
                mma16816h(acc[r][1], ah, f1.x, f1.y);
            }
        }
        #pragma unroll
        for (int j = 0; j < 12; j++) cur[j] = nxt[j];
    }

    #pragma unroll
    for (int r = 0; r < 4; r++) {
        const int oy = oy0 + r;
        if (oy >= H2) break;
        const size_t rowbase = (size_t)(b*H2 + oy) * H2;
        #pragma unroll
        for (int cg = 0; cg < 2; cg++) {
            const int co = cg*8 + ci0;
            const float b0 = sBA[co], b1 = sBA[co+1];
            const float a0 = sBA[16+co], a1 = sBA[16+co+1];
            float t0 = acc[r][cg][0] + b0, t1 = acc[r][cg][1] + b1;
            float t2 = acc[r][cg][2] + b0, t3 = acc[r][cg][3] + b1;
            float o00 = (t0 >= 0.f) ? t0 : a0*t0;
            float o01 = (t1 >= 0.f) ? t1 : a1*t1;
            float o10 = (t2 >= 0.f) ? t2 : a0*t2;
            float o11 = (t3 >= 0.f) ? t3 : a1*t3;
            __half2 s0 = __floats2half2_rn(o00, o01);
            __half2 s1 = __floats2half2_rn(o10, o11);
            if (p0 < H2) g_c2h[(rowbase + p0)*8 + cg*4 + q4] = *(uint32_t*)&s0;
            if (p1 < H2) g_c2h[(rowbase + p1)*8 + cg*4 + q4] = *(uint32_t*)&s1;
        }
    }
}

// ---------------------------------------------------------------------------
// Kernel 3: conv3 ROW-STREAMING + fused heads + softmax.
// ---------------------------------------------------------------------------
__global__ __launch_bounds__(256, 2) void k_conv3_heads(
    const float* __restrict__ w, const float* __restrict__ bias,
    const float* __restrict__ alpha,
    const float* __restrict__ w41, const float* __restrict__ b41,
    const float* __restrict__ w42, const float* __restrict__ b42,
    float* __restrict__ out)
{
    __shared__ uint2 sWf[9*4*32];
    __shared__ float sBA[64];
    __shared__ float sHW[6][32];
    __shared__ float sHB[6];

    const int b    = blockIdx.z;
    const int ox0  = blockIdx.x * 128;
    const int oy0  = blockIdx.y * 4;
    const int tid  = threadIdx.x;
    const int wid  = tid >> 5;
    const int lane = tid & 31;

    for (int f = tid; f < 9*4*32; f += 256) {
        int kc = f >> 7, cg = (f >> 5) & 3, ln = f & 31;
        int g = ln >> 2, ci0 = (ln & 3) * 2;
        int co = cg*8 + g;
        int ky = kc / 3, kx = kc % 3;
        __half2 b0 = __floats2half2_rn(w[((co*16 + ci0  )*3 + ky)*3 + kx],
                                       w[((co*16 + ci0+1)*3 + ky)*3 + kx]);
        __half2 b1 = __floats2half2_rn(w[((co*16 + ci0+8)*3 + ky)*3 + kx],
                                       w[((co*16 + ci0+9)*3 + ky)*3 + kx]);
        sWf[f] = make_uint2(*(uint32_t*)&b0, *(uint32_t*)&b1);
    }
    if (tid < 32) { sBA[tid] = bias[tid]; sBA[32+tid] = alpha[tid]; }
    if (tid < 64)  sHW[tid/32][tid%32] = w41[tid];
    if (tid >= 64 && tid < 192) sHW[2 + (tid-64)/32][(tid-64)%32] = w42[tid-64];
    if (tid < 2) sHB[tid] = b41[tid];
    if (tid >= 2 && tid < 6) sHB[tid] = b42[tid-2];
    __syncthreads();

    const int q4  = lane & 3;
    const int g   = lane >> 2;
    const int ci0 = q4 * 2;
    const int q   = q4;

    const int p0  = ox0 + wid * 16 + g;
    const int p1  = p0 + 8;
    const int p0c = min(p0, H3 - 1);
    const int p1c = min(p1, H3 - 1);

    float* regp  = out;
    float* probp = out + (size_t)B * 4 * P3;

    float acc[4][4][4];
    #pragma unroll
    for (int r = 0; r < 4; r++)
        #pragma unroll
        for (int cg = 0; cg < 4; cg++)
            #pragma unroll
            for (int j = 0; j < 4; j++) acc[r][cg][j] = 0.f;

    uint32_t cur[12], nxt[12];
    load_ky1(cur, &g_c2h[(size_t)(b*H2 + min(oy0, H2-1)) * H2 * 8], p0c, p1c, q4);

    #pragma unroll
    for (int i = 0; i < 6; i++) {
        if (i < 5)
            load_ky1(nxt, &g_c2h[(size_t)(b*H2 + min(oy0+i+1, H2-1)) * H2 * 8],
                     p0c, p1c, q4);
        #pragma unroll
        for (int kx = 0; kx < 3; kx++) {
            uint32_t ah[4] = {cur[kx*4+0], cur[kx*4+1], cur[kx*4+2], cur[kx*4+3]};
            #pragma unroll
            for (int r = 0; r < 4; r++) {
                if (r > i || r < i - 2) continue;
                const int kc = 3*(i - r) + kx;
                uint2 f0 = sWf[(kc*4 + 0)*32 + lane];
                uint2 f1 = sWf[(kc*4 + 1)*32 + lane];
                uint2 f2 = sWf[(kc*4 + 2)*32 + lane];
                uint2 f3 = sWf[(kc*4 + 3)*32 + lane];
                mma16816h(acc[r][0], ah, f0.x, f0.y);
                mma16816h(acc[r][1], ah, f1.x, f1.y);
                mma16816h(acc[r][2], ah, f2.x, f2.y);
                mma16816h(acc[r][3], ah, f3.x, f3.y);
            }
        }
        #pragma unroll
        for (int j = 0; j < 12; j++) cur[j] = nxt[j];
    }

    #pragma unroll
    for (int r = 0; r < 4; r++) {
        const int oy = oy0 + r;
        if (oy >= H3) break;
        const size_t rowbase = (size_t)oy * H3;
        #pragma unroll
        for (int px = 0; px < 2; px++) {
            const int pp = px ? p1 : p0;
            float o[6];
            #pragma unroll
            for (int k = 0; k < 6; k++) o[k] = 0.f;
            #pragma unroll
            for (int cg = 0; cg < 4; cg++) {
                #pragma unroll
                for (int j = 0; j < 2; j++) {
                    const int ch = cg*8 + ci0 + j;
                    float t = acc[r][cg][px*2 + j] + sBA[ch];
                    t = (t >= 0.f) ? t : sBA[32+ch]*t;
                    o[0] = fmaf(t, sHW[0][ch], o[0]);
                    o[1] = fmaf(t, sHW[1][ch], o[1]);
                    o[2] = fmaf(t, sHW[2][ch], o[2]);
                    o[3] = fmaf(t, sHW[3][ch], o[3]);
                    o[4] = fmaf(t, sHW[4][ch], o[4]);
                    o[5] = fmaf(t, sHW[5][ch], o[5]);
                }
            }
            #pragma unroll
            for (int off = 1; off <= 2; off <<= 1)
                #pragma unroll
                for (int k = 0; k < 6; k++)
                    o[k] += __shfl_xor_sync(0xffffffffu, o[k], off);

            float l0 = o[0] + sHB[0], l1 = o[1] + sHB[1];
            float m  = fmaxf(l0, l1);
            float e0 = expf(l0 - m), e1 = expf(l1 - m);
            float inv = 1.f / (e0 + e1);
            float pr0 = e0 * inv, pr1 = e1 * inv;

            if (pp < H3) {
                const size_t p = rowbase + pp;
                regp[(size_t)(b*4+q)*P3 + p] = o[2+q] + sHB[2+q];
                if (q == 0) probp[(size_t)(b*2+0)*P3 + p] = pr0;
                if (q == 1) probp[(size_t)(b*2+1)*P3 + p] = pr1;
            }
        }
    }
}

// ---------------------------------------------------------------------------
extern "C" void kernel_launch(void* const* d_in, const int* in_sizes, int n_in,
                              void* d_out, int out_size)
{
    const float* x    = (const float*)d_in[0];
    const float* c1w  = (const float*)d_in[1];
    const float* c1b  = (const float*)d_in[2];
    const float* p1a  = (const float*)d_in[3];
    const float* c2w  = (const float*)d_in[4];
    const float* c2b  = (const float*)d_in[5];
    const float* p2a  = (const float*)d_in[6];
    const float* c3w  = (const float*)d_in[7];
    const float* c3b  = (const float*)d_in[8];
    const float* p3a  = (const float*)d_in[9];
    const float* c41w = (const float*)d_in[10];
    const float* c41b = (const float*)d_in[11];
    const float* c42w = (const float*)d_in[12];
    const float* c42b = (const float*)d_in[13];
    float* out = (float*)d_out;

    {
        dim3 blk(32, 4);
        dim3 grd((HP + 31) / 32, (HP + 3) / 4, B);
        k_conv1_pool<<<grd, blk>>>(x, c1w, c1b, p1a);
    }
    {
        dim3 grd((H2 + 127) / 128, (H2 + 3) / 4, B);
        k_conv2_mma<<<grd, 256>>>(c2w, c2b, p2a);
    }
    {
        dim3 grd((H3 + 127) / 128, (H3 + 3) / 4, B);
        k_conv3_heads<<<grd, 256>>>(c3w, c3b, p3a, c41w, c41b, c42w, c42b, out);
    }
}